// round 1
// baseline (speedup 1.0000x reference)
#include <cuda_runtime.h>
#include <math.h>

#define Nn   10000
#define Tt   12
#define Dd   64
#define Hh   4
#define Ee   100000
#define DFFc 128
#define NTc  (Nn*Tt)        // 120000
#define NTDc (NTc*Dd)       // 7680000
#define THc  (Tt*Hh)        // 48
#define NTHc (Nn*THc)       // 480000
#define ETHc (Ee*THc)       // 4800000

// ---------------- scratch (static device globals; no allocs) ----------------
__device__ float    g_h[NTDc];      // BN output (reused for BN1 and BN2)
__device__ float    g_z[NTDc];      // per-relation projected features
__device__ float    g_acc[NTDc];    // unnormalized message accumulator
__device__ float    g_m[NTDc];      // combined normalized messages
__device__ float    g_x2[NTDc];     // residual x + m
__device__ float    g_ebuf[ETHc];   // per-edge e / ex values
__device__ float    g_el[NTc*Hh];
__device__ float    g_er[NTc*Hh];
__device__ float    g_denom[NTHc];
__device__ unsigned g_emax[NTHc];   // ordered-encoded float max

// ordered-int encoding for atomicMax on signed floats
__device__ __forceinline__ unsigned fenc(float f){
    unsigned u = __float_as_uint(f);
    return (u & 0x80000000u) ? ~u : (u | 0x80000000u);
}
__device__ __forceinline__ float fdec(unsigned u){
    return (u & 0x80000000u) ? __uint_as_float(u & 0x7FFFFFFFu) : __uint_as_float(~u);
}

// ---------------- BatchNorm over (T,D) per node ----------------
__global__ void bn_kernel(const float* __restrict__ xin,
                          const float* __restrict__ gamma,
                          const float* __restrict__ beta,
                          int use_x2){
    int n = blockIdx.x;
    const float* xr = (use_x2 ? (const float*)g_x2 : xin) + (size_t)n * 768;
    float s = 0.f, sq = 0.f;
    for (int i = threadIdx.x; i < 768; i += 256){
        float v = xr[i]; s += v; sq += v * v;
    }
    #pragma unroll
    for (int o = 16; o; o >>= 1){
        s  += __shfl_xor_sync(0xffffffffu, s,  o);
        sq += __shfl_xor_sync(0xffffffffu, sq, o);
    }
    __shared__ float ss[8], ssq[8];
    int w = threadIdx.x >> 5;
    if ((threadIdx.x & 31) == 0){ ss[w] = s; ssq[w] = sq; }
    __syncthreads();
    float ts = 0.f, tq = 0.f;
    #pragma unroll
    for (int i = 0; i < 8; i++){ ts += ss[i]; tq += ssq[i]; }
    float mean = ts * (1.f / 768.f);
    float var  = tq * (1.f / 768.f) - mean * mean;
    float rs   = rsqrtf(var + 1e-5f);
    float sc   = rs * gamma[n];
    float sh   = beta[n] - mean * sc;
    float* outr = g_h + (size_t)n * 768;
    for (int i = threadIdx.x; i < 768; i += 256)
        outr[i] = xr[i] * sc + sh;
}

// ---------------- z = h @ W  and el/er reductions ----------------
// block = 256 threads, handles 32 (n,t) rows; W (64x64) + rows cached in smem
__global__ void zel_kernel(const float* __restrict__ W,
                           const float* __restrict__ al,
                           const float* __restrict__ ar){
    __shared__ float sW[64 * 64];
    __shared__ float sh[32 * 64];
    __shared__ float sal[64], sar[64];
    int tid = threadIdx.x;
    for (int i = tid; i < 4096; i += 256) sW[i] = W[i];
    if (tid < 64){ sal[tid] = al[tid]; sar[tid] = ar[tid]; }
    int nt0 = blockIdx.x * 32;
    for (int i = tid; i < 2048; i += 256) sh[i] = g_h[(size_t)nt0 * 64 + i];
    __syncthreads();

    int he   = tid & 63;
    int rsub = tid >> 6;
    int h    = he >> 4;
    for (int rr = rsub; rr < 32; rr += 4){
        const float* hr = &sh[rr * 64];
        float acc = 0.f;
        #pragma unroll
        for (int d = 0; d < 64; d++) acc = fmaf(hr[d], sW[d * 64 + he], acc);
        int nt = nt0 + rr;
        g_z[(size_t)nt * 64 + he] = acc;
        float pl = acc * sal[he];
        float pr = acc * sar[he];
        #pragma unroll
        for (int o = 8; o; o >>= 1){
            pl += __shfl_xor_sync(0xffffffffu, pl, o);
            pr += __shfl_xor_sync(0xffffffffu, pr, o);
        }
        if ((he & 15) == 0){
            g_el[nt * 4 + h] = pl;
            g_er[nt * 4 + h] = pr;
        }
    }
}

// ---------------- clear accumulators between relations ----------------
__global__ void clear_kernel(){
    int i = blockIdx.x * 256 + threadIdx.x;
    if (i < NTDc) g_acc[i] = 0.f;
    if (i < NTHc){ g_denom[i] = 0.f; g_emax[i] = 0u; }
}

// ---------------- edge pass A: e = leaky_relu(el[src]+er[dst]); segment max ----
__global__ void edgeA_kernel(const int* __restrict__ src, const int* __restrict__ dst){
    int gtid = blockIdx.x * 192 + threadIdx.x;
    int ei = gtid / 48, th = gtid % 48;
    if (ei >= Ee) return;
    int s = src[ei], d = dst[ei];
    float v = g_el[s * 48 + th] + g_er[d * 48 + th];
    v = (v > 0.f) ? v : 0.2f * v;
    g_ebuf[(size_t)ei * 48 + th] = v;
    atomicMax(&g_emax[d * 48 + th], fenc(v));
}

// ---------------- edge pass B: ex = exp(e - max); segment sum denom ----------
__global__ void edgeB_kernel(const int* __restrict__ dst){
    int gtid = blockIdx.x * 192 + threadIdx.x;
    int ei = gtid / 48, th = gtid % 48;
    if (ei >= Ee) return;
    int d = dst[ei];
    size_t idx = (size_t)ei * 48 + th;
    float ex = expf(g_ebuf[idx] - fdec(g_emax[d * 48 + th]));
    g_ebuf[idx] = ex;
    atomicAdd(&g_denom[d * 48 + th], ex);
}

// ---------------- edge pass C: acc[dst] += ex * z[src] (unnormalized) --------
__global__ void edgeC_kernel(const int* __restrict__ src, const int* __restrict__ dst){
    int ei = blockIdx.x;
    __shared__ float sEx[48];
    __shared__ int ssd[2];
    if (threadIdx.x == 0){ ssd[0] = src[ei]; ssd[1] = dst[ei]; }
    if (threadIdx.x < 48) sEx[threadIdx.x] = g_ebuf[(size_t)ei * 48 + threadIdx.x];
    __syncthreads();
    int s = ssd[0], d = ssd[1];
    const float* zr = g_z  + (size_t)s * 768;
    float*       ar = g_acc + (size_t)d * 768;
    #pragma unroll
    for (int k = 0; k < 3; k++){
        int i = threadIdx.x + k * 256;
        int t = i >> 6;
        int h = (i & 63) >> 4;
        atomicAdd(&ar[i], sEx[t * 4 + h] * zr[i]);
    }
}

// ---------------- normalize by denom, combine relations ----------------
__global__ void norm_kernel(int add){
    int i = blockIdx.x * 256 + threadIdx.x;
    if (i >= NTDc) return;
    int n = i / 768, r = i % 768;
    int t = r >> 6, h = (r & 63) >> 4;
    float v = g_acc[i] / fmaxf(g_denom[n * 48 + t * 4 + h], 1e-16f);
    g_m[i] = add ? (g_m[i] + v) : v;
}

// ---------------- residual: x2 = x + m ----------------
__global__ void resid_kernel(const float* __restrict__ x){
    int i = blockIdx.x * 256 + threadIdx.x;
    if (i >= NTDc) return;
    g_x2[i] = x[i] + g_m[i];
}

// ---------------- fused FFN: out = x2 + gelu(h2@W1+b1)@W2+b2 ----------------
// block = 128 threads, 4 rows per iteration; W1 in smem, W2 via L1
__global__ void ff_kernel(const float* __restrict__ w1, const float* __restrict__ b1,
                          const float* __restrict__ w2, const float* __restrict__ b2,
                          float* __restrict__ out){
    __shared__ float sW1[64 * DFFc];   // 32 KB
    __shared__ float sB1[DFFc];
    __shared__ float sB2[64];
    __shared__ float sX[4 * 64];
    __shared__ float sG[4 * DFFc];
    int tid = threadIdx.x;
    for (int i = tid; i < 64 * DFFc; i += 128) sW1[i] = w1[i];
    if (tid < DFFc) sB1[tid] = b1[tid];
    if (tid < 64)   sB2[tid] = b2[tid];
    __syncthreads();

    const int ngroups = NTc / 4;  // 30000
    int dcol  = tid & 63;
    int rbase = tid >> 6;
    for (int g = blockIdx.x; g < ngroups; g += gridDim.x){
        int row0 = g * 4;
        for (int i = tid; i < 256; i += 128) sX[i] = g_h[(size_t)row0 * 64 + i];
        __syncthreads();
        float a0 = sB1[tid], a1 = a0, a2 = a0, a3 = a0;
        #pragma unroll
        for (int d = 0; d < 64; d++){
            float w = sW1[d * DFFc + tid];
            a0 = fmaf(sX[d],       w, a0);
            a1 = fmaf(sX[64 + d],  w, a1);
            a2 = fmaf(sX[128 + d], w, a2);
            a3 = fmaf(sX[192 + d], w, a3);
        }
        sG[tid]            = 0.5f * a0 * (1.f + erff(a0 * 0.70710678118654752f));
        sG[DFFc + tid]     = 0.5f * a1 * (1.f + erff(a1 * 0.70710678118654752f));
        sG[2 * DFFc + tid] = 0.5f * a2 * (1.f + erff(a2 * 0.70710678118654752f));
        sG[3 * DFFc + tid] = 0.5f * a3 * (1.f + erff(a3 * 0.70710678118654752f));
        __syncthreads();
        #pragma unroll
        for (int it = 0; it < 2; it++){
            int r = rbase + it * 2;
            const float* gr = &sG[r * DFFc];
            float acc = 0.f;
            #pragma unroll 16
            for (int j = 0; j < DFFc; j++)
                acc = fmaf(gr[j], __ldg(&w2[j * 64 + dcol]), acc);
            size_t o = (size_t)(row0 + r) * 64 + dcol;
            out[o] = g_x2[o] + acc + sB2[dcol];
        }
        __syncthreads();
    }
}

// ---------------- launcher ----------------
extern "C" void kernel_launch(void* const* d_in, const int* in_sizes, int n_in,
                              void* d_out, int out_size){
    const float* x    = (const float*)d_in[0];
    const int*   src1 = (const int*)d_in[1];
    const int*   dst1 = (const int*)d_in[2];
    const int*   src2 = (const int*)d_in[3];
    const int*   dst2 = (const int*)d_in[4];
    const float* W1   = (const float*)d_in[5];
    const float* al1  = (const float*)d_in[6];
    const float* ar1  = (const float*)d_in[7];
    const float* W2   = (const float*)d_in[8];
    const float* al2  = (const float*)d_in[9];
    const float* ar2  = (const float*)d_in[10];
    const float* bn1g = (const float*)d_in[11];
    const float* bn1b = (const float*)d_in[12];
    const float* bn2g = (const float*)d_in[13];
    const float* bn2b = (const float*)d_in[14];
    const float* fw1  = (const float*)d_in[15];
    const float* fb1  = (const float*)d_in[16];
    const float* fw2  = (const float*)d_in[17];
    const float* fb2  = (const float*)d_in[18];
    float* out = (float*)d_out;

    const int gridNTD  = (NTDc + 255) / 256;          // 30000
    const int gridEdge = (Ee * 48 + 191) / 192;       // 25000

    // BN1: x -> g_h
    bn_kernel<<<Nn, 256>>>(x, bn1g, bn1b, 0);

    // ---- relation 1 ----
    clear_kernel<<<gridNTD, 256>>>();
    zel_kernel<<<NTc / 32, 256>>>(W1, al1, ar1);
    edgeA_kernel<<<gridEdge, 192>>>(src1, dst1);
    edgeB_kernel<<<gridEdge, 192>>>(dst1);
    edgeC_kernel<<<Ee, 256>>>(src1, dst1);
    norm_kernel<<<gridNTD, 256>>>(0);

    // ---- relation 2 ----
    clear_kernel<<<gridNTD, 256>>>();
    zel_kernel<<<NTc / 32, 256>>>(W2, al2, ar2);
    edgeA_kernel<<<gridEdge, 192>>>(src2, dst2);
    edgeB_kernel<<<gridEdge, 192>>>(dst2);
    edgeC_kernel<<<Ee, 256>>>(src2, dst2);
    norm_kernel<<<gridNTD, 256>>>(1);

    // residual, BN2, FFN
    resid_kernel<<<gridNTD, 256>>>(x);
    bn_kernel<<<Nn, 256>>>(x, bn2g, bn2b, 1);   // reads g_x2, writes g_h
    ff_kernel<<<2960, 128>>>(fw1, fb1, fw2, fb2, out);
}

// round 2
// speedup vs baseline: 1.2917x; 1.2917x over previous
#include <cuda_runtime.h>
#include <math.h>

#define Nn   10000
#define Tt   12
#define Dd   64
#define Hh   4
#define Ee   100000
#define DFFc 128
#define NTc  (Nn*Tt)        // 120000
#define NTDc (NTc*Dd)       // 7680000
#define THc  (Tt*Hh)        // 48

// ---------------- scratch (static device globals; no allocs) ----------------
__device__ float g_h[NTDc];      // BN output (reused for BN1 and BN2)
__device__ float g_z[NTDc];      // per-relation projected features
__device__ float g_m[NTDc];      // relation-1 normalized messages
__device__ float g_x2[NTDc];     // residual x + m1 + m2
__device__ float g_el[NTc*Hh];
__device__ float g_er[NTc*Hh];
__device__ int   g_cnt[Nn+1];    // histogram (offset by +1)
__device__ int   g_rowptr[Nn+1];
__device__ int   g_fill[Nn];
__device__ int   g_esrc[Ee];     // src node ids, sorted by dst

// ---------------- BatchNorm over (T,D) per node ----------------
__global__ void bn_kernel(const float* __restrict__ xin,
                          const float* __restrict__ gamma,
                          const float* __restrict__ beta,
                          int use_x2){
    int n = blockIdx.x;
    const float* xr = (use_x2 ? (const float*)g_x2 : xin) + (size_t)n * 768;
    float s = 0.f, sq = 0.f;
    for (int i = threadIdx.x; i < 768; i += 256){
        float v = xr[i]; s += v; sq += v * v;
    }
    #pragma unroll
    for (int o = 16; o; o >>= 1){
        s  += __shfl_xor_sync(0xffffffffu, s,  o);
        sq += __shfl_xor_sync(0xffffffffu, sq, o);
    }
    __shared__ float ss[8], ssq[8];
    int w = threadIdx.x >> 5;
    if ((threadIdx.x & 31) == 0){ ss[w] = s; ssq[w] = sq; }
    __syncthreads();
    float ts = 0.f, tq = 0.f;
    #pragma unroll
    for (int i = 0; i < 8; i++){ ts += ss[i]; tq += ssq[i]; }
    float mean = ts * (1.f / 768.f);
    float var  = tq * (1.f / 768.f) - mean * mean;
    float rs   = rsqrtf(var + 1e-5f);
    float sc   = rs * gamma[n];
    float sh   = beta[n] - mean * sc;
    float* outr = g_h + (size_t)n * 768;
    for (int i = threadIdx.x; i < 768; i += 256)
        outr[i] = xr[i] * sc + sh;
}

// ---------------- z = h @ W  and el/er reductions ----------------
__global__ void zel_kernel(const float* __restrict__ W,
                           const float* __restrict__ al,
                           const float* __restrict__ ar){
    __shared__ float sW[64 * 64];
    __shared__ float sh[32 * 64];
    __shared__ float sal[64], sar[64];
    int tid = threadIdx.x;
    for (int i = tid; i < 4096; i += 256) sW[i] = W[i];
    if (tid < 64){ sal[tid] = al[tid]; sar[tid] = ar[tid]; }
    int nt0 = blockIdx.x * 32;
    for (int i = tid; i < 2048; i += 256) sh[i] = g_h[(size_t)nt0 * 64 + i];
    __syncthreads();

    int he   = tid & 63;
    int rsub = tid >> 6;
    int h    = he >> 4;
    for (int rr = rsub; rr < 32; rr += 4){
        const float* hr = &sh[rr * 64];
        float acc = 0.f;
        #pragma unroll
        for (int d = 0; d < 64; d++) acc = fmaf(hr[d], sW[d * 64 + he], acc);
        int nt = nt0 + rr;
        g_z[(size_t)nt * 64 + he] = acc;
        float pl = acc * sal[he];
        float pr = acc * sar[he];
        #pragma unroll
        for (int o = 8; o; o >>= 1){
            pl += __shfl_xor_sync(0xffffffffu, pl, o);
            pr += __shfl_xor_sync(0xffffffffu, pr, o);
        }
        if ((he & 15) == 0){
            g_el[nt * 4 + h] = pl;
            g_er[nt * 4 + h] = pr;
        }
    }
}

// ---------------- CSR build ----------------
__global__ void csr_clear(){
    int i = blockIdx.x * 256 + threadIdx.x;
    if (i <= Nn) g_cnt[i] = 0;
}
__global__ void csr_hist(const int* __restrict__ dst){
    int e = blockIdx.x * 256 + threadIdx.x;
    if (e < Ee) atomicAdd(&g_cnt[dst[e] + 1], 1);
}
__global__ void csr_scan(){
    __shared__ int s[1024];
    __shared__ int carry;
    int tid = threadIdx.x;
    if (tid == 0) carry = 0;
    __syncthreads();
    for (int base = 0; base <= Nn; base += 1024){
        int i = base + tid;
        int v = (i <= Nn) ? g_cnt[i] : 0;
        s[tid] = v;
        __syncthreads();
        #pragma unroll
        for (int o = 1; o < 1024; o <<= 1){
            int a = (tid >= o) ? s[tid - o] : 0;
            __syncthreads();
            s[tid] += a;
            __syncthreads();
        }
        int incl = s[tid] + carry;
        if (i <= Nn){
            g_rowptr[i] = incl;
            if (i < Nn) g_fill[i] = incl;
        }
        __syncthreads();
        if (tid == 1023) carry = incl;
        __syncthreads();
    }
}
__global__ void csr_scatter(const int* __restrict__ src, const int* __restrict__ dst){
    int e = blockIdx.x * 256 + threadIdx.x;
    if (e < Ee){
        int p = atomicAdd(&g_fill[dst[e]], 1);
        g_esrc[p] = src[e];
    }
}

// ---------------- fused GAT: online segment-softmax gather ----------------
// grid = Nn blocks of 384 threads; warp w handles (dst=blockIdx.x, t=w)
// mode 0: write g_m.  mode 1: g_x2 = x + g_m + msg.
__global__ void gat_kernel(const float* __restrict__ x, int mode){
    const unsigned FULL = 0xffffffffu;
    int d    = blockIdx.x;
    int t    = threadIdx.x >> 5;
    int lane = threadIdx.x & 31;

    float er_h = (lane < 4) ? g_er[d * 48 + t * 4 + lane] : 0.f;
    int beg = g_rowptr[d], end = g_rowptr[d + 1];

    float maxv = -1e30f, denom = 0.f, acc0 = 0.f, acc1 = 0.f;
    int hsel = lane >> 4;   // 0 or 1

    for (int e = beg; e < end; ++e){
        int s = g_esrc[e];
        float el_h = (lane < 4) ? g_el[s * 48 + t * 4 + lane] : 0.f;
        float ev = el_h + er_h;
        ev = (ev > 0.f) ? ev : 0.2f * ev;
        float nm  = fmaxf(maxv, ev);
        float scl = __expf(maxv - nm);
        float wgt = __expf(ev - nm);
        denom = denom * scl + wgt;
        maxv  = nm;
        float sc0 = __shfl_sync(FULL, scl, hsel);
        float w0  = __shfl_sync(FULL, wgt, hsel);
        float sc1 = __shfl_sync(FULL, scl, 2 + hsel);
        float w1  = __shfl_sync(FULL, wgt, 2 + hsel);
        const float* zr = g_z + (size_t)s * 768 + t * 64;
        acc0 = acc0 * sc0 + w0 * zr[lane];
        acc1 = acc1 * sc1 + w1 * zr[32 + lane];
    }
    float d0 = __shfl_sync(FULL, denom, hsel);
    float d1 = __shfl_sync(FULL, denom, 2 + hsel);
    float m0 = acc0 / fmaxf(d0, 1e-16f);
    float m1 = acc1 / fmaxf(d1, 1e-16f);

    size_t idx = (size_t)d * 768 + t * 64 + lane;
    if (mode == 0){
        g_m[idx]      = m0;
        g_m[idx + 32] = m1;
    } else {
        g_x2[idx]      = x[idx]      + g_m[idx]      + m0;
        g_x2[idx + 32] = x[idx + 32] + g_m[idx + 32] + m1;
    }
}

// ---------------- fused FFN: out = x2 + gelu(h2@W1+b1)@W2+b2 ----------------
__global__ void ff_kernel(const float* __restrict__ w1, const float* __restrict__ b1,
                          const float* __restrict__ w2, const float* __restrict__ b2,
                          float* __restrict__ out){
    __shared__ float sW1[64 * DFFc];   // 32 KB
    __shared__ float sB1[DFFc];
    __shared__ float sB2[64];
    __shared__ float sX[4 * 64];
    __shared__ float sG[4 * DFFc];
    int tid = threadIdx.x;
    for (int i = tid; i < 64 * DFFc; i += 128) sW1[i] = w1[i];
    if (tid < DFFc) sB1[tid] = b1[tid];
    if (tid < 64)   sB2[tid] = b2[tid];
    __syncthreads();

    const int ngroups = NTc / 4;  // 30000
    int dcol  = tid & 63;
    int rbase = tid >> 6;
    for (int g = blockIdx.x; g < ngroups; g += gridDim.x){
        int row0 = g * 4;
        for (int i = tid; i < 256; i += 128) sX[i] = g_h[(size_t)row0 * 64 + i];
        __syncthreads();
        float a0 = sB1[tid], a1 = a0, a2 = a0, a3 = a0;
        #pragma unroll
        for (int d = 0; d < 64; d++){
            float w = sW1[d * DFFc + tid];
            a0 = fmaf(sX[d],       w, a0);
            a1 = fmaf(sX[64 + d],  w, a1);
            a2 = fmaf(sX[128 + d], w, a2);
            a3 = fmaf(sX[192 + d], w, a3);
        }
        sG[tid]            = 0.5f * a0 * (1.f + erff(a0 * 0.70710678118654752f));
        sG[DFFc + tid]     = 0.5f * a1 * (1.f + erff(a1 * 0.70710678118654752f));
        sG[2 * DFFc + tid] = 0.5f * a2 * (1.f + erff(a2 * 0.70710678118654752f));
        sG[3 * DFFc + tid] = 0.5f * a3 * (1.f + erff(a3 * 0.70710678118654752f));
        __syncthreads();
        #pragma unroll
        for (int it = 0; it < 2; it++){
            int r = rbase + it * 2;
            const float* gr = &sG[r * DFFc];
            float acc = 0.f;
            #pragma unroll 16
            for (int j = 0; j < DFFc; j++)
                acc = fmaf(gr[j], __ldg(&w2[j * 64 + dcol]), acc);
            size_t o = (size_t)(row0 + r) * 64 + dcol;
            out[o] = g_x2[o] + acc + sB2[dcol];
        }
        __syncthreads();
    }
}

// ---------------- launcher ----------------
extern "C" void kernel_launch(void* const* d_in, const int* in_sizes, int n_in,
                              void* d_out, int out_size){
    const float* x    = (const float*)d_in[0];
    const int*   src1 = (const int*)d_in[1];
    const int*   dst1 = (const int*)d_in[2];
    const int*   src2 = (const int*)d_in[3];
    const int*   dst2 = (const int*)d_in[4];
    const float* W1   = (const float*)d_in[5];
    const float* al1  = (const float*)d_in[6];
    const float* ar1  = (const float*)d_in[7];
    const float* W2   = (const float*)d_in[8];
    const float* al2  = (const float*)d_in[9];
    const float* ar2  = (const float*)d_in[10];
    const float* bn1g = (const float*)d_in[11];
    const float* bn1b = (const float*)d_in[12];
    const float* bn2g = (const float*)d_in[13];
    const float* bn2b = (const float*)d_in[14];
    const float* fw1  = (const float*)d_in[15];
    const float* fb1  = (const float*)d_in[16];
    const float* fw2  = (const float*)d_in[17];
    const float* fb2  = (const float*)d_in[18];
    float* out = (float*)d_out;

    const int gridE = (Ee + 255) / 256;
    const int gridN = (Nn + 256) / 256;

    // BN1: x -> g_h
    bn_kernel<<<Nn, 256>>>(x, bn1g, bn1b, 0);

    // ---- relation 1 ----
    csr_clear<<<gridN, 256>>>();
    csr_hist<<<gridE, 256>>>(dst1);
    csr_scan<<<1, 1024>>>();
    csr_scatter<<<gridE, 256>>>(src1, dst1);
    zel_kernel<<<NTc / 32, 256>>>(W1, al1, ar1);
    gat_kernel<<<Nn, 384>>>(x, 0);

    // ---- relation 2 ----
    csr_clear<<<gridN, 256>>>();
    csr_hist<<<gridE, 256>>>(dst2);
    csr_scan<<<1, 1024>>>();
    csr_scatter<<<gridE, 256>>>(src2, dst2);
    zel_kernel<<<NTc / 32, 256>>>(W2, al2, ar2);
    gat_kernel<<<Nn, 384>>>(x, 1);   // fuses residual: x2 = x + m1 + m2

    // BN2 + FFN
    bn_kernel<<<Nn, 256>>>(x, bn2g, bn2b, 1);   // reads g_x2, writes g_h
    ff_kernel<<<2960, 128>>>(fw1, fb1, fw2, fb2, out);
}

// round 3
// speedup vs baseline: 2.0055x; 1.5526x over previous
#include <cuda_runtime.h>
#include <math.h>

#define Nn   10000
#define Tt   12
#define Ee   100000
#define NTc  (Nn*Tt)        // 120000
#define NTDc (NTc*64)       // 7680000

typedef unsigned long long ull;

// ---------------- scratch ----------------
__device__ float g_h[NTDc];          // BN2 output (input to FFN)
__device__ float g_z[2][NTDc];       // per-relation projected features
__device__ float g_x2[NTDc];         // residual x + m1 + m2
__device__ float g_el[2][NTc*4];
__device__ float g_er[2][NTc*4];
__device__ int   g_cnt[2*(Nn+1)];
__device__ int   g_rowptr[2*(Nn+1)];
__device__ int   g_fill[2*Nn];
__device__ int   g_esrc[2][Ee];

// ---------------- f32x2 helpers ----------------
__device__ __forceinline__ ull pk(float a, float b){
    ull r;
    asm("mov.b64 %0, {%1, %2};" : "=l"(r) : "r"(__float_as_uint(a)), "r"(__float_as_uint(b)));
    return r;
}
__device__ __forceinline__ ull fma2(ull a, ull b, ull c){
    ull d;
    asm("fma.rn.f32x2 %0, %1, %2, %3;" : "=l"(d) : "l"(a), "l"(b), "l"(c));
    return d;
}
__device__ __forceinline__ float2 upk(ull v){
    unsigned lo, hi;
    asm("mov.b64 {%0, %1}, %2;" : "=r"(lo), "=r"(hi) : "l"(v));
    return make_float2(__uint_as_float(lo), __uint_as_float(hi));
}

// ---------------- CSR build ----------------
__global__ void csr_clear(){
    int i = blockIdx.x * 256 + threadIdx.x;
    if (i < 2*(Nn+1)) g_cnt[i] = 0;
}
__global__ void csr_hist(const int* __restrict__ dst1, const int* __restrict__ dst2){
    int e = blockIdx.x * 256 + threadIdx.x;
    if (e < Ee)            atomicAdd(&g_cnt[dst1[e] + 1], 1);
    else if (e < 2*Ee)     atomicAdd(&g_cnt[(Nn+1) + dst2[e-Ee] + 1], 1);
}
__global__ void csr_scan(){
    __shared__ int wsum[32];
    int tid = threadIdx.x, lane = tid & 31, w = tid >> 5;
    for (int rel = 0; rel < 2; rel++){
        const int* cnt = g_cnt    + rel*(Nn+1);
        int*       rp  = g_rowptr + rel*(Nn+1);
        int*       fl  = g_fill   + rel*Nn;
        int base = tid * 10;
        int v[10]; int s = 0;
        #pragma unroll
        for (int i = 0; i < 10; i++){
            int idx = base + i;
            int c = (idx <= Nn) ? cnt[idx] : 0;
            s += c; v[i] = s;
        }
        int t = s;
        #pragma unroll
        for (int o = 1; o < 32; o <<= 1){
            int u = __shfl_up_sync(0xffffffffu, t, o);
            if (lane >= o) t += u;
        }
        if (lane == 31) wsum[w] = t;
        __syncthreads();
        if (w == 0){
            int ws = wsum[lane];
            #pragma unroll
            for (int o = 1; o < 32; o <<= 1){
                int u = __shfl_up_sync(0xffffffffu, ws, o);
                if (lane >= o) ws += u;
            }
            wsum[lane] = ws;
        }
        __syncthreads();
        int off = ((w > 0) ? wsum[w-1] : 0) + (t - s);
        #pragma unroll
        for (int i = 0; i < 10; i++){
            int idx = base + i;
            if (idx <= Nn){
                int val = off + v[i];
                rp[idx] = val;
                if (idx < Nn) fl[idx] = val;
            }
        }
        __syncthreads();
    }
}
__global__ void csr_scatter(const int* __restrict__ src1, const int* __restrict__ dst1,
                            const int* __restrict__ src2, const int* __restrict__ dst2){
    int e = blockIdx.x * 256 + threadIdx.x;
    if (e < Ee){
        int p = atomicAdd(&g_fill[dst1[e]], 1);
        g_esrc[0][p] = src1[e];
    } else if (e < 2*Ee){
        int p = atomicAdd(&g_fill[Nn + dst2[e-Ee]], 1);
        g_esrc[1][p] = src2[e-Ee];
    }
}

// ---------------- fused BN1 + dual-relation z/el/er ----------------
// block = 256 threads handles 24 rows = 2 nodes; f32x2 GEMM
__global__ void zel_kernel(const float* __restrict__ x,
                           const float* __restrict__ bg, const float* __restrict__ bb,
                           const float* __restrict__ W1, const float* __restrict__ al1, const float* __restrict__ ar1,
                           const float* __restrict__ W2, const float* __restrict__ al2, const float* __restrict__ ar2){
    __shared__ float sh2[64*26];     // [d][row] interleaved (pad 26)
    __shared__ float sW[4096];
    __shared__ float red[4];
    int tid  = threadIdx.x;
    int lane = tid & 31;
    int nt0  = blockIdx.x * 24;
    int n0   = blockIdx.x * 2;

    if (tid < 4) red[tid] = 0.f;
    __syncthreads();

    float sA = 0.f, qA = 0.f, sB = 0.f, qB = 0.f;
    #pragma unroll
    for (int k = 0; k < 6; k++){
        int i = tid + k*256;
        float v = x[(size_t)nt0*64 + i];
        int r = i >> 6, d = i & 63;
        sh2[d*26 + r] = v;
        if (r < 12){ sA += v; qA += v*v; } else { sB += v; qB += v*v; }
    }
    #pragma unroll
    for (int o = 16; o; o >>= 1){
        sA += __shfl_xor_sync(0xffffffffu, sA, o);
        qA += __shfl_xor_sync(0xffffffffu, qA, o);
        sB += __shfl_xor_sync(0xffffffffu, sB, o);
        qB += __shfl_xor_sync(0xffffffffu, qB, o);
    }
    if (lane == 0){
        atomicAdd(&red[0], sA); atomicAdd(&red[1], qA);
        atomicAdd(&red[2], sB); atomicAdd(&red[3], qB);
    }
    __syncthreads();
    float mA = red[0]*(1.f/768.f), vA = red[1]*(1.f/768.f) - mA*mA;
    float mB = red[2]*(1.f/768.f), vB = red[3]*(1.f/768.f) - mB*mB;
    float scA = rsqrtf(vA + 1e-5f) * bg[n0];
    float shA = bb[n0]   - mA*scA;
    float scB = rsqrtf(vB + 1e-5f) * bg[n0+1];
    float shB = bb[n0+1] - mB*scB;
    #pragma unroll
    for (int k = 0; k < 6; k++){
        int i = tid + k*256;
        int r = i >> 6, d = i & 63;
        float v = sh2[d*26 + r];
        sh2[d*26 + r] = (r < 12) ? v*scA + shA : v*scB + shB;
    }
    __syncthreads();

    int c0 = tid & 31;      // column pair (2c0, 2c0+1)
    int rg = tid >> 5;      // rows rg, rg+8, rg+16
    for (int rel = 0; rel < 2; rel++){
        const float* W  = rel ? W2  : W1;
        const float* al = rel ? al2 : al1;
        const float* ar = rel ? ar2 : ar1;
        for (int i = tid; i < 4096; i += 256) sW[i] = W[i];
        __syncthreads();

        ull a0 = 0ull, a1 = 0ull, a2 = 0ull;
        #pragma unroll
        for (int d = 0; d < 64; d++){
            ull w01 = *(const ull*)&sW[d*64 + 2*c0];
            float h0 = sh2[d*26 + rg];
            float h1 = sh2[d*26 + rg + 8];
            float h2 = sh2[d*26 + rg + 16];
            a0 = fma2(w01, pk(h0, h0), a0);
            a1 = fma2(w01, pk(h1, h1), a1);
            a2 = fma2(w01, pk(h2, h2), a2);
        }
        float alv0 = al[2*c0], alv1 = al[2*c0+1];
        float arv0 = ar[2*c0], arv1 = ar[2*c0+1];
        ull accs[3] = {a0, a1, a2};
        #pragma unroll
        for (int k = 0; k < 3; k++){
            int r  = rg + 8*k;
            int nt = nt0 + r;
            *(ull*)&g_z[rel][(size_t)nt*64 + 2*c0] = accs[k];
            float2 zp = upk(accs[k]);
            float pl = zp.x*alv0 + zp.y*alv1;
            float pr = zp.x*arv0 + zp.y*arv1;
            #pragma unroll
            for (int o = 4; o; o >>= 1){
                pl += __shfl_xor_sync(0xffffffffu, pl, o);
                pr += __shfl_xor_sync(0xffffffffu, pr, o);
            }
            if ((c0 & 7) == 0){
                g_el[rel][nt*4 + (c0>>3)] = pl;
                g_er[rel][nt*4 + (c0>>3)] = pr;
            }
        }
        __syncthreads();
    }
}

// ---------------- fused GAT (both rels) + residual + BN2 ----------------
// block = node d, 12 warps (one per t); two-pass shfl-free softmax
__global__ void gat_kernel(const float* __restrict__ x,
                           const float* __restrict__ bg, const float* __restrict__ bb){
    int d    = blockIdx.x;
    int t    = threadIdx.x >> 5;
    int lane = threadIdx.x & 31;
    int h0   = lane >> 4;       // head for cols 0..31
    int h1   = 2 + h0;          // head for cols 32..63

    float m0 = 0.f, m1 = 0.f;
    #pragma unroll
    for (int rel = 0; rel < 2; rel++){
        const int*   es = g_esrc[rel];
        const float* el = g_el[rel];
        const float* zb = g_z[rel];
        int beg = g_rowptr[rel*(Nn+1) + d];
        int end = g_rowptr[rel*(Nn+1) + d + 1];
        float er0 = g_er[rel][d*48 + t*4 + h0];
        float er1 = g_er[rel][d*48 + t*4 + h1];

        float mx0 = -1e30f, mx1 = -1e30f;
        for (int e = beg; e < end; ++e){
            int s = es[e];
            float a0 = el[s*48 + t*4 + h0] + er0;
            float a1 = el[s*48 + t*4 + h1] + er1;
            a0 = (a0 > 0.f) ? a0 : 0.2f*a0;
            a1 = (a1 > 0.f) ? a1 : 0.2f*a1;
            mx0 = fmaxf(mx0, a0);
            mx1 = fmaxf(mx1, a1);
        }
        float dn0 = 0.f, dn1 = 0.f, ac0 = 0.f, ac1 = 0.f;
        for (int e = beg; e < end; ++e){
            int s = es[e];
            float a0 = el[s*48 + t*4 + h0] + er0;
            float a1 = el[s*48 + t*4 + h1] + er1;
            a0 = (a0 > 0.f) ? a0 : 0.2f*a0;
            a1 = (a1 > 0.f) ? a1 : 0.2f*a1;
            float w0 = __expf(a0 - mx0);
            float w1 = __expf(a1 - mx1);
            dn0 += w0; dn1 += w1;
            const float* zr = zb + (size_t)s*768 + t*64;
            ac0 = fmaf(w0, zr[lane],      ac0);
            ac1 = fmaf(w1, zr[32 + lane], ac1);
        }
        m0 += ac0 / fmaxf(dn0, 1e-16f);
        m1 += ac1 / fmaxf(dn1, 1e-16f);
    }

    size_t idx = (size_t)d*768 + t*64 + lane;
    float v0 = x[idx]      + m0;
    float v1 = x[idx + 32] + m1;

    // BN2 over this node's 768 values
    float s = v0 + v1;
    float q = v0*v0 + v1*v1;
    #pragma unroll
    for (int o = 16; o; o >>= 1){
        s += __shfl_xor_sync(0xffffffffu, s, o);
        q += __shfl_xor_sync(0xffffffffu, q, o);
    }
    __shared__ float sms[12], sqs[12];
    if (lane == 0){ sms[t] = s; sqs[t] = q; }
    __syncthreads();
    float ts = 0.f, tq = 0.f;
    #pragma unroll
    for (int i = 0; i < 12; i++){ ts += sms[i]; tq += sqs[i]; }
    float mean = ts * (1.f/768.f);
    float var  = tq * (1.f/768.f) - mean*mean;
    float sc   = rsqrtf(var + 1e-5f) * bg[d];
    float sb   = bb[d] - mean*sc;

    g_x2[idx]      = v0;
    g_x2[idx + 32] = v1;
    g_h[idx]       = v0*sc + sb;
    g_h[idx + 32]  = v1*sc + sb;
}

// ---------------- FFN with f32x2: out = x2 + gelu(h@W1+b1)@W2+b2 ----------------
#define FF_SMEM (80128)
__global__ void ff_kernel(const float* __restrict__ w1, const float* __restrict__ b1,
                          const float* __restrict__ w2, const float* __restrict__ b2,
                          float* __restrict__ out){
    extern __shared__ float sm[];
    float* sW1 = sm;                 // 64*128
    float* sW2 = sW1 + 8192;         // 128*64
    float* sB1 = sW2 + 8192;         // 128
    float* sB2 = sB1 + 128;          // 64
    float* sX  = sB2 + 64;           // 64*18  [d][row]
    float* sG  = sX  + 64*18;        // 128*18 [j][row]
    int tid = threadIdx.x;
    for (int i = tid; i < 8192; i += 256) sW1[i] = w1[i];
    for (int i = tid; i < 8192; i += 256) sW2[i] = w2[i];
    if (tid < 128) sB1[tid] = b1[tid];
    if (tid < 64)  sB2[tid] = b2[tid];
    __syncthreads();

    int j    = tid & 127;
    int half = tid >> 7;     // rows 8*half .. 8*half+7
    int dcol = tid & 63;
    int rq   = tid >> 6;     // rows 4*rq .. 4*rq+3

    for (int grp = blockIdx.x; grp < NTc/16; grp += gridDim.x){
        int row0 = grp * 16;
        #pragma unroll
        for (int k = 0; k < 4; k++){
            int i = tid + k*256;
            float v = g_h[(size_t)row0*64 + i];
            sX[(i & 63)*18 + (i >> 6)] = v;
        }
        __syncthreads();

        ull p0 = 0ull, p1 = 0ull, p2 = 0ull, p3 = 0ull;
        #pragma unroll
        for (int dd = 0; dd < 64; dd++){
            float w = sW1[dd*128 + j];
            ull ww = pk(w, w);
            const float* xb = &sX[dd*18 + half*8];
            p0 = fma2(*(const ull*)&xb[0], ww, p0);
            p1 = fma2(*(const ull*)&xb[2], ww, p1);
            p2 = fma2(*(const ull*)&xb[4], ww, p2);
            p3 = fma2(*(const ull*)&xb[6], ww, p3);
        }
        float bj = sB1[j];
        float2 f0 = upk(p0), f1 = upk(p1), f2 = upk(p2), f3 = upk(p3);
        float av[8] = {f0.x+bj, f0.y+bj, f1.x+bj, f1.y+bj, f2.x+bj, f2.y+bj, f3.x+bj, f3.y+bj};
        float gv[8];
        #pragma unroll
        for (int r = 0; r < 8; r++)
            gv[r] = 0.5f * av[r] * (1.f + erff(av[r] * 0.70710678118654752f));
        float* gb = &sG[j*18 + half*8];
        *(ull*)&gb[0] = pk(gv[0], gv[1]);
        *(ull*)&gb[2] = pk(gv[2], gv[3]);
        *(ull*)&gb[4] = pk(gv[4], gv[5]);
        *(ull*)&gb[6] = pk(gv[6], gv[7]);
        __syncthreads();

        ull q0 = 0ull, q1 = 0ull;
        #pragma unroll
        for (int jj = 0; jj < 128; jj++){
            float w = sW2[jj*64 + dcol];
            ull ww = pk(w, w);
            const float* gg = &sG[jj*18 + rq*4];
            q0 = fma2(*(const ull*)&gg[0], ww, q0);
            q1 = fma2(*(const ull*)&gg[2], ww, q1);
        }
        float2 r01 = upk(q0), r23 = upk(q1);
        float bbv = sB2[dcol];
        size_t ob = (size_t)(row0 + rq*4)*64 + dcol;
        out[ob]       = g_x2[ob]       + r01.x + bbv;
        out[ob + 64]  = g_x2[ob + 64]  + r01.y + bbv;
        out[ob + 128] = g_x2[ob + 128] + r23.x + bbv;
        out[ob + 192] = g_x2[ob + 192] + r23.y + bbv;
        __syncthreads();
    }
}

// ---------------- launcher ----------------
extern "C" void kernel_launch(void* const* d_in, const int* in_sizes, int n_in,
                              void* d_out, int out_size){
    const float* x    = (const float*)d_in[0];
    const int*   src1 = (const int*)d_in[1];
    const int*   dst1 = (const int*)d_in[2];
    const int*   src2 = (const int*)d_in[3];
    const int*   dst2 = (const int*)d_in[4];
    const float* W1   = (const float*)d_in[5];
    const float* al1  = (const float*)d_in[6];
    const float* ar1  = (const float*)d_in[7];
    const float* W2   = (const float*)d_in[8];
    const float* al2  = (const float*)d_in[9];
    const float* ar2  = (const float*)d_in[10];
    const float* bn1g = (const float*)d_in[11];
    const float* bn1b = (const float*)d_in[12];
    const float* bn2g = (const float*)d_in[13];
    const float* bn2b = (const float*)d_in[14];
    const float* fw1  = (const float*)d_in[15];
    const float* fb1  = (const float*)d_in[16];
    const float* fw2  = (const float*)d_in[17];
    const float* fb2  = (const float*)d_in[18];
    float* out = (float*)d_out;

    cudaFuncSetAttribute(ff_kernel, cudaFuncAttributeMaxDynamicSharedMemorySize, FF_SMEM);

    csr_clear<<<(2*(Nn+1) + 255)/256, 256>>>();
    csr_hist<<<(2*Ee + 255)/256, 256>>>(dst1, dst2);
    csr_scan<<<1, 1024>>>();
    csr_scatter<<<(2*Ee + 255)/256, 256>>>(src1, dst1, src2, dst2);

    zel_kernel<<<NTc/24, 256>>>(x, bn1g, bn1b, W1, al1, ar1, W2, al2, ar2);
    gat_kernel<<<Nn, 384>>>(x, bn2g, bn2b);
    ff_kernel<<<296, 256, FF_SMEM>>>(fw1, fb1, fw2, fb2, out);
}

// round 4
// speedup vs baseline: 2.0290x; 1.0117x over previous
#include <cuda_runtime.h>
#include <math.h>

#define Nn   10000
#define Tt   12
#define Ee   100000
#define NTc  (Nn*Tt)        // 120000
#define NTDc (NTc*64)       // 7680000
#define CAP  128            // smem edge cache per relation (deg avg ~10)

typedef unsigned long long ull;

// ---------------- scratch ----------------
__device__ float g_h[NTDc];          // BN2 output (input to FFN)
__device__ float g_z[2][NTDc];       // per-relation projected features
__device__ float g_x2[NTDc];         // residual x + m1 + m2
__device__ float g_el[2][NTc*4];
__device__ float g_er[2][NTc*4];
__device__ int   g_cnt[2*(Nn+1)];
__device__ int   g_rowptr[2*(Nn+1)];
__device__ int   g_fill[2*Nn];
__device__ int   g_esrc[2][Ee];

// ---------------- f32x2 helpers ----------------
__device__ __forceinline__ ull pk(float a, float b){
    ull r;
    asm("mov.b64 %0, {%1, %2};" : "=l"(r) : "r"(__float_as_uint(a)), "r"(__float_as_uint(b)));
    return r;
}
__device__ __forceinline__ ull fma2(ull a, ull b, ull c){
    ull d;
    asm("fma.rn.f32x2 %0, %1, %2, %3;" : "=l"(d) : "l"(a), "l"(b), "l"(c));
    return d;
}
__device__ __forceinline__ float2 upk(ull v){
    unsigned lo, hi;
    asm("mov.b64 {%0, %1}, %2;" : "=r"(lo), "=r"(hi) : "l"(v));
    return make_float2(__uint_as_float(lo), __uint_as_float(hi));
}

// ---------------- CSR build ----------------
__global__ void csr_clear(){
    int i = blockIdx.x * 256 + threadIdx.x;
    if (i < 2*(Nn+1)) g_cnt[i] = 0;
}
__global__ void csr_hist(const int* __restrict__ dst1, const int* __restrict__ dst2){
    int e = blockIdx.x * 256 + threadIdx.x;
    if (e < Ee)            atomicAdd(&g_cnt[dst1[e] + 1], 1);
    else if (e < 2*Ee)     atomicAdd(&g_cnt[(Nn+1) + dst2[e-Ee] + 1], 1);
}
__global__ void csr_scan(){
    __shared__ int wsum[32];
    int tid = threadIdx.x, lane = tid & 31, w = tid >> 5;
    for (int rel = 0; rel < 2; rel++){
        const int* cnt = g_cnt    + rel*(Nn+1);
        int*       rp  = g_rowptr + rel*(Nn+1);
        int*       fl  = g_fill   + rel*Nn;
        int base = tid * 10;
        int v[10]; int s = 0;
        #pragma unroll
        for (int i = 0; i < 10; i++){
            int idx = base + i;
            int c = (idx <= Nn) ? cnt[idx] : 0;
            s += c; v[i] = s;
        }
        int t = s;
        #pragma unroll
        for (int o = 1; o < 32; o <<= 1){
            int u = __shfl_up_sync(0xffffffffu, t, o);
            if (lane >= o) t += u;
        }
        if (lane == 31) wsum[w] = t;
        __syncthreads();
        if (w == 0){
            int ws = wsum[lane];
            #pragma unroll
            for (int o = 1; o < 32; o <<= 1){
                int u = __shfl_up_sync(0xffffffffu, ws, o);
                if (lane >= o) ws += u;
            }
            wsum[lane] = ws;
        }
        __syncthreads();
        int off = ((w > 0) ? wsum[w-1] : 0) + (t - s);
        #pragma unroll
        for (int i = 0; i < 10; i++){
            int idx = base + i;
            if (idx <= Nn){
                int val = off + v[i];
                rp[idx] = val;
                if (idx < Nn) fl[idx] = val;
            }
        }
        __syncthreads();
    }
}
__global__ void csr_scatter(const int* __restrict__ src1, const int* __restrict__ dst1,
                            const int* __restrict__ src2, const int* __restrict__ dst2){
    int e = blockIdx.x * 256 + threadIdx.x;
    if (e < Ee){
        int p = atomicAdd(&g_fill[dst1[e]], 1);
        g_esrc[0][p] = src1[e];
    } else if (e < 2*Ee){
        int p = atomicAdd(&g_fill[Nn + dst2[e-Ee]], 1);
        g_esrc[1][p] = src2[e-Ee];
    }
}

// ---------------- fused BN1 + dual-relation z/el/er ----------------
__global__ void zel_kernel(const float* __restrict__ x,
                           const float* __restrict__ bg, const float* __restrict__ bb,
                           const float* __restrict__ W1, const float* __restrict__ al1, const float* __restrict__ ar1,
                           const float* __restrict__ W2, const float* __restrict__ al2, const float* __restrict__ ar2){
    __shared__ float sh2[64*26];     // [d][row] interleaved (pad 26)
    __shared__ float sW[4096];
    __shared__ float red[4];
    int tid  = threadIdx.x;
    int lane = tid & 31;
    int nt0  = blockIdx.x * 24;
    int n0   = blockIdx.x * 2;

    if (tid < 4) red[tid] = 0.f;
    __syncthreads();

    float sA = 0.f, qA = 0.f, sB = 0.f, qB = 0.f;
    #pragma unroll
    for (int k = 0; k < 6; k++){
        int i = tid + k*256;
        float v = x[(size_t)nt0*64 + i];
        int r = i >> 6, d = i & 63;
        sh2[d*26 + r] = v;
        if (r < 12){ sA += v; qA += v*v; } else { sB += v; qB += v*v; }
    }
    #pragma unroll
    for (int o = 16; o; o >>= 1){
        sA += __shfl_xor_sync(0xffffffffu, sA, o);
        qA += __shfl_xor_sync(0xffffffffu, qA, o);
        sB += __shfl_xor_sync(0xffffffffu, sB, o);
        qB += __shfl_xor_sync(0xffffffffu, qB, o);
    }
    if (lane == 0){
        atomicAdd(&red[0], sA); atomicAdd(&red[1], qA);
        atomicAdd(&red[2], sB); atomicAdd(&red[3], qB);
    }
    __syncthreads();
    float mA = red[0]*(1.f/768.f), vA = red[1]*(1.f/768.f) - mA*mA;
    float mB = red[2]*(1.f/768.f), vB = red[3]*(1.f/768.f) - mB*mB;
    float scA = rsqrtf(vA + 1e-5f) * bg[n0];
    float shA = bb[n0]   - mA*scA;
    float scB = rsqrtf(vB + 1e-5f) * bg[n0+1];
    float shB = bb[n0+1] - mB*scB;
    #pragma unroll
    for (int k = 0; k < 6; k++){
        int i = tid + k*256;
        int r = i >> 6, d = i & 63;
        float v = sh2[d*26 + r];
        sh2[d*26 + r] = (r < 12) ? v*scA + shA : v*scB + shB;
    }
    __syncthreads();

    int c0 = tid & 31;      // column pair (2c0, 2c0+1)
    int rg = tid >> 5;      // rows rg, rg+8, rg+16
    for (int rel = 0; rel < 2; rel++){
        const float* W  = rel ? W2  : W1;
        const float* al = rel ? al2 : al1;
        const float* ar = rel ? ar2 : ar1;
        for (int i = tid; i < 4096; i += 256) sW[i] = W[i];
        __syncthreads();

        ull a0 = 0ull, a1 = 0ull, a2 = 0ull;
        #pragma unroll
        for (int d = 0; d < 64; d++){
            ull w01 = *(const ull*)&sW[d*64 + 2*c0];
            float h0 = sh2[d*26 + rg];
            float h1 = sh2[d*26 + rg + 8];
            float h2 = sh2[d*26 + rg + 16];
            a0 = fma2(w01, pk(h0, h0), a0);
            a1 = fma2(w01, pk(h1, h1), a1);
            a2 = fma2(w01, pk(h2, h2), a2);
        }
        float alv0 = al[2*c0], alv1 = al[2*c0+1];
        float arv0 = ar[2*c0], arv1 = ar[2*c0+1];
        ull accs[3] = {a0, a1, a2};
        #pragma unroll
        for (int k = 0; k < 3; k++){
            int r  = rg + 8*k;
            int nt = nt0 + r;
            *(ull*)&g_z[rel][(size_t)nt*64 + 2*c0] = accs[k];
            float2 zp = upk(accs[k]);
            float pl = zp.x*alv0 + zp.y*alv1;
            float pr = zp.x*arv0 + zp.y*arv1;
            #pragma unroll
            for (int o = 4; o; o >>= 1){
                pl += __shfl_xor_sync(0xffffffffu, pl, o);
                pr += __shfl_xor_sync(0xffffffffu, pr, o);
            }
            if ((c0 & 7) == 0){
                g_el[rel][nt*4 + (c0>>3)] = pl;
                g_er[rel][nt*4 + (c0>>3)] = pr;
            }
        }
        __syncthreads();
    }
}

// ---------------- fused GAT (both rels) + residual + BN2 ----------------
// block = node d, 12 warps (one per t).
// Phase 1 (lane-parallel, edges across lanes): load el float4 once, compute
// leaky, warp-max, exp, warp-sum denom, cache weights in smem.
// Phase 2 (serial over edges, independent loads): z gather + FMA.
__global__ void gat_kernel(const float* __restrict__ x,
                           const float* __restrict__ bg, const float* __restrict__ bb){
    __shared__ int   s_src[2][CAP];
    __shared__ float s_w[12][CAP*4];      // weights per (t, edge, head)
    __shared__ float sms[12], sqs[12];

    const unsigned FULL = 0xffffffffu;
    int d    = blockIdx.x;
    int tid  = threadIdx.x;
    int t    = tid >> 5;
    int lane = tid & 31;
    int h0   = lane >> 4;       // head idx for cols 0..31 (0/1)
    int h1   = 2 + h0;          // head idx for cols 32..63 (2/3)

    int beg[2], deg[2];
    #pragma unroll
    for (int rel = 0; rel < 2; rel++){
        beg[rel] = g_rowptr[rel*(Nn+1) + d];
        deg[rel] = g_rowptr[rel*(Nn+1) + d + 1] - beg[rel];
        for (int i = tid; i < min(deg[rel], CAP); i += 384)
            s_src[rel][i] = g_esrc[rel][beg[rel] + i];
    }
    __syncthreads();

    float m0 = 0.f, m1 = 0.f;

    #pragma unroll
    for (int rel = 0; rel < 2; rel++){
        int dg = deg[rel], bg_e = beg[rel];
        const float* el = g_el[rel];
        const float* zb = g_z[rel];
        float4 er4 = *(const float4*)&g_er[rel][d*48 + t*4];

        // ---- phase 1: attention weights (lane-parallel over edges) ----
        float mx0 = -1e30f, mx1 = -1e30f, mx2 = -1e30f, mx3 = -1e30f;
        for (int e = lane; e < dg; e += 32){
            int s = (e < CAP) ? s_src[rel][e] : g_esrc[rel][bg_e + e];
            float4 e4 = *(const float4*)&el[s*48 + t*4];
            float a0 = e4.x + er4.x, a1 = e4.y + er4.y;
            float a2 = e4.z + er4.z, a3 = e4.w + er4.w;
            a0 = (a0 > 0.f) ? a0 : 0.2f*a0;
            a1 = (a1 > 0.f) ? a1 : 0.2f*a1;
            a2 = (a2 > 0.f) ? a2 : 0.2f*a2;
            a3 = (a3 > 0.f) ? a3 : 0.2f*a3;
            if (e < CAP){
                float4 st = make_float4(a0, a1, a2, a3);
                *(float4*)&s_w[t][e*4] = st;
            }
            mx0 = fmaxf(mx0, a0); mx1 = fmaxf(mx1, a1);
            mx2 = fmaxf(mx2, a2); mx3 = fmaxf(mx3, a3);
        }
        #pragma unroll
        for (int o = 16; o; o >>= 1){
            mx0 = fmaxf(mx0, __shfl_xor_sync(FULL, mx0, o));
            mx1 = fmaxf(mx1, __shfl_xor_sync(FULL, mx1, o));
            mx2 = fmaxf(mx2, __shfl_xor_sync(FULL, mx2, o));
            mx3 = fmaxf(mx3, __shfl_xor_sync(FULL, mx3, o));
        }
        float dn0 = 0.f, dn1 = 0.f, dn2 = 0.f, dn3 = 0.f;
        for (int e = lane; e < dg; e += 32){
            float a0, a1, a2, a3;
            if (e < CAP){
                float4 a4 = *(const float4*)&s_w[t][e*4];
                a0 = a4.x; a1 = a4.y; a2 = a4.z; a3 = a4.w;
            } else {
                int s = g_esrc[rel][bg_e + e];
                float4 e4 = *(const float4*)&el[s*48 + t*4];
                a0 = e4.x + er4.x; a1 = e4.y + er4.y;
                a2 = e4.z + er4.z; a3 = e4.w + er4.w;
                a0 = (a0 > 0.f) ? a0 : 0.2f*a0;
                a1 = (a1 > 0.f) ? a1 : 0.2f*a1;
                a2 = (a2 > 0.f) ? a2 : 0.2f*a2;
                a3 = (a3 > 0.f) ? a3 : 0.2f*a3;
            }
            float w0 = __expf(a0 - mx0), w1 = __expf(a1 - mx1);
            float w2 = __expf(a2 - mx2), w3 = __expf(a3 - mx3);
            dn0 += w0; dn1 += w1; dn2 += w2; dn3 += w3;
            if (e < CAP){
                float4 st = make_float4(w0, w1, w2, w3);
                *(float4*)&s_w[t][e*4] = st;
            }
        }
        #pragma unroll
        for (int o = 16; o; o >>= 1){
            dn0 += __shfl_xor_sync(FULL, dn0, o);
            dn1 += __shfl_xor_sync(FULL, dn1, o);
            dn2 += __shfl_xor_sync(FULL, dn2, o);
            dn3 += __shfl_xor_sync(FULL, dn3, o);
        }
        float invA = 1.f / fmaxf((h0 == 0) ? dn0 : dn1, 1e-16f);
        float invB = 1.f / fmaxf((h0 == 0) ? dn2 : dn3, 1e-16f);
        float mxA  = (h0 == 0) ? mx0 : mx1;
        float mxB  = (h0 == 0) ? mx2 : mx3;

        __syncwarp();

        // ---- phase 2: weighted gather (independent loads) ----
        float ac0 = 0.f, ac1 = 0.f;
        int ecached = min(dg, CAP);
        #pragma unroll 2
        for (int e = 0; e < ecached; ++e){
            int s = s_src[rel][e];
            float w0 = s_w[t][e*4 + h0];
            float w1 = s_w[t][e*4 + h1];
            const float* zr = zb + (size_t)s*768 + t*64;
            ac0 = fmaf(w0, zr[lane],      ac0);
            ac1 = fmaf(w1, zr[32 + lane], ac1);
        }
        for (int e = ecached; e < dg; ++e){   // cold path (deg > CAP)
            int s = g_esrc[rel][bg_e + e];
            float4 e4 = *(const float4*)&el[s*48 + t*4];
            float aA = ((h0 == 0) ? e4.x : e4.y) + ((h0 == 0) ? er4.x : er4.y);
            float aB = ((h0 == 0) ? e4.z : e4.w) + ((h0 == 0) ? er4.z : er4.w);
            aA = (aA > 0.f) ? aA : 0.2f*aA;
            aB = (aB > 0.f) ? aB : 0.2f*aB;
            float w0 = __expf(aA - mxA), w1 = __expf(aB - mxB);
            const float* zr = zb + (size_t)s*768 + t*64;
            ac0 = fmaf(w0, zr[lane],      ac0);
            ac1 = fmaf(w1, zr[32 + lane], ac1);
        }
        m0 += ac0 * invA;
        m1 += ac1 * invB;
        __syncthreads();   // protect s_w reuse across relations
    }

    size_t idx = (size_t)d*768 + t*64 + lane;
    float v0 = x[idx]      + m0;
    float v1 = x[idx + 32] + m1;

    // BN2 over this node's 768 values
    float s = v0 + v1;
    float q = v0*v0 + v1*v1;
    #pragma unroll
    for (int o = 16; o; o >>= 1){
        s += __shfl_xor_sync(FULL, s, o);
        q += __shfl_xor_sync(FULL, q, o);
    }
    if (lane == 0){ sms[t] = s; sqs[t] = q; }
    __syncthreads();
    float ts = 0.f, tq = 0.f;
    #pragma unroll
    for (int i = 0; i < 12; i++){ ts += sms[i]; tq += sqs[i]; }
    float mean = ts * (1.f/768.f);
    float var  = tq * (1.f/768.f) - mean*mean;
    float sc   = rsqrtf(var + 1e-5f) * bg[d];
    float sb   = bb[d] - mean*sc;

    g_x2[idx]      = v0;
    g_x2[idx + 32] = v1;
    g_h[idx]       = v0*sc + sb;
    g_h[idx + 32]  = v1*sc + sb;
}

// ---------------- FFN with f32x2: out = x2 + gelu(h@W1+b1)@W2+b2 ----------------
#define FF_SMEM (80128)
__global__ void ff_kernel(const float* __restrict__ w1, const float* __restrict__ b1,
                          const float* __restrict__ w2, const float* __restrict__ b2,
                          float* __restrict__ out){
    extern __shared__ float sm[];
    float* sW1 = sm;                 // 64*128
    float* sW2 = sW1 + 8192;         // 128*64
    float* sB1 = sW2 + 8192;         // 128
    float* sB2 = sB1 + 128;          // 64
    float* sX  = sB2 + 64;           // 64*18  [d][row]
    float* sG  = sX  + 64*18;        // 128*18 [j][row]
    int tid = threadIdx.x;
    for (int i = tid; i < 8192; i += 256) sW1[i] = w1[i];
    for (int i = tid; i < 8192; i += 256) sW2[i] = w2[i];
    if (tid < 128) sB1[tid] = b1[tid];
    if (tid < 64)  sB2[tid] = b2[tid];
    __syncthreads();

    int j    = tid & 127;
    int half = tid >> 7;     // rows 8*half .. 8*half+7
    int dcol = tid & 63;
    int rq   = tid >> 6;     // rows 4*rq .. 4*rq+3

    for (int grp = blockIdx.x; grp < NTc/16; grp += gridDim.x){
        int row0 = grp * 16;
        #pragma unroll
        for (int k = 0; k < 4; k++){
            int i = tid + k*256;
            float v = g_h[(size_t)row0*64 + i];
            sX[(i & 63)*18 + (i >> 6)] = v;
        }
        __syncthreads();

        ull p0 = 0ull, p1 = 0ull, p2 = 0ull, p3 = 0ull;
        #pragma unroll
        for (int dd = 0; dd < 64; dd++){
            float w = sW1[dd*128 + j];
            ull ww = pk(w, w);
            const float* xb = &sX[dd*18 + half*8];
            p0 = fma2(*(const ull*)&xb[0], ww, p0);
            p1 = fma2(*(const ull*)&xb[2], ww, p1);
            p2 = fma2(*(const ull*)&xb[4], ww, p2);
            p3 = fma2(*(const ull*)&xb[6], ww, p3);
        }
        float bj = sB1[j];
        float2 f0 = upk(p0), f1 = upk(p1), f2 = upk(p2), f3 = upk(p3);
        float av[8] = {f0.x+bj, f0.y+bj, f1.x+bj, f1.y+bj, f2.x+bj, f2.y+bj, f3.x+bj, f3.y+bj};
        float gv[8];
        #pragma unroll
        for (int r = 0; r < 8; r++)
            gv[r] = 0.5f * av[r] * (1.f + erff(av[r] * 0.70710678118654752f));
        float* gb = &sG[j*18 + half*8];
        *(ull*)&gb[0] = pk(gv[0], gv[1]);
        *(ull*)&gb[2] = pk(gv[2], gv[3]);
        *(ull*)&gb[4] = pk(gv[4], gv[5]);
        *(ull*)&gb[6] = pk(gv[6], gv[7]);
        __syncthreads();

        ull q0 = 0ull, q1 = 0ull;
        #pragma unroll
        for (int jj = 0; jj < 128; jj++){
            float w = sW2[jj*64 + dcol];
            ull ww = pk(w, w);
            const float* gg = &sG[jj*18 + rq*4];
            q0 = fma2(*(const ull*)&gg[0], ww, q0);
            q1 = fma2(*(const ull*)&gg[2], ww, q1);
        }
        float2 r01 = upk(q0), r23 = upk(q1);
        float bbv = sB2[dcol];
        size_t ob = (size_t)(row0 + rq*4)*64 + dcol;
        out[ob]       = g_x2[ob]       + r01.x + bbv;
        out[ob + 64]  = g_x2[ob + 64]  + r01.y + bbv;
        out[ob + 128] = g_x2[ob + 128] + r23.x + bbv;
        out[ob + 192] = g_x2[ob + 192] + r23.y + bbv;
        __syncthreads();
    }
}

// ---------------- launcher ----------------
extern "C" void kernel_launch(void* const* d_in, const int* in_sizes, int n_in,
                              void* d_out, int out_size){
    const float* x    = (const float*)d_in[0];
    const int*   src1 = (const int*)d_in[1];
    const int*   dst1 = (const int*)d_in[2];
    const int*   src2 = (const int*)d_in[3];
    const int*   dst2 = (const int*)d_in[4];
    const float* W1   = (const float*)d_in[5];
    const float* al1  = (const float*)d_in[6];
    const float* ar1  = (const float*)d_in[7];
    const float* W2   = (const float*)d_in[8];
    const float* al2  = (const float*)d_in[9];
    const float* ar2  = (const float*)d_in[10];
    const float* bn1g = (const float*)d_in[11];
    const float* bn1b = (const float*)d_in[12];
    const float* bn2g = (const float*)d_in[13];
    const float* bn2b = (const float*)d_in[14];
    const float* fw1  = (const float*)d_in[15];
    const float* fb1  = (const float*)d_in[16];
    const float* fw2  = (const float*)d_in[17];
    const float* fb2  = (const float*)d_in[18];
    float* out = (float*)d_out;

    cudaFuncSetAttribute(ff_kernel, cudaFuncAttributeMaxDynamicSharedMemorySize, FF_SMEM);

    csr_clear<<<(2*(Nn+1) + 255)/256, 256>>>();
    csr_hist<<<(2*Ee + 255)/256, 256>>>(dst1, dst2);
    csr_scan<<<1, 1024>>>();
    csr_scatter<<<(2*Ee + 255)/256, 256>>>(src1, dst1, src2, dst2);

    zel_kernel<<<NTc/24, 256>>>(x, bn1g, bn1b, W1, al1, ar1, W2, al2, ar2);
    gat_kernel<<<Nn, 384>>>(x, bn2g, bn2b);
    ff_kernel<<<296, 256, FF_SMEM>>>(fw1, fb1, fw2, fb2, out);
}

// round 5
// speedup vs baseline: 2.2807x; 1.1240x over previous
#include <cuda_runtime.h>
#include <math.h>

#define Nn   10000
#define Tt   12
#define Ee   100000
#define NTc  (Nn*Tt)        // 120000
#define NTDc (NTc*64)       // 7680000
#define CAP  128

typedef unsigned long long ull;

// ---------------- scratch ----------------
__device__ float g_h[NTDc];          // BN2 output (input to FFN)
__device__ float g_z[2][NTDc];       // per-relation projected features
__device__ float g_x2[NTDc];         // residual x + m1 + m2
__device__ float g_el[2][NTc*4];
__device__ float g_er[2][NTc*4];
__device__ int   g_cnt[2*(Nn+1)];
__device__ int   g_rowptr[2*(Nn+1)];
__device__ int   g_fill[2*Nn];
__device__ int   g_esrc[2][Ee];

// ---------------- f32x2 helpers ----------------
__device__ __forceinline__ ull pk(float a, float b){
    ull r;
    asm("mov.b64 %0, {%1, %2};" : "=l"(r) : "r"(__float_as_uint(a)), "r"(__float_as_uint(b)));
    return r;
}
__device__ __forceinline__ ull fma2(ull a, ull b, ull c){
    ull d;
    asm("fma.rn.f32x2 %0, %1, %2, %3;" : "=l"(d) : "l"(a), "l"(b), "l"(c));
    return d;
}
__device__ __forceinline__ ull mul2(ull a, ull b){
    ull d;
    asm("mul.rn.f32x2 %0, %1, %2;" : "=l"(d) : "l"(a), "l"(b));
    return d;
}
__device__ __forceinline__ ull add2(ull a, ull b){
    ull d;
    asm("add.rn.f32x2 %0, %1, %2;" : "=l"(d) : "l"(a), "l"(b));
    return d;
}
__device__ __forceinline__ float2 upk(ull v){
    unsigned lo, hi;
    asm("mov.b64 {%0, %1}, %2;" : "=r"(lo), "=r"(hi) : "l"(v));
    return make_float2(__uint_as_float(lo), __uint_as_float(hi));
}

// ---------------- CSR build ----------------
__global__ void csr_clear(){
    int i = blockIdx.x * 256 + threadIdx.x;
    if (i < 2*(Nn+1)) g_cnt[i] = 0;
}
__global__ void csr_hist(const int* __restrict__ dst1, const int* __restrict__ dst2){
    int e = blockIdx.x * 256 + threadIdx.x;
    if (e < Ee)            atomicAdd(&g_cnt[dst1[e] + 1], 1);
    else if (e < 2*Ee)     atomicAdd(&g_cnt[(Nn+1) + dst2[e-Ee] + 1], 1);
}
__global__ void csr_scan(){
    __shared__ int wsum[32];
    int tid = threadIdx.x, lane = tid & 31, w = tid >> 5;
    for (int rel = 0; rel < 2; rel++){
        const int* cnt = g_cnt    + rel*(Nn+1);
        int*       rp  = g_rowptr + rel*(Nn+1);
        int*       fl  = g_fill   + rel*Nn;
        int base = tid * 10;
        int v[10]; int s = 0;
        #pragma unroll
        for (int i = 0; i < 10; i++){
            int idx = base + i;
            int c = (idx <= Nn) ? cnt[idx] : 0;
            s += c; v[i] = s;
        }
        int t = s;
        #pragma unroll
        for (int o = 1; o < 32; o <<= 1){
            int u = __shfl_up_sync(0xffffffffu, t, o);
            if (lane >= o) t += u;
        }
        if (lane == 31) wsum[w] = t;
        __syncthreads();
        if (w == 0){
            int ws = wsum[lane];
            #pragma unroll
            for (int o = 1; o < 32; o <<= 1){
                int u = __shfl_up_sync(0xffffffffu, ws, o);
                if (lane >= o) ws += u;
            }
            wsum[lane] = ws;
        }
        __syncthreads();
        int off = ((w > 0) ? wsum[w-1] : 0) + (t - s);
        #pragma unroll
        for (int i = 0; i < 10; i++){
            int idx = base + i;
            if (idx <= Nn){
                int val = off + v[i];
                rp[idx] = val;
                if (idx < Nn) fl[idx] = val;
            }
        }
        __syncthreads();
    }
}
__global__ void csr_scatter(const int* __restrict__ src1, const int* __restrict__ dst1,
                            const int* __restrict__ src2, const int* __restrict__ dst2){
    int e = blockIdx.x * 256 + threadIdx.x;
    if (e < Ee){
        int p = atomicAdd(&g_fill[dst1[e]], 1);
        g_esrc[0][p] = src1[e];
    } else if (e < 2*Ee){
        int p = atomicAdd(&g_fill[Nn + dst2[e-Ee]], 1);
        g_esrc[1][p] = src2[e-Ee];
    }
}

// ---------------- fused BN1 + dual-relation z/el/er (register-tiled) ---------
// block = 4 nodes = 48 rows, 256 threads (8 warps).
// warp w: cols [16*(w&3), +16) (= head w&3), k-half (w>>2).
// lane: rg = lane>>3 -> rows rg*12..+11 ; cg = lane&7 -> col pair c0 = 16wcol+2cg
__global__ void zel_kernel(const float* __restrict__ x,
                           const float* __restrict__ bg, const float* __restrict__ bb,
                           const float* __restrict__ W1, const float* __restrict__ al1, const float* __restrict__ ar1,
                           const float* __restrict__ W2, const float* __restrict__ al2, const float* __restrict__ ar2){
    __shared__ float sh[64*50];      // [k][row], stride 50
    __shared__ float sW[64*64];      // [k][c]
    __shared__ float zred[64*50];    // [c][row], stride 50
    __shared__ float red[8];
    __shared__ float nsc[4], nsh[4];

    int tid  = threadIdx.x;
    int lane = tid & 31;
    int w    = tid >> 5;
    int wcol = w & 3;
    int khalf= w >> 2;
    int rg   = lane >> 3;
    int cg   = lane & 7;
    int r0   = rg * 12;
    int c0   = wcol*16 + 2*cg;
    int nt0  = blockIdx.x * 48;
    int nd0  = blockIdx.x * 4;

    if (tid < 8) red[tid] = 0.f;
    __syncthreads();

    // stage x -> sh[k][row], accumulate per-node BN stats
    float ls[4] = {0,0,0,0}, lq[4] = {0,0,0,0};
    #pragma unroll
    for (int it = 0; it < 12; it++){
        int i = tid + it*256;
        float v = x[(size_t)nt0*64 + i];
        int row = i >> 6, d = i & 63;
        sh[d*50 + row] = v;
        int nl = row / 12;
        ls[nl] += v; lq[nl] += v*v;
    }
    #pragma unroll
    for (int nl = 0; nl < 4; nl++){
        #pragma unroll
        for (int o = 16; o; o >>= 1){
            ls[nl] += __shfl_xor_sync(0xffffffffu, ls[nl], o);
            lq[nl] += __shfl_xor_sync(0xffffffffu, lq[nl], o);
        }
    }
    if (lane == 0){
        #pragma unroll
        for (int nl = 0; nl < 4; nl++){
            if (ls[nl] != 0.f || lq[nl] != 0.f){
                atomicAdd(&red[2*nl],   ls[nl]);
                atomicAdd(&red[2*nl+1], lq[nl]);
            }
        }
    }
    __syncthreads();
    if (tid < 4){
        float mean = red[2*tid] * (1.f/768.f);
        float var  = red[2*tid+1] * (1.f/768.f) - mean*mean;
        float sc   = rsqrtf(var + 1e-5f) * bg[nd0 + tid];
        nsc[tid] = sc;
        nsh[tid] = bb[nd0 + tid] - mean*sc;
    }
    __syncthreads();
    #pragma unroll
    for (int it = 0; it < 12; it++){
        int i = tid + it*256;
        int row = i >> 6, d = i & 63;
        int nl = row / 12;
        sh[d*50 + row] = sh[d*50 + row]*nsc[nl] + nsh[nl];
    }
    __syncthreads();

    for (int rel = 0; rel < 2; rel++){
        const float* W  = rel ? W2  : W1;
        const float* al = rel ? al2 : al1;
        const float* ar = rel ? ar2 : ar1;
        for (int i = tid; i < 4096; i += 256) sW[i] = W[i];
        __syncthreads();

        // acc[c][rp]: 2 cols x 6 row-pairs (f32x2 over rows)
        ull acc[2][6];
        #pragma unroll
        for (int c = 0; c < 2; c++)
            #pragma unroll
            for (int i = 0; i < 6; i++) acc[c][i] = 0ull;

        int kb = khalf * 32;
        #pragma unroll 4
        for (int kk = 0; kk < 32; kk++){
            int k = kb + kk;
            ull w2v = *(const ull*)&sW[k*64 + c0];
            float2 wf = upk(w2v);
            ull ws0 = pk(wf.x, wf.x);
            ull ws1 = pk(wf.y, wf.y);
            const float* hb = &sh[k*50 + r0];
            #pragma unroll
            for (int i = 0; i < 6; i++){
                ull h2 = *(const ull*)&hb[2*i];
                acc[0][i] = fma2(h2, ws0, acc[0][i]);
                acc[1][i] = fma2(h2, ws1, acc[1][i]);
            }
        }

        // k-split reduction via zred[c][row]
        if (khalf == 1){
            #pragma unroll
            for (int c = 0; c < 2; c++)
                #pragma unroll
                for (int i = 0; i < 6; i++)
                    *(ull*)&zred[(c0+c)*50 + r0 + 2*i] = acc[c][i];
        }
        __syncthreads();
        if (khalf == 0){
            #pragma unroll
            for (int c = 0; c < 2; c++)
                #pragma unroll
                for (int i = 0; i < 6; i++)
                    acc[c][i] = add2(acc[c][i], *(const ull*)&zred[(c0+c)*50 + r0 + 2*i]);
            // store final z back to zred
            #pragma unroll
            for (int c = 0; c < 2; c++)
                #pragma unroll
                for (int i = 0; i < 6; i++)
                    *(ull*)&zred[(c0+c)*50 + r0 + 2*i] = acc[c][i];

            // el/er partials: dot over this thread's 2 cols, f32x2 over row pairs
            ull al0 = pk(al[c0], al[c0]),   al1v = pk(al[c0+1], al[c0+1]);
            ull ar0 = pk(ar[c0], ar[c0]),   ar1v = pk(ar[c0+1], ar[c0+1]);
            ull pl[6], pr[6];
            #pragma unroll
            for (int i = 0; i < 6; i++){
                pl[i] = fma2(acc[1][i], al1v, mul2(acc[0][i], al0));
                pr[i] = fma2(acc[1][i], ar1v, mul2(acc[0][i], ar0));
            }
            #pragma unroll
            for (int o = 1; o < 8; o <<= 1){
                #pragma unroll
                for (int i = 0; i < 6; i++){
                    pl[i] = add2(pl[i], __shfl_xor_sync(0xffffffffu, pl[i], o));
                    pr[i] = add2(pr[i], __shfl_xor_sync(0xffffffffu, pr[i], o));
                }
            }
            if (cg == 0){
                #pragma unroll
                for (int i = 0; i < 6; i++){
                    float2 fl = upk(pl[i]);
                    float2 fr = upk(pr[i]);
                    int nt = nt0 + r0 + 2*i;
                    g_el[rel][nt*4 + wcol]     = fl.x;
                    g_el[rel][(nt+1)*4 + wcol] = fl.y;
                    g_er[rel][nt*4 + wcol]     = fr.x;
                    g_er[rel][(nt+1)*4 + wcol] = fr.y;
                }
            }
        }
        __syncthreads();
        // coalesced z write from zred
        #pragma unroll
        for (int it = 0; it < 12; it++){
            int i = tid + it*256;
            int row = i >> 6, d = i & 63;
            g_z[rel][(size_t)nt0*64 + i] = zred[d*50 + row];
        }
        __syncthreads();
    }
}

// ---------------- fused GAT (both rels) + residual + BN2 ----------------
// block = node d, 12 warps (one per t); lane covers col pair (2l, 2l+1).
__global__ void gat_kernel(const float* __restrict__ x,
                           const float* __restrict__ bg, const float* __restrict__ bb){
    __shared__ int   s_src[2][CAP];
    __shared__ float s_w[12][CAP*4];
    __shared__ float sms[12], sqs[12];

    const unsigned FULL = 0xffffffffu;
    int d    = blockIdx.x;
    int tid  = threadIdx.x;
    int t    = tid >> 5;
    int lane = tid & 31;
    int hA   = lane >> 3;       // head for cols (2l, 2l+1)

    int beg[2], deg[2];
    #pragma unroll
    for (int rel = 0; rel < 2; rel++){
        beg[rel] = g_rowptr[rel*(Nn+1) + d];
        deg[rel] = g_rowptr[rel*(Nn+1) + d + 1] - beg[rel];
        for (int i = tid; i < min(deg[rel], CAP); i += 384)
            s_src[rel][i] = g_esrc[rel][beg[rel] + i];
    }
    __syncthreads();

    ull m2 = 0ull;

    #pragma unroll
    for (int rel = 0; rel < 2; rel++){
        int dg = deg[rel], bg_e = beg[rel];
        const float* el = g_el[rel];
        const float* zb = g_z[rel];
        float4 er4 = *(const float4*)&g_er[rel][d*48 + t*4];

        // phase 1: attention weights (lane-parallel over edges)
        float mx0 = -1e30f, mx1 = -1e30f, mx2 = -1e30f, mx3 = -1e30f;
        for (int e = lane; e < dg; e += 32){
            int s = (e < CAP) ? s_src[rel][e] : g_esrc[rel][bg_e + e];
            float4 e4 = *(const float4*)&el[s*48 + t*4];
            float a0 = e4.x + er4.x, a1 = e4.y + er4.y;
            float a2 = e4.z + er4.z, a3 = e4.w + er4.w;
            a0 = (a0 > 0.f) ? a0 : 0.2f*a0;
            a1 = (a1 > 0.f) ? a1 : 0.2f*a1;
            a2 = (a2 > 0.f) ? a2 : 0.2f*a2;
            a3 = (a3 > 0.f) ? a3 : 0.2f*a3;
            if (e < CAP)
                *(float4*)&s_w[t][e*4] = make_float4(a0, a1, a2, a3);
            mx0 = fmaxf(mx0, a0); mx1 = fmaxf(mx1, a1);
            mx2 = fmaxf(mx2, a2); mx3 = fmaxf(mx3, a3);
        }
        #pragma unroll
        for (int o = 16; o; o >>= 1){
            mx0 = fmaxf(mx0, __shfl_xor_sync(FULL, mx0, o));
            mx1 = fmaxf(mx1, __shfl_xor_sync(FULL, mx1, o));
            mx2 = fmaxf(mx2, __shfl_xor_sync(FULL, mx2, o));
            mx3 = fmaxf(mx3, __shfl_xor_sync(FULL, mx3, o));
        }
        float dn0 = 0.f, dn1 = 0.f, dn2 = 0.f, dn3 = 0.f;
        for (int e = lane; e < dg; e += 32){
            float a0, a1, a2, a3;
            if (e < CAP){
                float4 a4 = *(const float4*)&s_w[t][e*4];
                a0 = a4.x; a1 = a4.y; a2 = a4.z; a3 = a4.w;
            } else {
                int s = g_esrc[rel][bg_e + e];
                float4 e4 = *(const float4*)&el[s*48 + t*4];
                a0 = e4.x + er4.x; a1 = e4.y + er4.y;
                a2 = e4.z + er4.z; a3 = e4.w + er4.w;
                a0 = (a0 > 0.f) ? a0 : 0.2f*a0;
                a1 = (a1 > 0.f) ? a1 : 0.2f*a1;
                a2 = (a2 > 0.f) ? a2 : 0.2f*a2;
                a3 = (a3 > 0.f) ? a3 : 0.2f*a3;
            }
            float w0 = __expf(a0 - mx0), w1 = __expf(a1 - mx1);
            float w2 = __expf(a2 - mx2), w3 = __expf(a3 - mx3);
            dn0 += w0; dn1 += w1; dn2 += w2; dn3 += w3;
            if (e < CAP)
                *(float4*)&s_w[t][e*4] = make_float4(w0, w1, w2, w3);
        }
        #pragma unroll
        for (int o = 16; o; o >>= 1){
            dn0 += __shfl_xor_sync(FULL, dn0, o);
            dn1 += __shfl_xor_sync(FULL, dn1, o);
            dn2 += __shfl_xor_sync(FULL, dn2, o);
            dn3 += __shfl_xor_sync(FULL, dn3, o);
        }
        float dnA = (hA < 2) ? ((hA == 0) ? dn0 : dn1) : ((hA == 2) ? dn2 : dn3);
        float mxA = (hA < 2) ? ((hA == 0) ? mx0 : mx1) : ((hA == 2) ? mx2 : mx3);
        float erA = (hA < 2) ? ((hA == 0) ? er4.x : er4.y) : ((hA == 2) ? er4.z : er4.w);
        float inv = 1.f / fmaxf(dnA, 1e-16f);

        __syncwarp();

        // phase 2: weighted gather, f32x2 column pairs
        ull ac = 0ull;
        int ecached = min(dg, CAP);
        #pragma unroll 2
        for (int e = 0; e < ecached; ++e){
            int s = s_src[rel][e];
            float wv = s_w[t][e*4 + hA];
            ull z2 = *(const ull*)(zb + (size_t)s*768 + t*64 + 2*lane);
            ac = fma2(pk(wv, wv), z2, ac);
        }
        for (int e = ecached; e < dg; ++e){
            int s = g_esrc[rel][bg_e + e];
            float a = el[s*48 + t*4 + hA] + erA;
            a = (a > 0.f) ? a : 0.2f*a;
            float wv = __expf(a - mxA);
            ull z2 = *(const ull*)(zb + (size_t)s*768 + t*64 + 2*lane);
            ac = fma2(pk(wv, wv), z2, ac);
        }
        m2 = add2(m2, mul2(ac, pk(inv, inv)));
        __syncthreads();   // protect s_w reuse across relations
    }

    size_t idx = (size_t)d*768 + t*64 + 2*lane;
    float2 xm = upk(*(const ull*)&x[idx]);
    float2 mm = upk(m2);
    float v0 = xm.x + mm.x;
    float v1 = xm.y + mm.y;

    // BN2 over this node's 768 values
    float s = v0 + v1;
    float q = v0*v0 + v1*v1;
    #pragma unroll
    for (int o = 16; o; o >>= 1){
        s += __shfl_xor_sync(FULL, s, o);
        q += __shfl_xor_sync(FULL, q, o);
    }
    if (lane == 0){ sms[t] = s; sqs[t] = q; }
    __syncthreads();
    float ts = 0.f, tq = 0.f;
    #pragma unroll
    for (int i = 0; i < 12; i++){ ts += sms[i]; tq += sqs[i]; }
    float mean = ts * (1.f/768.f);
    float var  = tq * (1.f/768.f) - mean*mean;
    float sc   = rsqrtf(var + 1e-5f) * bg[d];
    float sb   = bb[d] - mean*sc;

    *(ull*)&g_x2[idx] = pk(v0, v1);
    *(ull*)&g_h[idx]  = pk(v0*sc + sb, v1*sc + sb);
}

// ---------------- FFN (register-tiled): out = x2 + gelu(h@W1+b1)@W2+b2 -------
// persistent grid=148, 256 threads, 64-row tiles.
// GEMM1: warp w -> rows 8w..8w+7 ; lane -> cols 4l..4l+3. acc[4c][4 rowpairs].
// GEMM2: same rows ; lane -> cols 2l..2l+1. acc[2c][4 rowpairs].
#define FF_SMEM ((8192 + 8192 + 128 + 64 + 64*68 + 128*68) * 4)
__global__ void ff_kernel(const float* __restrict__ w1, const float* __restrict__ b1,
                          const float* __restrict__ w2, const float* __restrict__ b2,
                          float* __restrict__ out){
    extern __shared__ float sm[];
    float* sW1 = sm;                   // [k][j] 64*128
    float* sW2 = sW1 + 8192;           // [j][c] 128*64
    float* sB1 = sW2 + 8192;           // 128
    float* sB2 = sB1 + 128;            // 64
    float* sX  = sB2 + 64;             // [k][r] 64*68
    float* sG  = sX  + 64*68;          // [j][r] 128*68

    int tid  = threadIdx.x;
    int w    = tid >> 5;
    int lane = tid & 31;

    for (int i = tid; i < 8192; i += 256) sW1[i] = w1[i];
    for (int i = tid; i < 8192; i += 256) sW2[i] = w2[i];
    if (tid < 128) sB1[tid] = b1[tid];
    if (tid < 64)  sB2[tid] = b2[tid];
    __syncthreads();

    float b2v0 = sB2[2*lane], b2v1 = sB2[2*lane+1];

    for (int tile = blockIdx.x; tile < NTc/64; tile += 148){
        int row0 = tile * 64;

        // stage sX[k][r]
        #pragma unroll
        for (int it = 0; it < 16; it++){
            int i = tid + it*256;
            int r = i >> 6, k = i & 63;
            sX[k*68 + r] = g_h[(size_t)row0*64 + i];
        }
        __syncthreads();

        // ---- GEMM1: 64x128, k=64 ----
        ull a1[4][4];
        #pragma unroll
        for (int c = 0; c < 4; c++)
            #pragma unroll
            for (int i = 0; i < 4; i++) a1[c][i] = 0ull;

        #pragma unroll 4
        for (int k = 0; k < 64; k++){
            double2 hd0 = *(const double2*)&sX[k*68 + 8*w];
            double2 hd1 = *(const double2*)&sX[k*68 + 8*w + 4];
            ull h01 = __double_as_longlong(hd0.x);
            ull h23 = __double_as_longlong(hd0.y);
            ull h45 = __double_as_longlong(hd1.x);
            ull h67 = __double_as_longlong(hd1.y);
            float4 wv = *(const float4*)&sW1[k*128 + 4*lane];
            ull ws0 = pk(wv.x, wv.x), ws1 = pk(wv.y, wv.y);
            ull ws2 = pk(wv.z, wv.z), ws3 = pk(wv.w, wv.w);
            a1[0][0] = fma2(h01, ws0, a1[0][0]);
            a1[0][1] = fma2(h23, ws0, a1[0][1]);
            a1[0][2] = fma2(h45, ws0, a1[0][2]);
            a1[0][3] = fma2(h67, ws0, a1[0][3]);
            a1[1][0] = fma2(h01, ws1, a1[1][0]);
            a1[1][1] = fma2(h23, ws1, a1[1][1]);
            a1[1][2] = fma2(h45, ws1, a1[1][2]);
            a1[1][3] = fma2(h67, ws1, a1[1][3]);
            a1[2][0] = fma2(h01, ws2, a1[2][0]);
            a1[2][1] = fma2(h23, ws2, a1[2][1]);
            a1[2][2] = fma2(h45, ws2, a1[2][2]);
            a1[2][3] = fma2(h67, ws2, a1[2][3]);
            a1[3][0] = fma2(h01, ws3, a1[3][0]);
            a1[3][1] = fma2(h23, ws3, a1[3][1]);
            a1[3][2] = fma2(h45, ws3, a1[3][2]);
            a1[3][3] = fma2(h67, ws3, a1[3][3]);
        }

        // bias + gelu + store sG[j][r]
        #pragma unroll
        for (int c = 0; c < 4; c++){
            int j = 4*lane + c;
            float bj = sB1[j];
            float g[8];
            #pragma unroll
            for (int i = 0; i < 4; i++){
                float2 f = upk(a1[c][i]);
                float u0 = f.x + bj, u1 = f.y + bj;
                g[2*i]   = 0.5f * u0 * (1.f + erff(u0 * 0.70710678118654752f));
                g[2*i+1] = 0.5f * u1 * (1.f + erff(u1 * 0.70710678118654752f));
            }
            double2 st0, st1;
            st0.x = __longlong_as_double(pk(g[0], g[1]));
            st0.y = __longlong_as_double(pk(g[2], g[3]));
            st1.x = __longlong_as_double(pk(g[4], g[5]));
            st1.y = __longlong_as_double(pk(g[6], g[7]));
            *(double2*)&sG[j*68 + 8*w]     = st0;
            *(double2*)&sG[j*68 + 8*w + 4] = st1;
        }
        __syncthreads();

        // ---- GEMM2: 64x64, k=128 ----
        ull a2[2][4];
        #pragma unroll
        for (int c = 0; c < 2; c++)
            #pragma unroll
            for (int i = 0; i < 4; i++) a2[c][i] = 0ull;

        #pragma unroll 4
        for (int k = 0; k < 128; k++){
            double2 gd0 = *(const double2*)&sG[k*68 + 8*w];
            double2 gd1 = *(const double2*)&sG[k*68 + 8*w + 4];
            ull g01 = __double_as_longlong(gd0.x);
            ull g23 = __double_as_longlong(gd0.y);
            ull g45 = __double_as_longlong(gd1.x);
            ull g67 = __double_as_longlong(gd1.y);
            ull wv2 = *(const ull*)&sW2[k*64 + 2*lane];
            float2 wf = upk(wv2);
            ull ws0 = pk(wf.x, wf.x), ws1 = pk(wf.y, wf.y);
            a2[0][0] = fma2(g01, ws0, a2[0][0]);
            a2[0][1] = fma2(g23, ws0, a2[0][1]);
            a2[0][2] = fma2(g45, ws0, a2[0][2]);
            a2[0][3] = fma2(g67, ws0, a2[0][3]);
            a2[1][0] = fma2(g01, ws1, a2[1][0]);
            a2[1][1] = fma2(g23, ws1, a2[1][1]);
            a2[1][2] = fma2(g45, ws1, a2[1][2]);
            a2[1][3] = fma2(g67, ws1, a2[1][3]);
        }

        // epilogue: out = x2 + acc + b2
        #pragma unroll
        for (int i = 0; i < 4; i++){
            float2 f0 = upk(a2[0][i]);
            float2 f1 = upk(a2[1][i]);
            size_t o = (size_t)(row0 + 8*w + 2*i)*64 + 2*lane;
            out[o]        = g_x2[o]        + f0.x + b2v0;
            out[o+1]      = g_x2[o+1]      + f1.x + b2v1;
            out[o+64]     = g_x2[o+64]     + f0.y + b2v0;
            out[o+65]     = g_x2[o+65]     + f1.y + b2v1;
        }
        __syncthreads();
    }
}

// ---------------- launcher ----------------
extern "C" void kernel_launch(void* const* d_in, const int* in_sizes, int n_in,
                              void* d_out, int out_size){
    const float* x    = (const float*)d_in[0];
    const int*   src1 = (const int*)d_in[1];
    const int*   dst1 = (const int*)d_in[2];
    const int*   src2 = (const int*)d_in[3];
    const int*   dst2 = (const int*)d_in[4];
    const float* W1   = (const float*)d_in[5];
    const float* al1  = (const float*)d_in[6];
    const float* ar1  = (const float*)d_in[7];
    const float* W2   = (const float*)d_in[8];
    const float* al2  = (const float*)d_in[9];
    const float* ar2  = (const float*)d_in[10];
    const float* bn1g = (const float*)d_in[11];
    const float* bn1b = (const float*)d_in[12];
    const float* bn2g = (const float*)d_in[13];
    const float* bn2b = (const float*)d_in[14];
    const float* fw1  = (const float*)d_in[15];
    const float* fb1  = (const float*)d_in[16];
    const float* fw2  = (const float*)d_in[17];
    const float* fb2  = (const float*)d_in[18];
    float* out = (float*)d_out;

    cudaFuncSetAttribute(ff_kernel, cudaFuncAttributeMaxDynamicSharedMemorySize, FF_SMEM);

    csr_clear<<<(2*(Nn+1) + 255)/256, 256>>>();
    csr_hist<<<(2*Ee + 255)/256, 256>>>(dst1, dst2);
    csr_scan<<<1, 1024>>>();
    csr_scatter<<<(2*Ee + 255)/256, 256>>>(src1, dst1, src2, dst2);

    zel_kernel<<<NTc/48, 256>>>(x, bn1g, bn1b, W1, al1, ar1, W2, al2, ar2);
    gat_kernel<<<Nn, 384>>>(x, bn2g, bn2b);
    ff_kernel<<<148, 256, FF_SMEM>>>(fw1, fb1, fw2, fb2, out);
}

// round 6
// speedup vs baseline: 2.4257x; 1.0636x over previous
#include <cuda_runtime.h>
#include <math.h>

#define Nn   10000
#define Tt   12
#define Ee   100000
#define NTc  (Nn*Tt)        // 120000
#define NTDc (NTc*64)       // 7680000
#define CAP  128
#define SCAT_BLKS 782       // ceil(2*Ee/256)

typedef unsigned long long ull;

// ---------------- scratch ----------------
__device__ float g_h[NTDc];          // BN2 output (input to FFN)
__device__ float g_z[2][NTDc];       // per-relation projected features
__device__ float g_x2[NTDc];         // residual x + m1 + m2
__device__ float g_el[2][NTc*4];
__device__ float g_er[2][NTc*4];
__device__ int   g_cnt[2*(Nn+1)];    // starts zero; scan re-zeros after reading
__device__ int   g_rowptr[2*(Nn+1)];
__device__ int   g_fill[2*Nn];
__device__ int   g_esrc[2][Ee];

// ---------------- f32x2 helpers ----------------
__device__ __forceinline__ ull pk(float a, float b){
    ull r;
    asm("mov.b64 %0, {%1, %2};" : "=l"(r) : "r"(__float_as_uint(a)), "r"(__float_as_uint(b)));
    return r;
}
__device__ __forceinline__ ull fma2(ull a, ull b, ull c){
    ull d;
    asm("fma.rn.f32x2 %0, %1, %2, %3;" : "=l"(d) : "l"(a), "l"(b), "l"(c));
    return d;
}
__device__ __forceinline__ ull mul2(ull a, ull b){
    ull d;
    asm("mul.rn.f32x2 %0, %1, %2;" : "=l"(d) : "l"(a), "l"(b));
    return d;
}
__device__ __forceinline__ ull add2(ull a, ull b){
    ull d;
    asm("add.rn.f32x2 %0, %1, %2;" : "=l"(d) : "l"(a), "l"(b));
    return d;
}
__device__ __forceinline__ float2 upk(ull v){
    unsigned lo, hi;
    asm("mov.b64 {%0, %1}, %2;" : "=r"(lo), "=r"(hi) : "l"(v));
    return make_float2(__uint_as_float(lo), __uint_as_float(hi));
}

// ---------------- CSR: histogram ----------------
__global__ void csr_hist(const int* __restrict__ dst1, const int* __restrict__ dst2){
    int e = blockIdx.x * 256 + threadIdx.x;
    if (e < Ee)            atomicAdd(&g_cnt[dst1[e] + 1], 1);
    else if (e < 2*Ee)     atomicAdd(&g_cnt[(Nn+1) + dst2[e-Ee] + 1], 1);
}

// ---------------- CSR: scan (self-zeros g_cnt for next replay) ----------------
__global__ void csr_scan(){
    __shared__ int wsum[32];
    int tid = threadIdx.x, lane = tid & 31, w = tid >> 5;
    for (int rel = 0; rel < 2; rel++){
        int* cnt = g_cnt    + rel*(Nn+1);
        int* rp  = g_rowptr + rel*(Nn+1);
        int* fl  = g_fill   + rel*Nn;
        int base = tid * 10;
        int v[10]; int s = 0;
        #pragma unroll
        for (int i = 0; i < 10; i++){
            int idx = base + i;
            int c = 0;
            if (idx <= Nn){ c = cnt[idx]; cnt[idx] = 0; }
            s += c; v[i] = s;
        }
        int t = s;
        #pragma unroll
        for (int o = 1; o < 32; o <<= 1){
            int u = __shfl_up_sync(0xffffffffu, t, o);
            if (lane >= o) t += u;
        }
        if (lane == 31) wsum[w] = t;
        __syncthreads();
        if (w == 0){
            int ws = wsum[lane];
            #pragma unroll
            for (int o = 1; o < 32; o <<= 1){
                int u = __shfl_up_sync(0xffffffffu, ws, o);
                if (lane >= o) ws += u;
            }
            wsum[lane] = ws;
        }
        __syncthreads();
        int off = ((w > 0) ? wsum[w-1] : 0) + (t - s);
        #pragma unroll
        for (int i = 0; i < 10; i++){
            int idx = base + i;
            if (idx <= Nn){
                int val = off + v[i];
                rp[idx] = val;
                if (idx < Nn) fl[idx] = val;
            }
        }
        __syncthreads();
    }
}

// ---------------- fused: CSR scatter (blocks 0..781) + BN1/z/el/er (rest) -----
__global__ void scatter_zel(const int* __restrict__ src1, const int* __restrict__ dst1,
                            const int* __restrict__ src2, const int* __restrict__ dst2,
                            const float* __restrict__ x,
                            const float* __restrict__ bg, const float* __restrict__ bb,
                            const float* __restrict__ W1, const float* __restrict__ al1, const float* __restrict__ ar1,
                            const float* __restrict__ W2, const float* __restrict__ al2, const float* __restrict__ ar2){
    if (blockIdx.x < SCAT_BLKS){
        int e = blockIdx.x * 256 + threadIdx.x;
        if (e < Ee){
            int p = atomicAdd(&g_fill[dst1[e]], 1);
            g_esrc[0][p] = src1[e];
        } else if (e < 2*Ee){
            int p = atomicAdd(&g_fill[Nn + dst2[e-Ee]], 1);
            g_esrc[1][p] = src2[e-Ee];
        }
        return;
    }

    // ---- zel role: block = 4 nodes = 48 rows ----
    __shared__ __align__(16) float sh[64*52];    // [k][row], stride 52
    __shared__ __align__(16) float sW[64*64];    // [k][c]
    __shared__ __align__(16) float zred[64*52];  // [c][row], stride 52
    __shared__ float red[8];
    __shared__ float nsc[4], nsh[4];

    int tid  = threadIdx.x;
    int lane = tid & 31;
    int w    = tid >> 5;
    int wcol = w & 3;
    int khalf= w >> 2;
    int rg   = lane >> 3;
    int cg   = lane & 7;
    int r0   = rg * 12;
    int c0   = wcol*16 + 2*cg;
    int bz   = blockIdx.x - SCAT_BLKS;
    int nt0  = bz * 48;
    int nd0  = bz * 4;

    if (tid < 8) red[tid] = 0.f;
    __syncthreads();

    float ls[4] = {0,0,0,0}, lq[4] = {0,0,0,0};
    #pragma unroll
    for (int it = 0; it < 12; it++){
        int i = tid + it*256;
        float v = x[(size_t)nt0*64 + i];
        int row = i >> 6, d = i & 63;
        sh[d*52 + row] = v;
        int nl = row / 12;
        ls[nl] += v; lq[nl] += v*v;
    }
    #pragma unroll
    for (int nl = 0; nl < 4; nl++){
        #pragma unroll
        for (int o = 16; o; o >>= 1){
            ls[nl] += __shfl_xor_sync(0xffffffffu, ls[nl], o);
            lq[nl] += __shfl_xor_sync(0xffffffffu, lq[nl], o);
        }
    }
    if (lane == 0){
        #pragma unroll
        for (int nl = 0; nl < 4; nl++){
            if (ls[nl] != 0.f || lq[nl] != 0.f){
                atomicAdd(&red[2*nl],   ls[nl]);
                atomicAdd(&red[2*nl+1], lq[nl]);
            }
        }
    }
    __syncthreads();
    if (tid < 4){
        float mean = red[2*tid] * (1.f/768.f);
        float var  = red[2*tid+1] * (1.f/768.f) - mean*mean;
        float sc   = rsqrtf(var + 1e-5f) * bg[nd0 + tid];
        nsc[tid] = sc;
        nsh[tid] = bb[nd0 + tid] - mean*sc;
    }
    __syncthreads();
    #pragma unroll
    for (int it = 0; it < 12; it++){
        int i = tid + it*256;
        int row = i >> 6, d = i & 63;
        int nl = row / 12;
        sh[d*52 + row] = sh[d*52 + row]*nsc[nl] + nsh[nl];
    }
    __syncthreads();

    for (int rel = 0; rel < 2; rel++){
        const float* W  = rel ? W2  : W1;
        const float* al = rel ? al2 : al1;
        const float* ar = rel ? ar2 : ar1;
        for (int i = tid; i < 4096; i += 256) sW[i] = W[i];
        __syncthreads();

        ull acc[2][6];
        #pragma unroll
        for (int c = 0; c < 2; c++)
            #pragma unroll
            for (int i = 0; i < 6; i++) acc[c][i] = 0ull;

        int kb = khalf * 32;
        #pragma unroll 4
        for (int kk = 0; kk < 32; kk++){
            int k = kb + kk;
            ull w2v = *(const ull*)&sW[k*64 + c0];
            float2 wf = upk(w2v);
            ull ws0 = pk(wf.x, wf.x);
            ull ws1 = pk(wf.y, wf.y);
            const float4* hb = (const float4*)&sh[k*52 + r0];
            float4 hA = hb[0], hB = hb[1], hC = hb[2];
            ull h2[6];
            h2[0] = pk(hA.x, hA.y); h2[1] = pk(hA.z, hA.w);
            h2[2] = pk(hB.x, hB.y); h2[3] = pk(hB.z, hB.w);
            h2[4] = pk(hC.x, hC.y); h2[5] = pk(hC.z, hC.w);
            #pragma unroll
            for (int i = 0; i < 6; i++){
                acc[0][i] = fma2(h2[i], ws0, acc[0][i]);
                acc[1][i] = fma2(h2[i], ws1, acc[1][i]);
            }
        }

        if (khalf == 1){
            #pragma unroll
            for (int c = 0; c < 2; c++)
                #pragma unroll
                for (int i = 0; i < 6; i++)
                    *(ull*)&zred[(c0+c)*52 + r0 + 2*i] = acc[c][i];
        }
        __syncthreads();
        if (khalf == 0){
            #pragma unroll
            for (int c = 0; c < 2; c++)
                #pragma unroll
                for (int i = 0; i < 6; i++)
                    acc[c][i] = add2(acc[c][i], *(const ull*)&zred[(c0+c)*52 + r0 + 2*i]);
            #pragma unroll
            for (int c = 0; c < 2; c++)
                #pragma unroll
                for (int i = 0; i < 6; i++)
                    *(ull*)&zred[(c0+c)*52 + r0 + 2*i] = acc[c][i];

            ull al0 = pk(al[c0], al[c0]),   al1v = pk(al[c0+1], al[c0+1]);
            ull ar0 = pk(ar[c0], ar[c0]),   ar1v = pk(ar[c0+1], ar[c0+1]);
            ull pl[6], pr[6];
            #pragma unroll
            for (int i = 0; i < 6; i++){
                pl[i] = fma2(acc[1][i], al1v, mul2(acc[0][i], al0));
                pr[i] = fma2(acc[1][i], ar1v, mul2(acc[0][i], ar0));
            }
            #pragma unroll
            for (int o = 1; o < 8; o <<= 1){
                #pragma unroll
                for (int i = 0; i < 6; i++){
                    pl[i] = add2(pl[i], __shfl_xor_sync(0xffffffffu, pl[i], o));
                    pr[i] = add2(pr[i], __shfl_xor_sync(0xffffffffu, pr[i], o));
                }
            }
            if (cg == 0){
                #pragma unroll
                for (int i = 0; i < 6; i++){
                    float2 fl = upk(pl[i]);
                    float2 fr = upk(pr[i]);
                    int nt = nt0 + r0 + 2*i;
                    g_el[rel][nt*4 + wcol]     = fl.x;
                    g_el[rel][(nt+1)*4 + wcol] = fl.y;
                    g_er[rel][nt*4 + wcol]     = fr.x;
                    g_er[rel][(nt+1)*4 + wcol] = fr.y;
                }
            }
        }
        __syncthreads();
        #pragma unroll
        for (int it = 0; it < 12; it++){
            int i = tid + it*256;
            int row = i >> 6, d = i & 63;
            g_z[rel][(size_t)nt0*64 + i] = zred[d*52 + row];
        }
        __syncthreads();
    }
}

// ---------------- fused GAT (both rels) + residual + BN2 ----------------
__global__ void gat_kernel(const float* __restrict__ x,
                           const float* __restrict__ bg, const float* __restrict__ bb){
    __shared__ int   s_src[2][CAP];
    __shared__ float s_w[12][CAP*4];
    __shared__ float sms[12], sqs[12];

    const unsigned FULL = 0xffffffffu;
    int d    = blockIdx.x;
    int tid  = threadIdx.x;
    int t    = tid >> 5;
    int lane = tid & 31;
    int hA   = lane >> 3;

    int beg[2], deg[2];
    #pragma unroll
    for (int rel = 0; rel < 2; rel++){
        beg[rel] = g_rowptr[rel*(Nn+1) + d];
        deg[rel] = g_rowptr[rel*(Nn+1) + d + 1] - beg[rel];
        for (int i = tid; i < min(deg[rel], CAP); i += 384)
            s_src[rel][i] = g_esrc[rel][beg[rel] + i];
    }
    __syncthreads();

    ull m2 = 0ull;

    #pragma unroll
    for (int rel = 0; rel < 2; rel++){
        int dg = deg[rel], bg_e = beg[rel];
        const float* el = g_el[rel];
        const float* zb = g_z[rel];
        float4 er4 = *(const float4*)&g_er[rel][d*48 + t*4];

        float mx0 = -1e30f, mx1 = -1e30f, mx2 = -1e30f, mx3 = -1e30f;
        for (int e = lane; e < dg; e += 32){
            int s = (e < CAP) ? s_src[rel][e] : g_esrc[rel][bg_e + e];
            float4 e4 = *(const float4*)&el[s*48 + t*4];
            float a0 = e4.x + er4.x, a1 = e4.y + er4.y;
            float a2 = e4.z + er4.z, a3 = e4.w + er4.w;
            a0 = (a0 > 0.f) ? a0 : 0.2f*a0;
            a1 = (a1 > 0.f) ? a1 : 0.2f*a1;
            a2 = (a2 > 0.f) ? a2 : 0.2f*a2;
            a3 = (a3 > 0.f) ? a3 : 0.2f*a3;
            if (e < CAP)
                *(float4*)&s_w[t][e*4] = make_float4(a0, a1, a2, a3);
            mx0 = fmaxf(mx0, a0); mx1 = fmaxf(mx1, a1);
            mx2 = fmaxf(mx2, a2); mx3 = fmaxf(mx3, a3);
        }
        #pragma unroll
        for (int o = 16; o; o >>= 1){
            mx0 = fmaxf(mx0, __shfl_xor_sync(FULL, mx0, o));
            mx1 = fmaxf(mx1, __shfl_xor_sync(FULL, mx1, o));
            mx2 = fmaxf(mx2, __shfl_xor_sync(FULL, mx2, o));
            mx3 = fmaxf(mx3, __shfl_xor_sync(FULL, mx3, o));
        }
        float dn0 = 0.f, dn1 = 0.f, dn2 = 0.f, dn3 = 0.f;
        for (int e = lane; e < dg; e += 32){
            float a0, a1, a2, a3;
            if (e < CAP){
                float4 a4 = *(const float4*)&s_w[t][e*4];
                a0 = a4.x; a1 = a4.y; a2 = a4.z; a3 = a4.w;
            } else {
                int s = g_esrc[rel][bg_e + e];
                float4 e4 = *(const float4*)&el[s*48 + t*4];
                a0 = e4.x + er4.x; a1 = e4.y + er4.y;
                a2 = e4.z + er4.z; a3 = e4.w + er4.w;
                a0 = (a0 > 0.f) ? a0 : 0.2f*a0;
                a1 = (a1 > 0.f) ? a1 : 0.2f*a1;
                a2 = (a2 > 0.f) ? a2 : 0.2f*a2;
                a3 = (a3 > 0.f) ? a3 : 0.2f*a3;
            }
            float w0 = __expf(a0 - mx0), w1 = __expf(a1 - mx1);
            float w2 = __expf(a2 - mx2), w3 = __expf(a3 - mx3);
            dn0 += w0; dn1 += w1; dn2 += w2; dn3 += w3;
            if (e < CAP)
                *(float4*)&s_w[t][e*4] = make_float4(w0, w1, w2, w3);
        }
        #pragma unroll
        for (int o = 16; o; o >>= 1){
            dn0 += __shfl_xor_sync(FULL, dn0, o);
            dn1 += __shfl_xor_sync(FULL, dn1, o);
            dn2 += __shfl_xor_sync(FULL, dn2, o);
            dn3 += __shfl_xor_sync(FULL, dn3, o);
        }
        float dnA = (hA < 2) ? ((hA == 0) ? dn0 : dn1) : ((hA == 2) ? dn2 : dn3);
        float mxA = (hA < 2) ? ((hA == 0) ? mx0 : mx1) : ((hA == 2) ? mx2 : mx3);
        float erA = (hA < 2) ? ((hA == 0) ? er4.x : er4.y) : ((hA == 2) ? er4.z : er4.w);
        float inv = 1.f / fmaxf(dnA, 1e-16f);

        __syncwarp();

        ull ac = 0ull;
        int ecached = min(dg, CAP);
        #pragma unroll 4
        for (int e = 0; e < ecached; ++e){
            int s = s_src[rel][e];
            float wv = s_w[t][e*4 + hA];
            ull z2 = *(const ull*)(zb + (size_t)s*768 + t*64 + 2*lane);
            ac = fma2(pk(wv, wv), z2, ac);
        }
        for (int e = ecached; e < dg; ++e){
            int s = g_esrc[rel][bg_e + e];
            float a = el[s*48 + t*4 + hA] + erA;
            a = (a > 0.f) ? a : 0.2f*a;
            float wv = __expf(a - mxA);
            ull z2 = *(const ull*)(zb + (size_t)s*768 + t*64 + 2*lane);
            ac = fma2(pk(wv, wv), z2, ac);
        }
        m2 = add2(m2, mul2(ac, pk(inv, inv)));
        __syncthreads();
    }

    size_t idx = (size_t)d*768 + t*64 + 2*lane;
    float2 xm = upk(*(const ull*)&x[idx]);
    float2 mm = upk(m2);
    float v0 = xm.x + mm.x;
    float v1 = xm.y + mm.y;

    float s = v0 + v1;
    float q = v0*v0 + v1*v1;
    #pragma unroll
    for (int o = 16; o; o >>= 1){
        s += __shfl_xor_sync(FULL, s, o);
        q += __shfl_xor_sync(FULL, q, o);
    }
    if (lane == 0){ sms[t] = s; sqs[t] = q; }
    __syncthreads();
    float ts = 0.f, tq = 0.f;
    #pragma unroll
    for (int i = 0; i < 12; i++){ ts += sms[i]; tq += sqs[i]; }
    float mean = ts * (1.f/768.f);
    float var  = tq * (1.f/768.f) - mean*mean;
    float sc   = rsqrtf(var + 1e-5f) * bg[d];
    float sb   = bb[d] - mean*sc;

    *(ull*)&g_x2[idx] = pk(v0, v1);
    *(ull*)&g_h[idx]  = pk(v0*sc + sb, v1*sc + sb);
}

// ---------------- FFN (register-tiled, 512 thr, 128-row tiles) ----------------
#define FF_TILES ((NTc + 127) / 128)   // 938 (last tile has 64 rows)
#define FF_SMEM ((8192 + 8192 + 128 + 64 + 64*132 + 128*132) * 4)
__global__ void ff_kernel(const float* __restrict__ w1, const float* __restrict__ b1,
                          const float* __restrict__ w2, const float* __restrict__ b2,
                          float* __restrict__ out){
    extern __shared__ float sm[];
    float* sW1 = sm;                   // [k][j] 64*128
    float* sW2 = sW1 + 8192;           // [j][c] 128*64
    float* sB1 = sW2 + 8192;           // 128
    float* sB2 = sB1 + 128;            // 64
    float* sX  = sB2 + 64;             // [k][r] 64*132
    float* sG  = sX  + 64*132;         // [j][r] 128*132

    int tid  = threadIdx.x;
    int w    = tid >> 5;
    int lane = tid & 31;

    for (int i = tid; i < 8192; i += 512) sW1[i] = w1[i];
    for (int i = tid; i < 8192; i += 512) sW2[i] = w2[i];
    if (tid < 128) sB1[tid] = b1[tid];
    else if (tid < 192) sB2[tid-128] = b2[tid-128];
    __syncthreads();

    float b2v0 = sB2[2*lane], b2v1 = sB2[2*lane+1];

    for (int tile = blockIdx.x; tile < FF_TILES; tile += 148){
        size_t base = (size_t)tile * 128 * 64;

        #pragma unroll
        for (int it = 0; it < 16; it++){
            int i = tid + it*512;
            size_t gi = base + i;
            if (gi < (size_t)NTDc){
                int r = i >> 6, k = i & 63;
                sX[k*132 + r] = g_h[gi];
            }
        }
        __syncthreads();

        // ---- GEMM1: 128x128, k=64 ----
        ull a1[4][4];
        #pragma unroll
        for (int c = 0; c < 4; c++)
            #pragma unroll
            for (int i = 0; i < 4; i++) a1[c][i] = 0ull;

        #pragma unroll 4
        for (int k = 0; k < 64; k++){
            double2 hd0 = *(const double2*)&sX[k*132 + 8*w];
            double2 hd1 = *(const double2*)&sX[k*132 + 8*w + 4];
            ull h01 = __double_as_longlong(hd0.x);
            ull h23 = __double_as_longlong(hd0.y);
            ull h45 = __double_as_longlong(hd1.x);
            ull h67 = __double_as_longlong(hd1.y);
            float4 wv = *(const float4*)&sW1[k*128 + 4*lane];
            ull ws0 = pk(wv.x, wv.x), ws1 = pk(wv.y, wv.y);
            ull ws2 = pk(wv.z, wv.z), ws3 = pk(wv.w, wv.w);
            a1[0][0] = fma2(h01, ws0, a1[0][0]);
            a1[0][1] = fma2(h23, ws0, a1[0][1]);
            a1[0][2] = fma2(h45, ws0, a1[0][2]);
            a1[0][3] = fma2(h67, ws0, a1[0][3]);
            a1[1][0] = fma2(h01, ws1, a1[1][0]);
            a1[1][1] = fma2(h23, ws1, a1[1][1]);
            a1[1][2] = fma2(h45, ws1, a1[1][2]);
            a1[1][3] = fma2(h67, ws1, a1[1][3]);
            a1[2][0] = fma2(h01, ws2, a1[2][0]);
            a1[2][1] = fma2(h23, ws2, a1[2][1]);
            a1[2][2] = fma2(h45, ws2, a1[2][2]);
            a1[2][3] = fma2(h67, ws2, a1[2][3]);
            a1[3][0] = fma2(h01, ws3, a1[3][0]);
            a1[3][1] = fma2(h23, ws3, a1[3][1]);
            a1[3][2] = fma2(h45, ws3, a1[3][2]);
            a1[3][3] = fma2(h67, ws3, a1[3][3]);
        }

        #pragma unroll
        for (int c = 0; c < 4; c++){
            int j = 4*lane + c;
            float bj = sB1[j];
            float g[8];
            #pragma unroll
            for (int i = 0; i < 4; i++){
                float2 f = upk(a1[c][i]);
                float u0 = f.x + bj, u1 = f.y + bj;
                g[2*i]   = 0.5f * u0 * (1.f + erff(u0 * 0.70710678118654752f));
                g[2*i+1] = 0.5f * u1 * (1.f + erff(u1 * 0.70710678118654752f));
            }
            double2 st0, st1;
            st0.x = __longlong_as_double(pk(g[0], g[1]));
            st0.y = __longlong_as_double(pk(g[2], g[3]));
            st1.x = __longlong_as_double(pk(g[4], g[5]));
            st1.y = __longlong_as_double(pk(g[6], g[7]));
            *(double2*)&sG[j*132 + 8*w]     = st0;
            *(double2*)&sG[j*132 + 8*w + 4] = st1;
        }
        __syncthreads();

        // ---- GEMM2: 128x64, k=128 ----
        ull a2[2][4];
        #pragma unroll
        for (int c = 0; c < 2; c++)
            #pragma unroll
            for (int i = 0; i < 4; i++) a2[c][i] = 0ull;

        #pragma unroll 4
        for (int k = 0; k < 128; k++){
            double2 gd0 = *(const double2*)&sG[k*132 + 8*w];
            double2 gd1 = *(const double2*)&sG[k*132 + 8*w + 4];
            ull g01 = __double_as_longlong(gd0.x);
            ull g23 = __double_as_longlong(gd0.y);
            ull g45 = __double_as_longlong(gd1.x);
            ull g67 = __double_as_longlong(gd1.y);
            ull wv2 = *(const ull*)&sW2[k*64 + 2*lane];
            float2 wf = upk(wv2);
            ull ws0 = pk(wf.x, wf.x), ws1 = pk(wf.y, wf.y);
            a2[0][0] = fma2(g01, ws0, a2[0][0]);
            a2[0][1] = fma2(g23, ws0, a2[0][1]);
            a2[0][2] = fma2(g45, ws0, a2[0][2]);
            a2[0][3] = fma2(g67, ws0, a2[0][3]);
            a2[1][0] = fma2(g01, ws1, a2[1][0]);
            a2[1][1] = fma2(g23, ws1, a2[1][1]);
            a2[1][2] = fma2(g45, ws1, a2[1][2]);
            a2[1][3] = fma2(g67, ws1, a2[1][3]);
        }

        #pragma unroll
        for (int i = 0; i < 4; i++){
            float2 f0 = upk(a2[0][i]);
            float2 f1 = upk(a2[1][i]);
            size_t o = base + (size_t)(8*w + 2*i)*64 + 2*lane;
            if (o < (size_t)NTDc){
                out[o]    = g_x2[o]    + f0.x + b2v0;
                out[o+1]  = g_x2[o+1]  + f1.x + b2v1;
                out[o+64] = g_x2[o+64] + f0.y + b2v0;
                out[o+65] = g_x2[o+65] + f1.y + b2v1;
            }
        }
        __syncthreads();
    }
}

// ---------------- launcher ----------------
extern "C" void kernel_launch(void* const* d_in, const int* in_sizes, int n_in,
                              void* d_out, int out_size){
    const float* x    = (const float*)d_in[0];
    const int*   src1 = (const int*)d_in[1];
    const int*   dst1 = (const int*)d_in[2];
    const int*   src2 = (const int*)d_in[3];
    const int*   dst2 = (const int*)d_in[4];
    const float* W1   = (const float*)d_in[5];
    const float* al1  = (const float*)d_in[6];
    const float* ar1  = (const float*)d_in[7];
    const float* W2   = (const float*)d_in[8];
    const float* al2  = (const float*)d_in[9];
    const float* ar2  = (const float*)d_in[10];
    const float* bn1g = (const float*)d_in[11];
    const float* bn1b = (const float*)d_in[12];
    const float* bn2g = (const float*)d_in[13];
    const float* bn2b = (const float*)d_in[14];
    const float* fw1  = (const float*)d_in[15];
    const float* fb1  = (const float*)d_in[16];
    const float* fw2  = (const float*)d_in[17];
    const float* fb2  = (const float*)d_in[18];
    float* out = (float*)d_out;

    cudaFuncSetAttribute(ff_kernel, cudaFuncAttributeMaxDynamicSharedMemorySize, FF_SMEM);

    csr_hist<<<(2*Ee + 255)/256, 256>>>(dst1, dst2);               // idx 0
    csr_scan<<<1, 1024>>>();                                        // idx 1
    scatter_zel<<<SCAT_BLKS + NTc/48, 256>>>(src1, dst1, src2, dst2,
        x, bn1g, bn1b, W1, al1, ar1, W2, al2, ar2);                 // idx 2
    gat_kernel<<<Nn, 384>>>(x, bn2g, bn2b);                         // idx 3 (profiled)
    ff_kernel<<<148, 512, FF_SMEM>>>(fw1, fb1, fw2, fb2, out);      // idx 4
}

// round 8
// speedup vs baseline: 2.4778x; 1.0215x over previous
#include <cuda_runtime.h>
#include <math.h>

#define Nn   10000
#define Tt   12
#define Ee   100000
#define NTc  (Nn*Tt)        // 120000
#define NTDc (NTc*64)       // 7680000
#define CAP  128
#define SCAT_BLKS 782       // ceil(2*Ee/256)

typedef unsigned long long ull;

// ---------------- scratch ----------------
__device__ float g_h[NTDc];          // BN2 output (input to FFN)
__device__ float g_z[2][NTDc];       // per-relation projected features
__device__ float g_x2[NTDc];         // residual x + m1 + m2
__device__ float g_el[2][NTc*4];
__device__ float g_er[2][NTc*4];
__device__ int   g_cnt[2*(Nn+1)];    // starts zero; scan re-zeros after reading
__device__ int   g_rowptr[2*(Nn+1)];
__device__ int   g_fill[2*Nn];
__device__ int   g_esrc[2][Ee];

// ---------------- f32x2 helpers ----------------
__device__ __forceinline__ ull pk(float a, float b){
    ull r;
    asm("mov.b64 %0, {%1, %2};" : "=l"(r) : "r"(__float_as_uint(a)), "r"(__float_as_uint(b)));
    return r;
}
__device__ __forceinline__ ull fma2(ull a, ull b, ull c){
    ull d;
    asm("fma.rn.f32x2 %0, %1, %2, %3;" : "=l"(d) : "l"(a), "l"(b), "l"(c));
    return d;
}
__device__ __forceinline__ ull mul2(ull a, ull b){
    ull d;
    asm("mul.rn.f32x2 %0, %1, %2;" : "=l"(d) : "l"(a), "l"(b));
    return d;
}
__device__ __forceinline__ ull add2(ull a, ull b){
    ull d;
    asm("add.rn.f32x2 %0, %1, %2;" : "=l"(d) : "l"(a), "l"(b));
    return d;
}
__device__ __forceinline__ float2 upk(ull v){
    unsigned lo, hi;
    asm("mov.b64 {%0, %1}, %2;" : "=r"(lo), "=r"(hi) : "l"(v));
    return make_float2(__uint_as_float(lo), __uint_as_float(hi));
}
// warp-wide reductions via shfl butterfly (no fp32 redux on sm_103)
__device__ __forceinline__ float rmax32(float v){
    #pragma unroll
    for (int o = 16; o; o >>= 1)
        v = fmaxf(v, __shfl_xor_sync(0xffffffffu, v, o));
    return v;
}
__device__ __forceinline__ float radd32(float v){
    #pragma unroll
    for (int o = 16; o; o >>= 1)
        v += __shfl_xor_sync(0xffffffffu, v, o);
    return v;
}

// ---------------- CSR: histogram ----------------
__global__ void csr_hist(const int* __restrict__ dst1, const int* __restrict__ dst2){
    int e = blockIdx.x * 256 + threadIdx.x;
    if (e < Ee)            atomicAdd(&g_cnt[dst1[e] + 1], 1);
    else if (e < 2*Ee)     atomicAdd(&g_cnt[(Nn+1) + dst2[e-Ee] + 1], 1);
}

// ---------------- CSR: scan (self-zeros g_cnt for next replay) ----------------
__global__ void csr_scan(){
    __shared__ int wsum[32];
    int tid = threadIdx.x, lane = tid & 31, w = tid >> 5;
    for (int rel = 0; rel < 2; rel++){
        int* cnt = g_cnt    + rel*(Nn+1);
        int* rp  = g_rowptr + rel*(Nn+1);
        int* fl  = g_fill   + rel*Nn;
        int base = tid * 10;
        int v[10]; int s = 0;
        #pragma unroll
        for (int i = 0; i < 10; i++){
            int idx = base + i;
            int c = 0;
            if (idx <= Nn){ c = cnt[idx]; cnt[idx] = 0; }
            s += c; v[i] = s;
        }
        int t = s;
        #pragma unroll
        for (int o = 1; o < 32; o <<= 1){
            int u = __shfl_up_sync(0xffffffffu, t, o);
            if (lane >= o) t += u;
        }
        if (lane == 31) wsum[w] = t;
        __syncthreads();
        if (w == 0){
            int ws = wsum[lane];
            #pragma unroll
            for (int o = 1; o < 32; o <<= 1){
                int u = __shfl_up_sync(0xffffffffu, ws, o);
                if (lane >= o) ws += u;
            }
            wsum[lane] = ws;
        }
        __syncthreads();
        int off = ((w > 0) ? wsum[w-1] : 0) + (t - s);
        #pragma unroll
        for (int i = 0; i < 10; i++){
            int idx = base + i;
            if (idx <= Nn){
                int val = off + v[i];
                rp[idx] = val;
                if (idx < Nn) fl[idx] = val;
            }
        }
        __syncthreads();
    }
}

// ---------------- fused: CSR scatter (blocks 0..781) + BN1/z/el/er (rest) -----
__global__ void scatter_zel(const int* __restrict__ src1, const int* __restrict__ dst1,
                            const int* __restrict__ src2, const int* __restrict__ dst2,
                            const float* __restrict__ x,
                            const float* __restrict__ bg, const float* __restrict__ bb,
                            const float* __restrict__ W1, const float* __restrict__ al1, const float* __restrict__ ar1,
                            const float* __restrict__ W2, const float* __restrict__ al2, const float* __restrict__ ar2){
    if (blockIdx.x < SCAT_BLKS){
        int e = blockIdx.x * 256 + threadIdx.x;
        if (e < Ee){
            int p = atomicAdd(&g_fill[dst1[e]], 1);
            g_esrc[0][p] = src1[e];
        } else if (e < 2*Ee){
            int p = atomicAdd(&g_fill[Nn + dst2[e-Ee]], 1);
            g_esrc[1][p] = src2[e-Ee];
        }
        return;
    }

    __shared__ __align__(16) float sh[64*52];
    __shared__ __align__(16) float sW[64*64];
    __shared__ __align__(16) float zred[64*52];
    __shared__ float red[8];
    __shared__ float nsc[4], nsh[4];

    int tid  = threadIdx.x;
    int lane = tid & 31;
    int w    = tid >> 5;
    int wcol = w & 3;
    int khalf= w >> 2;
    int rg   = lane >> 3;
    int cg   = lane & 7;
    int r0   = rg * 12;
    int c0   = wcol*16 + 2*cg;
    int bz   = blockIdx.x - SCAT_BLKS;
    int nt0  = bz * 48;
    int nd0  = bz * 4;

    if (tid < 8) red[tid] = 0.f;
    __syncthreads();

    float ls[4] = {0,0,0,0}, lq[4] = {0,0,0,0};
    #pragma unroll
    for (int it = 0; it < 12; it++){
        int i = tid + it*256;
        float v = x[(size_t)nt0*64 + i];
        int row = i >> 6, d = i & 63;
        sh[d*52 + row] = v;
        int nl = row / 12;
        ls[nl] += v; lq[nl] += v*v;
    }
    #pragma unroll
    for (int nl = 0; nl < 4; nl++){
        ls[nl] = radd32(ls[nl]);
        lq[nl] = radd32(lq[nl]);
    }
    if (lane == 0){
        #pragma unroll
        for (int nl = 0; nl < 4; nl++){
            if (ls[nl] != 0.f || lq[nl] != 0.f){
                atomicAdd(&red[2*nl],   ls[nl]);
                atomicAdd(&red[2*nl+1], lq[nl]);
            }
        }
    }
    __syncthreads();
    if (tid < 4){
        float mean = red[2*tid] * (1.f/768.f);
        float var  = red[2*tid+1] * (1.f/768.f) - mean*mean;
        float sc   = rsqrtf(var + 1e-5f) * bg[nd0 + tid];
        nsc[tid] = sc;
        nsh[tid] = bb[nd0 + tid] - mean*sc;
    }
    __syncthreads();
    #pragma unroll
    for (int it = 0; it < 12; it++){
        int i = tid + it*256;
        int row = i >> 6, d = i & 63;
        int nl = row / 12;
        sh[d*52 + row] = sh[d*52 + row]*nsc[nl] + nsh[nl];
    }
    __syncthreads();

    for (int rel = 0; rel < 2; rel++){
        const float* W  = rel ? W2  : W1;
        const float* al = rel ? al2 : al1;
        const float* ar = rel ? ar2 : ar1;
        for (int i = tid; i < 4096; i += 256) sW[i] = W[i];
        __syncthreads();

        ull acc[2][6];
        #pragma unroll
        for (int c = 0; c < 2; c++)
            #pragma unroll
            for (int i = 0; i < 6; i++) acc[c][i] = 0ull;

        int kb = khalf * 32;
        #pragma unroll 4
        for (int kk = 0; kk < 32; kk++){
            int k = kb + kk;
            ull w2v = *(const ull*)&sW[k*64 + c0];
            float2 wf = upk(w2v);
            ull ws0 = pk(wf.x, wf.x);
            ull ws1 = pk(wf.y, wf.y);
            const float4* hb = (const float4*)&sh[k*52 + r0];
            float4 hA = hb[0], hB = hb[1], hC = hb[2];
            ull h2[6];
            h2[0] = pk(hA.x, hA.y); h2[1] = pk(hA.z, hA.w);
            h2[2] = pk(hB.x, hB.y); h2[3] = pk(hB.z, hB.w);
            h2[4] = pk(hC.x, hC.y); h2[5] = pk(hC.z, hC.w);
            #pragma unroll
            for (int i = 0; i < 6; i++){
                acc[0][i] = fma2(h2[i], ws0, acc[0][i]);
                acc[1][i] = fma2(h2[i], ws1, acc[1][i]);
            }
        }

        if (khalf == 1){
            #pragma unroll
            for (int c = 0; c < 2; c++)
                #pragma unroll
                for (int i = 0; i < 6; i++)
                    *(ull*)&zred[(c0+c)*52 + r0 + 2*i] = acc[c][i];
        }
        __syncthreads();
        if (khalf == 0){
            #pragma unroll
            for (int c = 0; c < 2; c++)
                #pragma unroll
                for (int i = 0; i < 6; i++)
                    acc[c][i] = add2(acc[c][i], *(const ull*)&zred[(c0+c)*52 + r0 + 2*i]);
            #pragma unroll
            for (int c = 0; c < 2; c++)
                #pragma unroll
                for (int i = 0; i < 6; i++)
                    *(ull*)&zred[(c0+c)*52 + r0 + 2*i] = acc[c][i];

            ull al0 = pk(al[c0], al[c0]),   al1v = pk(al[c0+1], al[c0+1]);
            ull ar0 = pk(ar[c0], ar[c0]),   ar1v = pk(ar[c0+1], ar[c0+1]);
            ull pl[6], pr[6];
            #pragma unroll
            for (int i = 0; i < 6; i++){
                pl[i] = fma2(acc[1][i], al1v, mul2(acc[0][i], al0));
                pr[i] = fma2(acc[1][i], ar1v, mul2(acc[0][i], ar0));
            }
            #pragma unroll
            for (int o = 1; o < 8; o <<= 1){
                #pragma unroll
                for (int i = 0; i < 6; i++){
                    pl[i] = add2(pl[i], __shfl_xor_sync(0xffffffffu, pl[i], o));
                    pr[i] = add2(pr[i], __shfl_xor_sync(0xffffffffu, pr[i], o));
                }
            }
            if (cg == 0){
                #pragma unroll
                for (int i = 0; i < 6; i++){
                    float2 fl = upk(pl[i]);
                    float2 fr = upk(pr[i]);
                    int nt = nt0 + r0 + 2*i;
                    g_el[rel][nt*4 + wcol]     = fl.x;
                    g_el[rel][(nt+1)*4 + wcol] = fl.y;
                    g_er[rel][nt*4 + wcol]     = fr.x;
                    g_er[rel][(nt+1)*4 + wcol] = fr.y;
                }
            }
        }
        __syncthreads();
        #pragma unroll
        for (int it = 0; it < 12; it++){
            int i = tid + it*256;
            int row = i >> 6, d = i & 63;
            g_z[rel][(size_t)nt0*64 + i] = zred[d*52 + row];
        }
        __syncthreads();
    }
}

// ---------------- fused GAT (both rels) + residual + BN2 ----------------
// block = node d, 12 warps (one per t); single-pass softmax for deg<=32
__global__ void gat_kernel(const float* __restrict__ x,
                           const float* __restrict__ bg, const float* __restrict__ bb){
    __shared__ int   s_src[2][CAP];
    __shared__ float s_w[12][CAP*4];
    __shared__ float sms[12], sqs[12];

    int d    = blockIdx.x;
    int tid  = threadIdx.x;
    int t    = tid >> 5;
    int lane = tid & 31;
    int hA   = lane >> 3;

    int beg[2], deg[2];
    #pragma unroll
    for (int rel = 0; rel < 2; rel++){
        beg[rel] = g_rowptr[rel*(Nn+1) + d];
        deg[rel] = g_rowptr[rel*(Nn+1) + d + 1] - beg[rel];
        for (int i = tid; i < min(deg[rel], CAP); i += 384)
            s_src[rel][i] = g_esrc[rel][beg[rel] + i];
    }
    __syncthreads();

    ull m2 = 0ull;

    #pragma unroll
    for (int rel = 0; rel < 2; rel++){
        int dg = deg[rel], bg_e = beg[rel];
        const float* el = g_el[rel];
        const float* zb = g_z[rel];
        float4 er4 = *(const float4*)&g_er[rel][d*48 + t*4];

        float mx0, mx1, mx2, mx3, dn0, dn1, dn2, dn3;

        if (dg <= 32){
            // single pass: a-values stay in registers; el read once, exp once
            float a0 = -1e30f, a1 = -1e30f, a2 = -1e30f, a3 = -1e30f;
            if (lane < dg){
                int s = s_src[rel][lane];
                float4 e4 = *(const float4*)&el[s*48 + t*4];
                a0 = e4.x + er4.x; a1 = e4.y + er4.y;
                a2 = e4.z + er4.z; a3 = e4.w + er4.w;
                a0 = (a0 > 0.f) ? a0 : 0.2f*a0;
                a1 = (a1 > 0.f) ? a1 : 0.2f*a1;
                a2 = (a2 > 0.f) ? a2 : 0.2f*a2;
                a3 = (a3 > 0.f) ? a3 : 0.2f*a3;
            }
            mx0 = rmax32(a0); mx1 = rmax32(a1);
            mx2 = rmax32(a2); mx3 = rmax32(a3);
            float w0 = 0.f, w1 = 0.f, w2 = 0.f, w3 = 0.f;
            if (lane < dg){
                w0 = __expf(a0 - mx0); w1 = __expf(a1 - mx1);
                w2 = __expf(a2 - mx2); w3 = __expf(a3 - mx3);
                *(float4*)&s_w[t][lane*4] = make_float4(w0, w1, w2, w3);
            }
            dn0 = radd32(w0); dn1 = radd32(w1);
            dn2 = radd32(w2); dn3 = radd32(w3);
        } else {
            // general two-pass fallback (rare)
            mx0 = -1e30f; mx1 = -1e30f; mx2 = -1e30f; mx3 = -1e30f;
            for (int e = lane; e < dg; e += 32){
                int s = (e < CAP) ? s_src[rel][e] : g_esrc[rel][bg_e + e];
                float4 e4 = *(const float4*)&el[s*48 + t*4];
                float a0 = e4.x + er4.x, a1 = e4.y + er4.y;
                float a2 = e4.z + er4.z, a3 = e4.w + er4.w;
                a0 = (a0 > 0.f) ? a0 : 0.2f*a0;
                a1 = (a1 > 0.f) ? a1 : 0.2f*a1;
                a2 = (a2 > 0.f) ? a2 : 0.2f*a2;
                a3 = (a3 > 0.f) ? a3 : 0.2f*a3;
                if (e < CAP)
                    *(float4*)&s_w[t][e*4] = make_float4(a0, a1, a2, a3);
                mx0 = fmaxf(mx0, a0); mx1 = fmaxf(mx1, a1);
                mx2 = fmaxf(mx2, a2); mx3 = fmaxf(mx3, a3);
            }
            mx0 = rmax32(mx0); mx1 = rmax32(mx1);
            mx2 = rmax32(mx2); mx3 = rmax32(mx3);
            dn0 = 0.f; dn1 = 0.f; dn2 = 0.f; dn3 = 0.f;
            for (int e = lane; e < dg; e += 32){
                float a0, a1, a2, a3;
                if (e < CAP){
                    float4 a4 = *(const float4*)&s_w[t][e*4];
                    a0 = a4.x; a1 = a4.y; a2 = a4.z; a3 = a4.w;
                } else {
                    int s = g_esrc[rel][bg_e + e];
                    float4 e4 = *(const float4*)&el[s*48 + t*4];
                    a0 = e4.x + er4.x; a1 = e4.y + er4.y;
                    a2 = e4.z + er4.z; a3 = e4.w + er4.w;
                    a0 = (a0 > 0.f) ? a0 : 0.2f*a0;
                    a1 = (a1 > 0.f) ? a1 : 0.2f*a1;
                    a2 = (a2 > 0.f) ? a2 : 0.2f*a2;
                    a3 = (a3 > 0.f) ? a3 : 0.2f*a3;
                }
                float w0 = __expf(a0 - mx0), w1 = __expf(a1 - mx1);
                float w2 = __expf(a2 - mx2), w3 = __expf(a3 - mx3);
                dn0 += w0; dn1 += w1; dn2 += w2; dn3 += w3;
                if (e < CAP)
                    *(float4*)&s_w[t][e*4] = make_float4(w0, w1, w2, w3);
            }
            dn0 = radd32(dn0); dn1 = radd32(dn1);
            dn2 = radd32(dn2); dn3 = radd32(dn3);
        }

        float dnA = (hA < 2) ? ((hA == 0) ? dn0 : dn1) : ((hA == 2) ? dn2 : dn3);
        float mxA = (hA < 2) ? ((hA == 0) ? mx0 : mx1) : ((hA == 2) ? mx2 : mx3);
        float erA = (hA < 2) ? ((hA == 0) ? er4.x : er4.y) : ((hA == 2) ? er4.z : er4.w);
        float inv = 1.f / fmaxf(dnA, 1e-16f);

        __syncwarp();

        ull ac = 0ull;
        int ecached = min(dg, CAP);
        const float* zt = zb + t*64 + 2*lane;
        #pragma unroll 4
        for (int e = 0; e < ecached; ++e){
            int s = s_src[rel][e];
            float wv = s_w[t][e*4 + hA];
            ull z2 = *(const ull*)(zt + (size_t)s*768);
            ac = fma2(pk(wv, wv), z2, ac);
        }
        for (int e = ecached; e < dg; ++e){
            int s = g_esrc[rel][bg_e + e];
            float a = el[s*48 + t*4 + hA] + erA;
            a = (a > 0.f) ? a : 0.2f*a;
            float wv = __expf(a - mxA);
            ull z2 = *(const ull*)(zt + (size_t)s*768);
            ac = fma2(pk(wv, wv), z2, ac);
        }
        m2 = add2(m2, mul2(ac, pk(inv, inv)));
        __syncthreads();
    }

    size_t idx = (size_t)d*768 + t*64 + 2*lane;
    float2 xm = upk(*(const ull*)&x[idx]);
    float2 mm = upk(m2);
    float v0 = xm.x + mm.x;
    float v1 = xm.y + mm.y;

    float s = radd32(v0 + v1);
    float q = radd32(v0*v0 + v1*v1);
    if (lane == 0){ sms[t] = s; sqs[t] = q; }
    __syncthreads();
    float ts = 0.f, tq = 0.f;
    #pragma unroll
    for (int i = 0; i < 12; i++){ ts += sms[i]; tq += sqs[i]; }
    float mean = ts * (1.f/768.f);
    float var  = tq * (1.f/768.f) - mean*mean;
    float sc   = rsqrtf(var + 1e-5f) * bg[d];
    float sb   = bb[d] - mean*sc;

    *(ull*)&g_x2[idx] = pk(v0, v1);
    *(ull*)&g_h[idx]  = pk(v0*sc + sb, v1*sc + sb);
}

// ---------------- FFN (register-tiled, 512 thr, 128-row tiles) ----------------
#define FF_TILES ((NTc + 127) / 128)   // 938 (last tile has 64 rows)
#define FF_SMEM ((8192 + 8192 + 128 + 64 + 64*132 + 128*132) * 4)
__global__ void ff_kernel(const float* __restrict__ w1, const float* __restrict__ b1,
                          const float* __restrict__ w2, const float* __restrict__ b2,
                          float* __restrict__ out){
    extern __shared__ float sm[];
    float* sW1 = sm;
    float* sW2 = sW1 + 8192;
    float* sB1 = sW2 + 8192;
    float* sB2 = sB1 + 128;
    float* sX  = sB2 + 64;
    float* sG  = sX  + 64*132;

    int tid  = threadIdx.x;
    int w    = tid >> 5;
    int lane = tid & 31;

    for (int i = tid; i < 8192; i += 512) sW1[i] = w1[i];
    for (int i = tid; i < 8192; i += 512) sW2[i] = w2[i];
    if (tid < 128) sB1[tid] = b1[tid];
    else if (tid < 192) sB2[tid-128] = b2[tid-128];
    __syncthreads();

    float b2v0 = sB2[2*lane], b2v1 = sB2[2*lane+1];

    for (int tile = blockIdx.x; tile < FF_TILES; tile += 148){
        size_t base = (size_t)tile * 128 * 64;

        #pragma unroll
        for (int it = 0; it < 16; it++){
            int i = tid + it*512;
            size_t gi = base + i;
            if (gi < (size_t)NTDc){
                int r = i >> 6, k = i & 63;
                sX[k*132 + r] = g_h[gi];
            }
        }
        __syncthreads();

        ull a1[4][4];
        #pragma unroll
        for (int c = 0; c < 4; c++)
            #pragma unroll
            for (int i = 0; i < 4; i++) a1[c][i] = 0ull;

        #pragma unroll 4
        for (int k = 0; k < 64; k++){
            double2 hd0 = *(const double2*)&sX[k*132 + 8*w];
            double2 hd1 = *(const double2*)&sX[k*132 + 8*w + 4];
            ull h01 = __double_as_longlong(hd0.x);
            ull h23 = __double_as_longlong(hd0.y);
            ull h45 = __double_as_longlong(hd1.x);
            ull h67 = __double_as_longlong(hd1.y);
            float4 wv = *(const float4*)&sW1[k*128 + 4*lane];
            ull ws0 = pk(wv.x, wv.x), ws1 = pk(wv.y, wv.y);
            ull ws2 = pk(wv.z, wv.z), ws3 = pk(wv.w, wv.w);
            a1[0][0] = fma2(h01, ws0, a1[0][0]);
            a1[0][1] = fma2(h23, ws0, a1[0][1]);
            a1[0][2] = fma2(h45, ws0, a1[0][2]);
            a1[0][3] = fma2(h67, ws0, a1[0][3]);
            a1[1][0] = fma2(h01, ws1, a1[1][0]);
            a1[1][1] = fma2(h23, ws1, a1[1][1]);
            a1[1][2] = fma2(h45, ws1, a1[1][2]);
            a1[1][3] = fma2(h67, ws1, a1[1][3]);
            a1[2][0] = fma2(h01, ws2, a1[2][0]);
            a1[2][1] = fma2(h23, ws2, a1[2][1]);
            a1[2][2] = fma2(h45, ws2, a1[2][2]);
            a1[2][3] = fma2(h67, ws2, a1[2][3]);
            a1[3][0] = fma2(h01, ws3, a1[3][0]);
            a1[3][1] = fma2(h23, ws3, a1[3][1]);
            a1[3][2] = fma2(h45, ws3, a1[3][2]);
            a1[3][3] = fma2(h67, ws3, a1[3][3]);
        }

        #pragma unroll
        for (int c = 0; c < 4; c++){
            int j = 4*lane + c;
            float bj = sB1[j];
            float g[8];
            #pragma unroll
            for (int i = 0; i < 4; i++){
                float2 f = upk(a1[c][i]);
                float u0 = f.x + bj, u1 = f.y + bj;
                g[2*i]   = 0.5f * u0 * (1.f + erff(u0 * 0.70710678118654752f));
                g[2*i+1] = 0.5f * u1 * (1.f + erff(u1 * 0.70710678118654752f));
            }
            double2 st0, st1;
            st0.x = __longlong_as_double(pk(g[0], g[1]));
            st0.y = __longlong_as_double(pk(g[2], g[3]));
            st1.x = __longlong_as_double(pk(g[4], g[5]));
            st1.y = __longlong_as_double(pk(g[6], g[7]));
            *(double2*)&sG[j*132 + 8*w]     = st0;
            *(double2*)&sG[j*132 + 8*w + 4] = st1;
        }
        __syncthreads();

        ull a2[2][4];
        #pragma unroll
        for (int c = 0; c < 2; c++)
            #pragma unroll
            for (int i = 0; i < 4; i++) a2[c][i] = 0ull;

        #pragma unroll 4
        for (int k = 0; k < 128; k++){
            double2 gd0 = *(const double2*)&sG[k*132 + 8*w];
            double2 gd1 = *(const double2*)&sG[k*132 + 8*w + 4];
            ull g01 = __double_as_longlong(gd0.x);
            ull g23 = __double_as_longlong(gd0.y);
            ull g45 = __double_as_longlong(gd1.x);
            ull g67 = __double_as_longlong(gd1.y);
            ull wv2 = *(const ull*)&sW2[k*64 + 2*lane];
            float2 wf = upk(wv2);
            ull ws0 = pk(wf.x, wf.x), ws1 = pk(wf.y, wf.y);
            a2[0][0] = fma2(g01, ws0, a2[0][0]);
            a2[0][1] = fma2(g23, ws0, a2[0][1]);
            a2[0][2] = fma2(g45, ws0, a2[0][2]);
            a2[0][3] = fma2(g67, ws0, a2[0][3]);
            a2[1][0] = fma2(g01, ws1, a2[1][0]);
            a2[1][1] = fma2(g23, ws1, a2[1][1]);
            a2[1][2] = fma2(g45, ws1, a2[1][2]);
            a2[1][3] = fma2(g67, ws1, a2[1][3]);
        }

        #pragma unroll
        for (int i = 0; i < 4; i++){
            float2 f0 = upk(a2[0][i]);
            float2 f1 = upk(a2[1][i]);
            size_t o = base + (size_t)(8*w + 2*i)*64 + 2*lane;
            if (o < (size_t)NTDc){
                out[o]    = g_x2[o]    + f0.x + b2v0;
                out[o+1]  = g_x2[o+1]  + f1.x + b2v1;
                out[o+64] = g_x2[o+64] + f0.y + b2v0;
                out[o+65] = g_x2[o+65] + f1.y + b2v1;
            }
        }
        __syncthreads();
    }
}

// ---------------- launcher ----------------
extern "C" void kernel_launch(void* const* d_in, const int* in_sizes, int n_in,
                              void* d_out, int out_size){
    const float* x    = (const float*)d_in[0];
    const int*   src1 = (const int*)d_in[1];
    const int*   dst1 = (const int*)d_in[2];
    const int*   src2 = (const int*)d_in[3];
    const int*   dst2 = (const int*)d_in[4];
    const float* W1   = (const float*)d_in[5];
    const float* al1  = (const float*)d_in[6];
    const float* ar1  = (const float*)d_in[7];
    const float* W2   = (const float*)d_in[8];
    const float* al2  = (const float*)d_in[9];
    const float* ar2  = (const float*)d_in[10];
    const float* bn1g = (const float*)d_in[11];
    const float* bn1b = (const float*)d_in[12];
    const float* bn2g = (const float*)d_in[13];
    const float* bn2b = (const float*)d_in[14];
    const float* fw1  = (const float*)d_in[15];
    const float* fb1  = (const float*)d_in[16];
    const float* fw2  = (const float*)d_in[17];
    const float* fb2  = (const float*)d_in[18];
    float* out = (float*)d_out;

    cudaFuncSetAttribute(ff_kernel, cudaFuncAttributeMaxDynamicSharedMemorySize, FF_SMEM);

    csr_hist<<<(2*Ee + 255)/256, 256>>>(dst1, dst2);               // idx 0
    csr_scan<<<1, 1024>>>();                                        // idx 1
    scatter_zel<<<SCAT_BLKS + NTc/48, 256>>>(src1, dst1, src2, dst2,
        x, bn1g, bn1b, W1, al1, ar1, W2, al2, ar2);                 // idx 2
    gat_kernel<<<Nn, 384>>>(x, bn2g, bn2b);                         // idx 3 (profiled)
    ff_kernel<<<148, 512, FF_SMEM>>>(fw1, fb1, fw2, fb2, out);      // idx 4
}

// round 9
// speedup vs baseline: 2.5141x; 1.0146x over previous
#include <cuda_runtime.h>
#include <math.h>

#define Nn   10000
#define Tt   12
#define Ee   100000
#define NTc  (Nn*Tt)        // 120000
#define NTDc (NTc*64)       // 7680000
#define CAP  128
#define SCAT_BLKS 782       // ceil(2*Ee/256)

typedef unsigned long long ull;

// ---------------- scratch ----------------
__device__ float g_h[NTDc];          // BN2 output (input to FFN)
__device__ float g_z[2][NTDc];       // per-relation projected features
__device__ float g_x2[NTDc];         // residual x + m1 + m2
__device__ float g_el[2][NTc*4];
__device__ float g_er[2][NTc*4];
__device__ int   g_cnt[2*(Nn+1)];    // starts zero; scan re-zeros after reading
__device__ int   g_rowptr[2*(Nn+1)];
__device__ int   g_fill[2*Nn];
__device__ int   g_esrc[2][Ee];      // src node BYTE OFFSETS (src*3072)

// ---------------- f32x2 helpers ----------------
__device__ __forceinline__ ull pk(float a, float b){
    ull r;
    asm("mov.b64 %0, {%1, %2};" : "=l"(r) : "r"(__float_as_uint(a)), "r"(__float_as_uint(b)));
    return r;
}
__device__ __forceinline__ ull fma2(ull a, ull b, ull c){
    ull d;
    asm("fma.rn.f32x2 %0, %1, %2, %3;" : "=l"(d) : "l"(a), "l"(b), "l"(c));
    return d;
}
__device__ __forceinline__ ull mul2(ull a, ull b){
    ull d;
    asm("mul.rn.f32x2 %0, %1, %2;" : "=l"(d) : "l"(a), "l"(b));
    return d;
}
__device__ __forceinline__ ull add2(ull a, ull b){
    ull d;
    asm("add.rn.f32x2 %0, %1, %2;" : "=l"(d) : "l"(a), "l"(b));
    return d;
}
__device__ __forceinline__ float2 upk(ull v){
    unsigned lo, hi;
    asm("mov.b64 {%0, %1}, %2;" : "=r"(lo), "=r"(hi) : "l"(v));
    return make_float2(__uint_as_float(lo), __uint_as_float(hi));
}
// warp-wide reductions via shfl butterfly (no fp32 redux on sm_103)
__device__ __forceinline__ float rmax32(float v){
    #pragma unroll
    for (int o = 16; o; o >>= 1)
        v = fmaxf(v, __shfl_xor_sync(0xffffffffu, v, o));
    return v;
}
__device__ __forceinline__ float radd32(float v){
    #pragma unroll
    for (int o = 16; o; o >>= 1)
        v += __shfl_xor_sync(0xffffffffu, v, o);
    return v;
}

// ---------------- CSR: histogram ----------------
__global__ void csr_hist(const int* __restrict__ dst1, const int* __restrict__ dst2){
    int e = blockIdx.x * 256 + threadIdx.x;
    if (e < Ee)            atomicAdd(&g_cnt[dst1[e] + 1], 1);
    else if (e < 2*Ee)     atomicAdd(&g_cnt[(Nn+1) + dst2[e-Ee] + 1], 1);
}

// ---------------- CSR: scan (self-zeros g_cnt for next replay) ----------------
__global__ void csr_scan(){
    __shared__ int wsum[32];
    int tid = threadIdx.x, lane = tid & 31, w = tid >> 5;
    for (int rel = 0; rel < 2; rel++){
        int* cnt = g_cnt    + rel*(Nn+1);
        int* rp  = g_rowptr + rel*(Nn+1);
        int* fl  = g_fill   + rel*Nn;
        int base = tid * 10;
        int v[10]; int s = 0;
        #pragma unroll
        for (int i = 0; i < 10; i++){
            int idx = base + i;
            int c = 0;
            if (idx <= Nn){ c = cnt[idx]; cnt[idx] = 0; }
            s += c; v[i] = s;
        }
        int t = s;
        #pragma unroll
        for (int o = 1; o < 32; o <<= 1){
            int u = __shfl_up_sync(0xffffffffu, t, o);
            if (lane >= o) t += u;
        }
        if (lane == 31) wsum[w] = t;
        __syncthreads();
        if (w == 0){
            int ws = wsum[lane];
            #pragma unroll
            for (int o = 1; o < 32; o <<= 1){
                int u = __shfl_up_sync(0xffffffffu, ws, o);
                if (lane >= o) ws += u;
            }
            wsum[lane] = ws;
        }
        __syncthreads();
        int off = ((w > 0) ? wsum[w-1] : 0) + (t - s);
        #pragma unroll
        for (int i = 0; i < 10; i++){
            int idx = base + i;
            if (idx <= Nn){
                int val = off + v[i];
                rp[idx] = val;
                if (idx < Nn) fl[idx] = val;
            }
        }
        __syncthreads();
    }
}

// ---------------- fused: CSR scatter (blocks 0..781) + BN1/z/el/er (rest) -----
__global__ void scatter_zel(const int* __restrict__ src1, const int* __restrict__ dst1,
                            const int* __restrict__ src2, const int* __restrict__ dst2,
                            const float* __restrict__ x,
                            const float* __restrict__ bg, const float* __restrict__ bb,
                            const float* __restrict__ W1, const float* __restrict__ al1, const float* __restrict__ ar1,
                            const float* __restrict__ W2, const float* __restrict__ al2, const float* __restrict__ ar2){
    if (blockIdx.x < SCAT_BLKS){
        int e = blockIdx.x * 256 + threadIdx.x;
        if (e < Ee){
            int p = atomicAdd(&g_fill[dst1[e]], 1);
            g_esrc[0][p] = src1[e] * 3072;       // z-row byte offset
        } else if (e < 2*Ee){
            int p = atomicAdd(&g_fill[Nn + dst2[e-Ee]], 1);
            g_esrc[1][p] = src2[e-Ee] * 3072;
        }
        return;
    }

    __shared__ __align__(16) float sh[64*52];
    __shared__ __align__(16) float sW[64*64];
    __shared__ __align__(16) float zred[64*52];
    __shared__ float red[8];
    __shared__ float nsc[4], nsh[4];

    int tid  = threadIdx.x;
    int lane = tid & 31;
    int w    = tid >> 5;
    int wcol = w & 3;
    int khalf= w >> 2;
    int rg   = lane >> 3;
    int cg   = lane & 7;
    int r0   = rg * 12;
    int c0   = wcol*16 + 2*cg;
    int bz   = blockIdx.x - SCAT_BLKS;
    int nt0  = bz * 48;
    int nd0  = bz * 4;

    if (tid < 8) red[tid] = 0.f;
    __syncthreads();

    float ls[4] = {0,0,0,0}, lq[4] = {0,0,0,0};
    #pragma unroll
    for (int it = 0; it < 12; it++){
        int i = tid + it*256;
        float v = x[(size_t)nt0*64 + i];
        int row = i >> 6, d = i & 63;
        sh[d*52 + row] = v;
        int nl = row / 12;
        ls[nl] += v; lq[nl] += v*v;
    }
    #pragma unroll
    for (int nl = 0; nl < 4; nl++){
        ls[nl] = radd32(ls[nl]);
        lq[nl] = radd32(lq[nl]);
    }
    if (lane == 0){
        #pragma unroll
        for (int nl = 0; nl < 4; nl++){
            if (ls[nl] != 0.f || lq[nl] != 0.f){
                atomicAdd(&red[2*nl],   ls[nl]);
                atomicAdd(&red[2*nl+1], lq[nl]);
            }
        }
    }
    __syncthreads();
    if (tid < 4){
        float mean = red[2*tid] * (1.f/768.f);
        float var  = red[2*tid+1] * (1.f/768.f) - mean*mean;
        float sc   = rsqrtf(var + 1e-5f) * bg[nd0 + tid];
        nsc[tid] = sc;
        nsh[tid] = bb[nd0 + tid] - mean*sc;
    }
    __syncthreads();
    #pragma unroll
    for (int it = 0; it < 12; it++){
        int i = tid + it*256;
        int row = i >> 6, d = i & 63;
        int nl = row / 12;
        sh[d*52 + row] = sh[d*52 + row]*nsc[nl] + nsh[nl];
    }
    __syncthreads();

    for (int rel = 0; rel < 2; rel++){
        const float* W  = rel ? W2  : W1;
        const float* al = rel ? al2 : al1;
        const float* ar = rel ? ar2 : ar1;
        for (int i = tid; i < 4096; i += 256) sW[i] = W[i];
        __syncthreads();

        ull acc[2][6];
        #pragma unroll
        for (int c = 0; c < 2; c++)
            #pragma unroll
            for (int i = 0; i < 6; i++) acc[c][i] = 0ull;

        int kb = khalf * 32;
        #pragma unroll 4
        for (int kk = 0; kk < 32; kk++){
            int k = kb + kk;
            ull w2v = *(const ull*)&sW[k*64 + c0];
            float2 wf = upk(w2v);
            ull ws0 = pk(wf.x, wf.x);
            ull ws1 = pk(wf.y, wf.y);
            const float4* hb = (const float4*)&sh[k*52 + r0];
            float4 hA = hb[0], hB = hb[1], hC = hb[2];
            ull h2[6];
            h2[0] = pk(hA.x, hA.y); h2[1] = pk(hA.z, hA.w);
            h2[2] = pk(hB.x, hB.y); h2[3] = pk(hB.z, hB.w);
            h2[4] = pk(hC.x, hC.y); h2[5] = pk(hC.z, hC.w);
            #pragma unroll
            for (int i = 0; i < 6; i++){
                acc[0][i] = fma2(h2[i], ws0, acc[0][i]);
                acc[1][i] = fma2(h2[i], ws1, acc[1][i]);
            }
        }

        if (khalf == 1){
            #pragma unroll
            for (int c = 0; c < 2; c++)
                #pragma unroll
                for (int i = 0; i < 6; i++)
                    *(ull*)&zred[(c0+c)*52 + r0 + 2*i] = acc[c][i];
        }
        __syncthreads();
        if (khalf == 0){
            #pragma unroll
            for (int c = 0; c < 2; c++)
                #pragma unroll
                for (int i = 0; i < 6; i++)
                    acc[c][i] = add2(acc[c][i], *(const ull*)&zred[(c0+c)*52 + r0 + 2*i]);
            #pragma unroll
            for (int c = 0; c < 2; c++)
                #pragma unroll
                for (int i = 0; i < 6; i++)
                    *(ull*)&zred[(c0+c)*52 + r0 + 2*i] = acc[c][i];

            ull al0 = pk(al[c0], al[c0]),   al1v = pk(al[c0+1], al[c0+1]);
            ull ar0 = pk(ar[c0], ar[c0]),   ar1v = pk(ar[c0+1], ar[c0+1]);
            ull pl[6], pr[6];
            #pragma unroll
            for (int i = 0; i < 6; i++){
                pl[i] = fma2(acc[1][i], al1v, mul2(acc[0][i], al0));
                pr[i] = fma2(acc[1][i], ar1v, mul2(acc[0][i], ar0));
            }
            #pragma unroll
            for (int o = 1; o < 8; o <<= 1){
                #pragma unroll
                for (int i = 0; i < 6; i++){
                    pl[i] = add2(pl[i], __shfl_xor_sync(0xffffffffu, pl[i], o));
                    pr[i] = add2(pr[i], __shfl_xor_sync(0xffffffffu, pr[i], o));
                }
            }
            if (cg == 0){
                #pragma unroll
                for (int i = 0; i < 6; i++){
                    float2 fl = upk(pl[i]);
                    float2 fr = upk(pr[i]);
                    int nt = nt0 + r0 + 2*i;
                    g_el[rel][nt*4 + wcol]     = fl.x;
                    g_el[rel][(nt+1)*4 + wcol] = fl.y;
                    g_er[rel][nt*4 + wcol]     = fr.x;
                    g_er[rel][(nt+1)*4 + wcol] = fr.y;
                }
            }
        }
        __syncthreads();
        #pragma unroll
        for (int it = 0; it < 12; it++){
            int i = tid + it*256;
            int row = i >> 6, d = i & 63;
            g_z[rel][(size_t)nt0*64 + i] = zred[d*52 + row];
        }
        __syncthreads();
    }
}

// ---------------- fused GAT (both rels) + residual + BN2 ----------------
// block = node d, 12 warps (one per t). s_w is WARP-PRIVATE -> no block
// barriers inside the relation loop. g_esrc holds byte offsets (src*3072).
__global__ void gat_kernel(const float* __restrict__ x,
                           const float* __restrict__ bg, const float* __restrict__ bb){
    __shared__ int   s_src[2][CAP];
    __shared__ float s_w[12][CAP*4];
    __shared__ float sms[12], sqs[12];

    int d    = blockIdx.x;
    int tid  = threadIdx.x;
    int t    = tid >> 5;
    int lane = tid & 31;
    int hA   = lane >> 3;

    int beg[2], deg[2];
    #pragma unroll
    for (int rel = 0; rel < 2; rel++){
        beg[rel] = g_rowptr[rel*(Nn+1) + d];
        deg[rel] = g_rowptr[rel*(Nn+1) + d + 1] - beg[rel];
        for (int i = tid; i < min(deg[rel], CAP); i += 384)
            s_src[rel][i] = g_esrc[rel][beg[rel] + i];
    }
    __syncthreads();

    ull m2 = 0ull;

    #pragma unroll
    for (int rel = 0; rel < 2; rel++){
        int dg = deg[rel], bg_e = beg[rel];
        const char* elb = (const char*)g_el[rel] + t*16;   // + (off>>4) -> el[s*48+t*4]
        const char* ztb = (const char*)g_z[rel] + t*256 + lane*8;
        float4 er4 = *(const float4*)&g_er[rel][d*48 + t*4];

        float mx0, mx1, mx2, mx3, dn0, dn1, dn2, dn3;

        if (dg <= 32){
            float a0 = -1e30f, a1 = -1e30f, a2 = -1e30f, a3 = -1e30f;
            if (lane < dg){
                int off = s_src[rel][lane];
                float4 e4 = *(const float4*)(elb + (off >> 4));
                a0 = e4.x + er4.x; a1 = e4.y + er4.y;
                a2 = e4.z + er4.z; a3 = e4.w + er4.w;
                a0 = (a0 > 0.f) ? a0 : 0.2f*a0;
                a1 = (a1 > 0.f) ? a1 : 0.2f*a1;
                a2 = (a2 > 0.f) ? a2 : 0.2f*a2;
                a3 = (a3 > 0.f) ? a3 : 0.2f*a3;
            }
            mx0 = rmax32(a0); mx1 = rmax32(a1);
            mx2 = rmax32(a2); mx3 = rmax32(a3);
            float w0 = 0.f, w1 = 0.f, w2 = 0.f, w3 = 0.f;
            if (lane < dg){
                w0 = __expf(a0 - mx0); w1 = __expf(a1 - mx1);
                w2 = __expf(a2 - mx2); w3 = __expf(a3 - mx3);
                *(float4*)&s_w[t][lane*4] = make_float4(w0, w1, w2, w3);
            }
            dn0 = radd32(w0); dn1 = radd32(w1);
            dn2 = radd32(w2); dn3 = radd32(w3);
        } else {
            mx0 = -1e30f; mx1 = -1e30f; mx2 = -1e30f; mx3 = -1e30f;
            for (int e = lane; e < dg; e += 32){
                int off = (e < CAP) ? s_src[rel][e] : g_esrc[rel][bg_e + e];
                float4 e4 = *(const float4*)(elb + (off >> 4));
                float a0 = e4.x + er4.x, a1 = e4.y + er4.y;
                float a2 = e4.z + er4.z, a3 = e4.w + er4.w;
                a0 = (a0 > 0.f) ? a0 : 0.2f*a0;
                a1 = (a1 > 0.f) ? a1 : 0.2f*a1;
                a2 = (a2 > 0.f) ? a2 : 0.2f*a2;
                a3 = (a3 > 0.f) ? a3 : 0.2f*a3;
                if (e < CAP)
                    *(float4*)&s_w[t][e*4] = make_float4(a0, a1, a2, a3);
                mx0 = fmaxf(mx0, a0); mx1 = fmaxf(mx1, a1);
                mx2 = fmaxf(mx2, a2); mx3 = fmaxf(mx3, a3);
            }
            mx0 = rmax32(mx0); mx1 = rmax32(mx1);
            mx2 = rmax32(mx2); mx3 = rmax32(mx3);
            dn0 = 0.f; dn1 = 0.f; dn2 = 0.f; dn3 = 0.f;
            for (int e = lane; e < dg; e += 32){
                float a0, a1, a2, a3;
                if (e < CAP){
                    float4 a4 = *(const float4*)&s_w[t][e*4];
                    a0 = a4.x; a1 = a4.y; a2 = a4.z; a3 = a4.w;
                } else {
                    int off = g_esrc[rel][bg_e + e];
                    float4 e4 = *(const float4*)(elb + (off >> 4));
                    a0 = e4.x + er4.x; a1 = e4.y + er4.y;
                    a2 = e4.z + er4.z; a3 = e4.w + er4.w;
                    a0 = (a0 > 0.f) ? a0 : 0.2f*a0;
                    a1 = (a1 > 0.f) ? a1 : 0.2f*a1;
                    a2 = (a2 > 0.f) ? a2 : 0.2f*a2;
                    a3 = (a3 > 0.f) ? a3 : 0.2f*a3;
                }
                float w0 = __expf(a0 - mx0), w1 = __expf(a1 - mx1);
                float w2 = __expf(a2 - mx2), w3 = __expf(a3 - mx3);
                dn0 += w0; dn1 += w1; dn2 += w2; dn3 += w3;
                if (e < CAP)
                    *(float4*)&s_w[t][e*4] = make_float4(w0, w1, w2, w3);
            }
            dn0 = radd32(dn0); dn1 = radd32(dn1);
            dn2 = radd32(dn2); dn3 = radd32(dn3);
        }

        float dnA = (hA < 2) ? ((hA == 0) ? dn0 : dn1) : ((hA == 2) ? dn2 : dn3);
        float mxA = (hA < 2) ? ((hA == 0) ? mx0 : mx1) : ((hA == 2) ? mx2 : mx3);
        float erA = (hA < 2) ? ((hA == 0) ? er4.x : er4.y) : ((hA == 2) ? er4.z : er4.w);
        float inv = 1.f / fmaxf(dnA, 1e-16f);

        __syncwarp();

        // phase 2: dual accumulators, 2 edges per iteration
        ull ac0 = 0ull, ac1 = 0ull;
        int ecached = min(dg, CAP);
        const float* wrow = s_w[t];
        int e = 0;
        #pragma unroll 2
        for (; e + 1 < ecached; e += 2){
            int o0 = s_src[rel][e];
            int o1 = s_src[rel][e+1];
            float wv0 = wrow[e*4 + hA];
            float wv1 = wrow[(e+1)*4 + hA];
            ull z0 = *(const ull*)(ztb + o0);
            ull z1 = *(const ull*)(ztb + o1);
            ac0 = fma2(pk(wv0, wv0), z0, ac0);
            ac1 = fma2(pk(wv1, wv1), z1, ac1);
        }
        if (e < ecached){
            int o0 = s_src[rel][e];
            float wv0 = wrow[e*4 + hA];
            ull z0 = *(const ull*)(ztb + o0);
            ac0 = fma2(pk(wv0, wv0), z0, ac0);
        }
        for (int ec = ecached; ec < dg; ++ec){   // cold path
            int off = g_esrc[rel][bg_e + ec];
            float4 e4 = *(const float4*)(elb + (off >> 4));
            float a = ((hA == 0) ? e4.x : (hA == 1) ? e4.y : (hA == 2) ? e4.z : e4.w) + erA;
            a = (a > 0.f) ? a : 0.2f*a;
            float wv = __expf(a - mxA);
            ull z2 = *(const ull*)(ztb + off);
            ac0 = fma2(pk(wv, wv), z2, ac0);
        }
        ull ac = add2(ac0, ac1);
        m2 = add2(m2, mul2(ac, pk(inv, inv)));
        // no block barrier: s_w/s_src are read-only or warp-private from here
    }

    size_t idx = (size_t)d*768 + t*64 + 2*lane;
    float2 xm = upk(*(const ull*)&x[idx]);
    float2 mm = upk(m2);
    float v0 = xm.x + mm.x;
    float v1 = xm.y + mm.y;

    float s = radd32(v0 + v1);
    float q = radd32(v0*v0 + v1*v1);
    if (lane == 0){ sms[t] = s; sqs[t] = q; }
    __syncthreads();
    float ts = 0.f, tq = 0.f;
    #pragma unroll
    for (int i = 0; i < 12; i++){ ts += sms[i]; tq += sqs[i]; }
    float mean = ts * (1.f/768.f);
    float var  = tq * (1.f/768.f) - mean*mean;
    float sc   = rsqrtf(var + 1e-5f) * bg[d];
    float sb   = bb[d] - mean*sc;

    *(ull*)&g_x2[idx] = pk(v0, v1);
    *(ull*)&g_h[idx]  = pk(v0*sc + sb, v1*sc + sb);
}

// ---------------- FFN (register-tiled, 512 thr, 128-row tiles) ----------------
#define FF_TILES ((NTc + 127) / 128)   // 938 (last tile has 64 rows)
#define FF_SMEM ((8192 + 8192 + 128 + 64 + 64*132 + 128*132) * 4)
__global__ void ff_kernel(const float* __restrict__ w1, const float* __restrict__ b1,
                          const float* __restrict__ w2, const float* __restrict__ b2,
                          float* __restrict__ out){
    extern __shared__ float sm[];
    float* sW1 = sm;
    float* sW2 = sW1 + 8192;
    float* sB1 = sW2 + 8192;
    float* sB2 = sB1 + 128;
    float* sX  = sB2 + 64;
    float* sG  = sX  + 64*132;

    int tid  = threadIdx.x;
    int w    = tid >> 5;
    int lane = tid & 31;

    for (int i = tid; i < 8192; i += 512) sW1[i] = w1[i];
    for (int i = tid; i < 8192; i += 512) sW2[i] = w2[i];
    if (tid < 128) sB1[tid] = b1[tid];
    else if (tid < 192) sB2[tid-128] = b2[tid-128];
    __syncthreads();

    float b2v0 = sB2[2*lane], b2v1 = sB2[2*lane+1];

    for (int tile = blockIdx.x; tile < FF_TILES; tile += 148){
        size_t base = (size_t)tile * 128 * 64;

        #pragma unroll
        for (int it = 0; it < 16; it++){
            int i = tid + it*512;
            size_t gi = base + i;
            if (gi < (size_t)NTDc){
                int r = i >> 6, k = i & 63;
                sX[k*132 + r] = g_h[gi];
            }
        }
        __syncthreads();

        ull a1[4][4];
        #pragma unroll
        for (int c = 0; c < 4; c++)
            #pragma unroll
            for (int i = 0; i < 4; i++) a1[c][i] = 0ull;

        #pragma unroll 4
        for (int k = 0; k < 64; k++){
            double2 hd0 = *(const double2*)&sX[k*132 + 8*w];
            double2 hd1 = *(const double2*)&sX[k*132 + 8*w + 4];
            ull h01 = __double_as_longlong(hd0.x);
            ull h23 = __double_as_longlong(hd0.y);
            ull h45 = __double_as_longlong(hd1.x);
            ull h67 = __double_as_longlong(hd1.y);
            float4 wv = *(const float4*)&sW1[k*128 + 4*lane];
            ull ws0 = pk(wv.x, wv.x), ws1 = pk(wv.y, wv.y);
            ull ws2 = pk(wv.z, wv.z), ws3 = pk(wv.w, wv.w);
            a1[0][0] = fma2(h01, ws0, a1[0][0]);
            a1[0][1] = fma2(h23, ws0, a1[0][1]);
            a1[0][2] = fma2(h45, ws0, a1[0][2]);
            a1[0][3] = fma2(h67, ws0, a1[0][3]);
            a1[1][0] = fma2(h01, ws1, a1[1][0]);
            a1[1][1] = fma2(h23, ws1, a1[1][1]);
            a1[1][2] = fma2(h45, ws1, a1[1][2]);
            a1[1][3] = fma2(h67, ws1, a1[1][3]);
            a1[2][0] = fma2(h01, ws2, a1[2][0]);
            a1[2][1] = fma2(h23, ws2, a1[2][1]);
            a1[2][2] = fma2(h45, ws2, a1[2][2]);
            a1[2][3] = fma2(h67, ws2, a1[2][3]);
            a1[3][0] = fma2(h01, ws3, a1[3][0]);
            a1[3][1] = fma2(h23, ws3, a1[3][1]);
            a1[3][2] = fma2(h45, ws3, a1[3][2]);
            a1[3][3] = fma2(h67, ws3, a1[3][3]);
        }

        #pragma unroll
        for (int c = 0; c < 4; c++){
            int j = 4*lane + c;
            float bj = sB1[j];
            float g[8];
            #pragma unroll
            for (int i = 0; i < 4; i++){
                float2 f = upk(a1[c][i]);
                float u0 = f.x + bj, u1 = f.y + bj;
                g[2*i]   = 0.5f * u0 * (1.f + erff(u0 * 0.70710678118654752f));
                g[2*i+1] = 0.5f * u1 * (1.f + erff(u1 * 0.70710678118654752f));
            }
            double2 st0, st1;
            st0.x = __longlong_as_double(pk(g[0], g[1]));
            st0.y = __longlong_as_double(pk(g[2], g[3]));
            st1.x = __longlong_as_double(pk(g[4], g[5]));
            st1.y = __longlong_as_double(pk(g[6], g[7]));
            *(double2*)&sG[j*132 + 8*w]     = st0;
            *(double2*)&sG[j*132 + 8*w + 4] = st1;
        }
        __syncthreads();

        ull a2[2][4];
        #pragma unroll
        for (int c = 0; c < 2; c++)
            #pragma unroll
            for (int i = 0; i < 4; i++) a2[c][i] = 0ull;

        #pragma unroll 4
        for (int k = 0; k < 128; k++){
            double2 gd0 = *(const double2*)&sG[k*132 + 8*w];
            double2 gd1 = *(const double2*)&sG[k*132 + 8*w + 4];
            ull g01 = __double_as_longlong(gd0.x);
            ull g23 = __double_as_longlong(gd0.y);
            ull g45 = __double_as_longlong(gd1.x);
            ull g67 = __double_as_longlong(gd1.y);
            ull wv2 = *(const ull*)&sW2[k*64 + 2*lane];
            float2 wf = upk(wv2);
            ull ws0 = pk(wf.x, wf.x), ws1 = pk(wf.y, wf.y);
            a2[0][0] = fma2(g01, ws0, a2[0][0]);
            a2[0][1] = fma2(g23, ws0, a2[0][1]);
            a2[0][2] = fma2(g45, ws0, a2[0][2]);
            a2[0][3] = fma2(g67, ws0, a2[0][3]);
            a2[1][0] = fma2(g01, ws1, a2[1][0]);
            a2[1][1] = fma2(g23, ws1, a2[1][1]);
            a2[1][2] = fma2(g45, ws1, a2[1][2]);
            a2[1][3] = fma2(g67, ws1, a2[1][3]);
        }

        #pragma unroll
        for (int i = 0; i < 4; i++){
            float2 f0 = upk(a2[0][i]);
            float2 f1 = upk(a2[1][i]);
            size_t o = base + (size_t)(8*w + 2*i)*64 + 2*lane;
            if (o < (size_t)NTDc){
                out[o]    = g_x2[o]    + f0.x + b2v0;
                out[o+1]  = g_x2[o+1]  + f1.x + b2v1;
                out[o+64] = g_x2[o+64] + f0.y + b2v0;
                out[o+65] = g_x2[o+65] + f1.y + b2v1;
            }
        }
        __syncthreads();
    }
}

// ---------------- launcher ----------------
extern "C" void kernel_launch(void* const* d_in, const int* in_sizes, int n_in,
                              void* d_out, int out_size){
    const float* x    = (const float*)d_in[0];
    const int*   src1 = (const int*)d_in[1];
    const int*   dst1 = (const int*)d_in[2];
    const int*   src2 = (const int*)d_in[3];
    const int*   dst2 = (const int*)d_in[4];
    const float* W1   = (const float*)d_in[5];
    const float* al1  = (const float*)d_in[6];
    const float* ar1  = (const float*)d_in[7];
    const float* W2   = (const float*)d_in[8];
    const float* al2  = (const float*)d_in[9];
    const float* ar2  = (const float*)d_in[10];
    const float* bn1g = (const float*)d_in[11];
    const float* bn1b = (const float*)d_in[12];
    const float* bn2g = (const float*)d_in[13];
    const float* bn2b = (const float*)d_in[14];
    const float* fw1  = (const float*)d_in[15];
    const float* fb1  = (const float*)d_in[16];
    const float* fw2  = (const float*)d_in[17];
    const float* fb2  = (const float*)d_in[18];
    float* out = (float*)d_out;

    cudaFuncSetAttribute(ff_kernel, cudaFuncAttributeMaxDynamicSharedMemorySize, FF_SMEM);

    csr_hist<<<(2*Ee + 255)/256, 256>>>(dst1, dst2);               // idx 0
    csr_scan<<<1, 1024>>>();                                        // idx 1
    scatter_zel<<<SCAT_BLKS + NTc/48, 256>>>(src1, dst1, src2, dst2,
        x, bn1g, bn1b, W1, al1, ar1, W2, al2, ar2);                 // idx 2
    gat_kernel<<<Nn, 384>>>(x, bn2g, bn2b);                         // idx 3 (profiled)
    ff_kernel<<<148, 512, FF_SMEM>>>(fw1, fb1, fw2, fb2, out);      // idx 4
}

// round 10
// speedup vs baseline: 2.6162x; 1.0406x over previous
#include <cuda_runtime.h>
#include <math.h>

#define Nn   10000
#define Tt   12
#define Ee   100000
#define NTc  (Nn*Tt)        // 120000
#define NTDc (NTc*64)       // 7680000
#define SCAT_BLKS 782       // ceil(2*Ee/256)

typedef unsigned long long ull;

// ---------------- scratch ----------------
__device__ float g_h[NTDc];          // BN2 output (input to FFN)
__device__ float g_z[2][NTDc];       // per-relation projected features
__device__ float g_x2[NTDc];         // residual x + m1 + m2
__device__ float g_el[2][NTc*4];
__device__ float g_er[2][NTc*4];
__device__ int   g_cnt[2*(Nn+1)];    // starts zero; scan re-zeros after reading
__device__ int   g_rowptr[2*(Nn+1)];
__device__ int   g_fill[2*Nn];
__device__ int   g_esrc[2][Ee];      // src node BYTE OFFSETS (src*3072)

// ---------------- f32x2 helpers ----------------
__device__ __forceinline__ ull pk(float a, float b){
    ull r;
    asm("mov.b64 %0, {%1, %2};" : "=l"(r) : "r"(__float_as_uint(a)), "r"(__float_as_uint(b)));
    return r;
}
__device__ __forceinline__ ull fma2(ull a, ull b, ull c){
    ull d;
    asm("fma.rn.f32x2 %0, %1, %2, %3;" : "=l"(d) : "l"(a), "l"(b), "l"(c));
    return d;
}
__device__ __forceinline__ ull mul2(ull a, ull b){
    ull d;
    asm("mul.rn.f32x2 %0, %1, %2;" : "=l"(d) : "l"(a), "l"(b));
    return d;
}
__device__ __forceinline__ ull add2(ull a, ull b){
    ull d;
    asm("add.rn.f32x2 %0, %1, %2;" : "=l"(d) : "l"(a), "l"(b));
    return d;
}
__device__ __forceinline__ float2 upk(ull v){
    unsigned lo, hi;
    asm("mov.b64 {%0, %1}, %2;" : "=r"(lo), "=r"(hi) : "l"(v));
    return make_float2(__uint_as_float(lo), __uint_as_float(hi));
}
// warp-wide reductions via shfl butterfly (no fp32 redux on sm_103)
__device__ __forceinline__ float rmax32(float v){
    #pragma unroll
    for (int o = 16; o; o >>= 1)
        v = fmaxf(v, __shfl_xor_sync(0xffffffffu, v, o));
    return v;
}
__device__ __forceinline__ float radd32(float v){
    #pragma unroll
    for (int o = 16; o; o >>= 1)
        v += __shfl_xor_sync(0xffffffffu, v, o);
    return v;
}
__device__ __forceinline__ float lrelu(float a){
    return (a > 0.f) ? a : 0.2f*a;
}

// ---------------- CSR: histogram ----------------
__global__ void csr_hist(const int* __restrict__ dst1, const int* __restrict__ dst2){
    int e = blockIdx.x * 256 + threadIdx.x;
    if (e < Ee)            atomicAdd(&g_cnt[dst1[e] + 1], 1);
    else if (e < 2*Ee)     atomicAdd(&g_cnt[(Nn+1) + dst2[e-Ee] + 1], 1);
}

// ---------------- CSR: scan (self-zeros g_cnt for next replay) ----------------
__global__ void csr_scan(){
    __shared__ int wsum[32];
    int tid = threadIdx.x, lane = tid & 31, w = tid >> 5;
    for (int rel = 0; rel < 2; rel++){
        int* cnt = g_cnt    + rel*(Nn+1);
        int* rp  = g_rowptr + rel*(Nn+1);
        int* fl  = g_fill   + rel*Nn;
        int base = tid * 10;
        int v[10]; int s = 0;
        #pragma unroll
        for (int i = 0; i < 10; i++){
            int idx = base + i;
            int c = 0;
            if (idx <= Nn){ c = cnt[idx]; cnt[idx] = 0; }
            s += c; v[i] = s;
        }
        int t = s;
        #pragma unroll
        for (int o = 1; o < 32; o <<= 1){
            int u = __shfl_up_sync(0xffffffffu, t, o);
            if (lane >= o) t += u;
        }
        if (lane == 31) wsum[w] = t;
        __syncthreads();
        if (w == 0){
            int ws = wsum[lane];
            #pragma unroll
            for (int o = 1; o < 32; o <<= 1){
                int u = __shfl_up_sync(0xffffffffu, ws, o);
                if (lane >= o) ws += u;
            }
            wsum[lane] = ws;
        }
        __syncthreads();
        int off = ((w > 0) ? wsum[w-1] : 0) + (t - s);
        #pragma unroll
        for (int i = 0; i < 10; i++){
            int idx = base + i;
            if (idx <= Nn){
                int val = off + v[i];
                rp[idx] = val;
                if (idx < Nn) fl[idx] = val;
            }
        }
        __syncthreads();
    }
}

// ---------------- fused: CSR scatter (blocks 0..781) + BN1/z/el/er (rest) -----
__global__ void scatter_zel(const int* __restrict__ src1, const int* __restrict__ dst1,
                            const int* __restrict__ src2, const int* __restrict__ dst2,
                            const float* __restrict__ x,
                            const float* __restrict__ bg, const float* __restrict__ bb,
                            const float* __restrict__ W1, const float* __restrict__ al1, const float* __restrict__ ar1,
                            const float* __restrict__ W2, const float* __restrict__ al2, const float* __restrict__ ar2){
    if (blockIdx.x < SCAT_BLKS){
        int e = blockIdx.x * 256 + threadIdx.x;
        if (e < Ee){
            int p = atomicAdd(&g_fill[dst1[e]], 1);
            g_esrc[0][p] = src1[e] * 3072;       // z-row byte offset
        } else if (e < 2*Ee){
            int p = atomicAdd(&g_fill[Nn + dst2[e-Ee]], 1);
            g_esrc[1][p] = src2[e-Ee] * 3072;
        }
        return;
    }

    __shared__ __align__(16) float sh[64*52];
    __shared__ __align__(16) float sW[64*64];
    __shared__ __align__(16) float zred[64*52];
    __shared__ float red[8];
    __shared__ float nsc[4], nsh[4];

    int tid  = threadIdx.x;
    int lane = tid & 31;
    int w    = tid >> 5;
    int wcol = w & 3;
    int khalf= w >> 2;
    int rg   = lane >> 3;
    int cg   = lane & 7;
    int r0   = rg * 12;
    int c0   = wcol*16 + 2*cg;
    int bz   = blockIdx.x - SCAT_BLKS;
    int nt0  = bz * 48;
    int nd0  = bz * 4;

    if (tid < 8) red[tid] = 0.f;
    __syncthreads();

    float ls[4] = {0,0,0,0}, lq[4] = {0,0,0,0};
    #pragma unroll
    for (int it = 0; it < 12; it++){
        int i = tid + it*256;
        float v = x[(size_t)nt0*64 + i];
        int row = i >> 6, d = i & 63;
        sh[d*52 + row] = v;
        int nl = row / 12;
        ls[nl] += v; lq[nl] += v*v;
    }
    #pragma unroll
    for (int nl = 0; nl < 4; nl++){
        ls[nl] = radd32(ls[nl]);
        lq[nl] = radd32(lq[nl]);
    }
    if (lane == 0){
        #pragma unroll
        for (int nl = 0; nl < 4; nl++){
            if (ls[nl] != 0.f || lq[nl] != 0.f){
                atomicAdd(&red[2*nl],   ls[nl]);
                atomicAdd(&red[2*nl+1], lq[nl]);
            }
        }
    }
    __syncthreads();
    if (tid < 4){
        float mean = red[2*tid] * (1.f/768.f);
        float var  = red[2*tid+1] * (1.f/768.f) - mean*mean;
        float sc   = rsqrtf(var + 1e-5f) * bg[nd0 + tid];
        nsc[tid] = sc;
        nsh[tid] = bb[nd0 + tid] - mean*sc;
    }
    __syncthreads();
    #pragma unroll
    for (int it = 0; it < 12; it++){
        int i = tid + it*256;
        int row = i >> 6, d = i & 63;
        int nl = row / 12;
        sh[d*52 + row] = sh[d*52 + row]*nsc[nl] + nsh[nl];
    }
    __syncthreads();

    for (int rel = 0; rel < 2; rel++){
        const float* W  = rel ? W2  : W1;
        const float* al = rel ? al2 : al1;
        const float* ar = rel ? ar2 : ar1;
        for (int i = tid; i < 4096; i += 256) sW[i] = W[i];
        __syncthreads();

        ull acc[2][6];
        #pragma unroll
        for (int c = 0; c < 2; c++)
            #pragma unroll
            for (int i = 0; i < 6; i++) acc[c][i] = 0ull;

        int kb = khalf * 32;
        #pragma unroll 4
        for (int kk = 0; kk < 32; kk++){
            int k = kb + kk;
            ull w2v = *(const ull*)&sW[k*64 + c0];
            float2 wf = upk(w2v);
            ull ws0 = pk(wf.x, wf.x);
            ull ws1 = pk(wf.y, wf.y);
            const float4* hb = (const float4*)&sh[k*52 + r0];
            float4 hA = hb[0], hB = hb[1], hC = hb[2];
            ull h2[6];
            h2[0] = pk(hA.x, hA.y); h2[1] = pk(hA.z, hA.w);
            h2[2] = pk(hB.x, hB.y); h2[3] = pk(hB.z, hB.w);
            h2[4] = pk(hC.x, hC.y); h2[5] = pk(hC.z, hC.w);
            #pragma unroll
            for (int i = 0; i < 6; i++){
                acc[0][i] = fma2(h2[i], ws0, acc[0][i]);
                acc[1][i] = fma2(h2[i], ws1, acc[1][i]);
            }
        }

        if (khalf == 1){
            #pragma unroll
            for (int c = 0; c < 2; c++)
                #pragma unroll
                for (int i = 0; i < 6; i++)
                    *(ull*)&zred[(c0+c)*52 + r0 + 2*i] = acc[c][i];
        }
        __syncthreads();
        if (khalf == 0){
            #pragma unroll
            for (int c = 0; c < 2; c++)
                #pragma unroll
                for (int i = 0; i < 6; i++)
                    acc[c][i] = add2(acc[c][i], *(const ull*)&zred[(c0+c)*52 + r0 + 2*i]);
            #pragma unroll
            for (int c = 0; c < 2; c++)
                #pragma unroll
                for (int i = 0; i < 6; i++)
                    *(ull*)&zred[(c0+c)*52 + r0 + 2*i] = acc[c][i];

            ull al0 = pk(al[c0], al[c0]),   al1v = pk(al[c0+1], al[c0+1]);
            ull ar0 = pk(ar[c0], ar[c0]),   ar1v = pk(ar[c0+1], ar[c0+1]);
            ull pl[6], pr[6];
            #pragma unroll
            for (int i = 0; i < 6; i++){
                pl[i] = fma2(acc[1][i], al1v, mul2(acc[0][i], al0));
                pr[i] = fma2(acc[1][i], ar1v, mul2(acc[0][i], ar0));
            }
            #pragma unroll
            for (int o = 1; o < 8; o <<= 1){
                #pragma unroll
                for (int i = 0; i < 6; i++){
                    pl[i] = add2(pl[i], __shfl_xor_sync(0xffffffffu, pl[i], o));
                    pr[i] = add2(pr[i], __shfl_xor_sync(0xffffffffu, pr[i], o));
                }
            }
            if (cg == 0){
                #pragma unroll
                for (int i = 0; i < 6; i++){
                    float2 fl = upk(pl[i]);
                    float2 fr = upk(pr[i]);
                    int nt = nt0 + r0 + 2*i;
                    g_el[rel][nt*4 + wcol]     = fl.x;
                    g_el[rel][(nt+1)*4 + wcol] = fl.y;
                    g_er[rel][nt*4 + wcol]     = fr.x;
                    g_er[rel][(nt+1)*4 + wcol] = fr.y;
                }
            }
        }
        __syncthreads();
        #pragma unroll
        for (int it = 0; it < 12; it++){
            int i = tid + it*256;
            int row = i >> 6, d = i & 63;
            g_z[rel][(size_t)nt0*64 + i] = zred[d*52 + row];
        }
        __syncthreads();
    }
}

// ---------------- fused GAT (both rels) + residual + BN2 ----------------
// block = node d, 6 warps; warp w handles t = 2w (half 0) and 2w+1 (half 1).
// lane: half = lane>>4, l16 = lane&15 -> cols 4*l16..4*l16+3, head = l16>>2.
// Phase 1 (deg<=32): lane = edge; offsets kept in registers, weights in s_w.
// Phase 2: offset via shfl (ALU), weight via 1 broadcast LDS, z via LDG.128.
__global__ void __launch_bounds__(192) gat_kernel(const float* __restrict__ x,
                           const float* __restrict__ bg, const float* __restrict__ bb){
    __shared__ float s_w[6][32*8];   // [warp][edge*8 + half*4 + head]
    __shared__ float sms[6], sqs[6];

    const unsigned FULL = 0xffffffffu;
    int d    = blockIdx.x;
    int w    = threadIdx.x >> 5;
    int lane = threadIdx.x & 31;
    int half = lane >> 4;
    int l16  = lane & 15;
    int hA   = l16 >> 2;
    int t0   = 2*w;

    ull m01 = 0ull, m23 = 0ull;

    #pragma unroll
    for (int rel = 0; rel < 2; rel++){
        int bg_e = g_rowptr[rel*(Nn+1) + d];
        int dg   = g_rowptr[rel*(Nn+1) + d + 1] - bg_e;
        const char* elb   = (const char*)g_el[rel];
        const char* zbase = (const char*)g_z[rel] + (t0+half)*256 + l16*16;
        float4 er0 = *(const float4*)&g_er[rel][d*48 + t0*4];
        float4 er1 = *(const float4*)&g_er[rel][d*48 + t0*4 + 4];

        float inv, mxSel;

        if (dg <= 32){
            // ---- phase 1: lane = edge ----
            int off = 0;
            float a00=-1e30f,a01=-1e30f,a02=-1e30f,a03=-1e30f;
            float a10=-1e30f,a11=-1e30f,a12=-1e30f,a13=-1e30f;
            if (lane < dg){
                off = g_esrc[rel][bg_e + lane];
                const char* ep = elb + (off >> 4) + t0*16;
                float4 f0 = *(const float4*)ep;
                float4 f1 = *(const float4*)(ep + 16);
                a00 = lrelu(f0.x + er0.x); a01 = lrelu(f0.y + er0.y);
                a02 = lrelu(f0.z + er0.z); a03 = lrelu(f0.w + er0.w);
                a10 = lrelu(f1.x + er1.x); a11 = lrelu(f1.y + er1.y);
                a12 = lrelu(f1.z + er1.z); a13 = lrelu(f1.w + er1.w);
            }
            float mx00=rmax32(a00), mx01=rmax32(a01), mx02=rmax32(a02), mx03=rmax32(a03);
            float mx10=rmax32(a10), mx11=rmax32(a11), mx12=rmax32(a12), mx13=rmax32(a13);
            float w00=0.f,w01=0.f,w02=0.f,w03=0.f,w10=0.f,w11=0.f,w12=0.f,w13=0.f;
            if (lane < dg){
                w00=__expf(a00-mx00); w01=__expf(a01-mx01);
                w02=__expf(a02-mx02); w03=__expf(a03-mx03);
                w10=__expf(a10-mx10); w11=__expf(a11-mx11);
                w12=__expf(a12-mx12); w13=__expf(a13-mx13);
                *(float4*)&s_w[w][lane*8]     = make_float4(w00,w01,w02,w03);
                *(float4*)&s_w[w][lane*8 + 4] = make_float4(w10,w11,w12,w13);
            }
            float dn00=radd32(w00), dn01=radd32(w01), dn02=radd32(w02), dn03=radd32(w03);
            float dn10=radd32(w10), dn11=radd32(w11), dn12=radd32(w12), dn13=radd32(w13);

            float dnSel = half ? ((hA==0)?dn10:(hA==1)?dn11:(hA==2)?dn12:dn13)
                               : ((hA==0)?dn00:(hA==1)?dn01:(hA==2)?dn02:dn03);
            inv = 1.f / fmaxf(dnSel, 1e-16f);

            __syncwarp();

            // ---- phase 2: edges serial, dual accumulators ----
            ull p0=0ull, p1=0ull, q0=0ull, q1=0ull;
            const float* wrow = &s_w[w][half*4 + hA];
            int e = 0;
            for (; e + 1 < dg; e += 2){
                int ofA = __shfl_sync(FULL, off, e);
                int ofB = __shfl_sync(FULL, off, e+1);
                float wA = wrow[e*8];
                float wB = wrow[e*8 + 8];
                ulonglong2 zA = *(const ulonglong2*)(zbase + ofA);
                ulonglong2 zB = *(const ulonglong2*)(zbase + ofB);
                ull wA2 = pk(wA, wA), wB2 = pk(wB, wB);
                p0 = fma2(wA2, zA.x, p0);
                p1 = fma2(wA2, zA.y, p1);
                q0 = fma2(wB2, zB.x, q0);
                q1 = fma2(wB2, zB.y, q1);
            }
            if (e < dg){
                int ofA = __shfl_sync(FULL, off, e);
                float wA = wrow[e*8];
                ulonglong2 zA = *(const ulonglong2*)(zbase + ofA);
                ull wA2 = pk(wA, wA);
                p0 = fma2(wA2, zA.x, p0);
                p1 = fma2(wA2, zA.y, p1);
            }
            ull inv2 = pk(inv, inv);
            m01 = add2(m01, mul2(add2(p0, q0), inv2));
            m23 = add2(m23, mul2(add2(p1, q1), inv2));
        } else {
            // ---- fallback (deg>32, ~never): two strided passes + recompute ----
            float mx00=-1e30f,mx01=-1e30f,mx02=-1e30f,mx03=-1e30f;
            float mx10=-1e30f,mx11=-1e30f,mx12=-1e30f,mx13=-1e30f;
            for (int e = lane; e < dg; e += 32){
                int off = g_esrc[rel][bg_e + e];
                const char* ep = elb + (off >> 4) + t0*16;
                float4 f0 = *(const float4*)ep;
                float4 f1 = *(const float4*)(ep + 16);
                mx00=fmaxf(mx00, lrelu(f0.x+er0.x)); mx01=fmaxf(mx01, lrelu(f0.y+er0.y));
                mx02=fmaxf(mx02, lrelu(f0.z+er0.z)); mx03=fmaxf(mx03, lrelu(f0.w+er0.w));
                mx10=fmaxf(mx10, lrelu(f1.x+er1.x)); mx11=fmaxf(mx11, lrelu(f1.y+er1.y));
                mx12=fmaxf(mx12, lrelu(f1.z+er1.z)); mx13=fmaxf(mx13, lrelu(f1.w+er1.w));
            }
            mx00=rmax32(mx00); mx01=rmax32(mx01); mx02=rmax32(mx02); mx03=rmax32(mx03);
            mx10=rmax32(mx10); mx11=rmax32(mx11); mx12=rmax32(mx12); mx13=rmax32(mx13);
            float dn00=0.f,dn01=0.f,dn02=0.f,dn03=0.f,dn10=0.f,dn11=0.f,dn12=0.f,dn13=0.f;
            for (int e = lane; e < dg; e += 32){
                int off = g_esrc[rel][bg_e + e];
                const char* ep = elb + (off >> 4) + t0*16;
                float4 f0 = *(const float4*)ep;
                float4 f1 = *(const float4*)(ep + 16);
                dn00 += __expf(lrelu(f0.x+er0.x)-mx00); dn01 += __expf(lrelu(f0.y+er0.y)-mx01);
                dn02 += __expf(lrelu(f0.z+er0.z)-mx02); dn03 += __expf(lrelu(f0.w+er0.w)-mx03);
                dn10 += __expf(lrelu(f1.x+er1.x)-mx10); dn11 += __expf(lrelu(f1.y+er1.y)-mx11);
                dn12 += __expf(lrelu(f1.z+er1.z)-mx12); dn13 += __expf(lrelu(f1.w+er1.w)-mx13);
            }
            dn00=radd32(dn00); dn01=radd32(dn01); dn02=radd32(dn02); dn03=radd32(dn03);
            dn10=radd32(dn10); dn11=radd32(dn11); dn12=radd32(dn12); dn13=radd32(dn13);

            float dnSel = half ? ((hA==0)?dn10:(hA==1)?dn11:(hA==2)?dn12:dn13)
                               : ((hA==0)?dn00:(hA==1)?dn01:(hA==2)?dn02:dn03);
            mxSel = half ? ((hA==0)?mx10:(hA==1)?mx11:(hA==2)?mx12:mx13)
                         : ((hA==0)?mx00:(hA==1)?mx01:(hA==2)?mx02:mx03);
            float erSel = half ? ((hA==0)?er1.x:(hA==1)?er1.y:(hA==2)?er1.z:er1.w)
                               : ((hA==0)?er0.x:(hA==1)?er0.y:(hA==2)?er0.z:er0.w);
            inv = 1.f / fmaxf(dnSel, 1e-16f);

            ull p0=0ull, p1=0ull;
            for (int e = 0; e < dg; ++e){
                int off = g_esrc[rel][bg_e + e];
                const float* ep = (const float*)(elb + (off >> 4) + (t0+half)*16);
                float a = lrelu(ep[hA] + erSel);
                float wv = __expf(a - mxSel);
                ulonglong2 zA = *(const ulonglong2*)(zbase + off);
                ull w2 = pk(wv, wv);
                p0 = fma2(w2, zA.x, p0);
                p1 = fma2(w2, zA.y, p1);
            }
            ull inv2 = pk(inv, inv);
            m01 = add2(m01, mul2(p0, inv2));
            m23 = add2(m23, mul2(p1, inv2));
        }
    }

    // residual + BN2; lane owns 4 floats at (t0+half, cols 4*l16..+3)
    size_t idxb = (size_t)d*3072 + (t0+half)*256 + l16*16;
    ulonglong2 xv = *(const ulonglong2*)((const char*)x + idxb);
    ull v01 = add2(xv.x, m01);
    ull v23 = add2(xv.y, m23);

    float2 u01 = upk(v01), u23 = upk(v23);
    float s = radd32(u01.x + u01.y + u23.x + u23.y);
    float q = radd32(u01.x*u01.x + u01.y*u01.y + u23.x*u23.x + u23.y*u23.y);
    if (lane == 0){ sms[w] = s; sqs[w] = q; }
    __syncthreads();
    float ts = 0.f, tq = 0.f;
    #pragma unroll
    for (int i = 0; i < 6; i++){ ts += sms[i]; tq += sqs[i]; }
    float mean = ts * (1.f/768.f);
    float var  = tq * (1.f/768.f) - mean*mean;
    float sc   = rsqrtf(var + 1e-5f) * bg[d];
    float sb   = bb[d] - mean*sc;
    ull sc2 = pk(sc, sc), sb2 = pk(sb, sb);

    ulonglong2 xo, ho;
    xo.x = v01; xo.y = v23;
    ho.x = fma2(v01, sc2, sb2);
    ho.y = fma2(v23, sc2, sb2);
    *(ulonglong2*)((char*)g_x2 + idxb) = xo;
    *(ulonglong2*)((char*)g_h  + idxb) = ho;
}

// ---------------- FFN (register-tiled, 512 thr, 128-row tiles) ----------------
#define FF_TILES ((NTc + 127) / 128)   // 938 (last tile has 64 rows)
#define FF_SMEM ((8192 + 8192 + 128 + 64 + 64*132 + 128*132) * 4)
__global__ void ff_kernel(const float* __restrict__ w1, const float* __restrict__ b1,
                          const float* __restrict__ w2, const float* __restrict__ b2,
                          float* __restrict__ out){
    extern __shared__ float sm[];
    float* sW1 = sm;
    float* sW2 = sW1 + 8192;
    float* sB1 = sW2 + 8192;
    float* sB2 = sB1 + 128;
    float* sX  = sB2 + 64;
    float* sG  = sX  + 64*132;

    int tid  = threadIdx.x;
    int w    = tid >> 5;
    int lane = tid & 31;

    for (int i = tid; i < 8192; i += 512) sW1[i] = w1[i];
    for (int i = tid; i < 8192; i += 512) sW2[i] = w2[i];
    if (tid < 128) sB1[tid] = b1[tid];
    else if (tid < 192) sB2[tid-128] = b2[tid-128];
    __syncthreads();

    float b2v0 = sB2[2*lane], b2v1 = sB2[2*lane+1];

    for (int tile = blockIdx.x; tile < FF_TILES; tile += 148){
        size_t base = (size_t)tile * 128 * 64;

        #pragma unroll
        for (int it = 0; it < 16; it++){
            int i = tid + it*512;
            size_t gi = base + i;
            if (gi < (size_t)NTDc){
                int r = i >> 6, k = i & 63;
                sX[k*132 + r] = g_h[gi];
            }
        }
        __syncthreads();

        ull a1[4][4];
        #pragma unroll
        for (int c = 0; c < 4; c++)
            #pragma unroll
            for (int i = 0; i < 4; i++) a1[c][i] = 0ull;

        #pragma unroll 4
        for (int k = 0; k < 64; k++){
            double2 hd0 = *(const double2*)&sX[k*132 + 8*w];
            double2 hd1 = *(const double2*)&sX[k*132 + 8*w + 4];
            ull h01 = __double_as_longlong(hd0.x);
            ull h23 = __double_as_longlong(hd0.y);
            ull h45 = __double_as_longlong(hd1.x);
            ull h67 = __double_as_longlong(hd1.y);
            float4 wv = *(const float4*)&sW1[k*128 + 4*lane];
            ull ws0 = pk(wv.x, wv.x), ws1 = pk(wv.y, wv.y);
            ull ws2 = pk(wv.z, wv.z), ws3 = pk(wv.w, wv.w);
            a1[0][0] = fma2(h01, ws0, a1[0][0]);
            a1[0][1] = fma2(h23, ws0, a1[0][1]);
            a1[0][2] = fma2(h45, ws0, a1[0][2]);
            a1[0][3] = fma2(h67, ws0, a1[0][3]);
            a1[1][0] = fma2(h01, ws1, a1[1][0]);
            a1[1][1] = fma2(h23, ws1, a1[1][1]);
            a1[1][2] = fma2(h45, ws1, a1[1][2]);
            a1[1][3] = fma2(h67, ws1, a1[1][3]);
            a1[2][0] = fma2(h01, ws2, a1[2][0]);
            a1[2][1] = fma2(h23, ws2, a1[2][1]);
            a1[2][2] = fma2(h45, ws2, a1[2][2]);
            a1[2][3] = fma2(h67, ws2, a1[2][3]);
            a1[3][0] = fma2(h01, ws3, a1[3][0]);
            a1[3][1] = fma2(h23, ws3, a1[3][1]);
            a1[3][2] = fma2(h45, ws3, a1[3][2]);
            a1[3][3] = fma2(h67, ws3, a1[3][3]);
        }

        #pragma unroll
        for (int c = 0; c < 4; c++){
            int j = 4*lane + c;
            float bj = sB1[j];
            float g[8];
            #pragma unroll
            for (int i = 0; i < 4; i++){
                float2 f = upk(a1[c][i]);
                float u0 = f.x + bj, u1 = f.y + bj;
                g[2*i]   = 0.5f * u0 * (1.f + erff(u0 * 0.70710678118654752f));
                g[2*i+1] = 0.5f * u1 * (1.f + erff(u1 * 0.70710678118654752f));
            }
            double2 st0, st1;
            st0.x = __longlong_as_double(pk(g[0], g[1]));
            st0.y = __longlong_as_double(pk(g[2], g[3]));
            st1.x = __longlong_as_double(pk(g[4], g[5]));
            st1.y = __longlong_as_double(pk(g[6], g[7]));
            *(double2*)&sG[j*132 + 8*w]     = st0;
            *(double2*)&sG[j*132 + 8*w + 4] = st1;
        }
        __syncthreads();

        ull a2[2][4];
        #pragma unroll
        for (int c = 0; c < 2; c++)
            #pragma unroll
            for (int i = 0; i < 4; i++) a2[c][i] = 0ull;

        #pragma unroll 4
        for (int k = 0; k < 128; k++){
            double2 gd0 = *(const double2*)&sG[k*132 + 8*w];
            double2 gd1 = *(const double2*)&sG[k*132 + 8*w + 4];
            ull g01 = __double_as_longlong(gd0.x);
            ull g23 = __double_as_longlong(gd0.y);
            ull g45 = __double_as_longlong(gd1.x);
            ull g67 = __double_as_longlong(gd1.y);
            ull wv2 = *(const ull*)&sW2[k*64 + 2*lane];
            float2 wf = upk(wv2);
            ull ws0 = pk(wf.x, wf.x), ws1 = pk(wf.y, wf.y);
            a2[0][0] = fma2(g01, ws0, a2[0][0]);
            a2[0][1] = fma2(g23, ws0, a2[0][1]);
            a2[0][2] = fma2(g45, ws0, a2[0][2]);
            a2[0][3] = fma2(g67, ws0, a2[0][3]);
            a2[1][0] = fma2(g01, ws1, a2[1][0]);
            a2[1][1] = fma2(g23, ws1, a2[1][1]);
            a2[1][2] = fma2(g45, ws1, a2[1][2]);
            a2[1][3] = fma2(g67, ws1, a2[1][3]);
        }

        #pragma unroll
        for (int i = 0; i < 4; i++){
            float2 f0 = upk(a2[0][i]);
            float2 f1 = upk(a2[1][i]);
            size_t o = base + (size_t)(8*w + 2*i)*64 + 2*lane;
            if (o < (size_t)NTDc){
                out[o]    = g_x2[o]    + f0.x + b2v0;
                out[o+1]  = g_x2[o+1]  + f1.x + b2v1;
                out[o+64] = g_x2[o+64] + f0.y + b2v0;
                out[o+65] = g_x2[o+65] + f1.y + b2v1;
            }
        }
        __syncthreads();
    }
}

// ---------------- launcher ----------------
extern "C" void kernel_launch(void* const* d_in, const int* in_sizes, int n_in,
                              void* d_out, int out_size){
    const float* x    = (const float*)d_in[0];
    const int*   src1 = (const int*)d_in[1];
    const int*   dst1 = (const int*)d_in[2];
    const int*   src2 = (const int*)d_in[3];
    const int*   dst2 = (const int*)d_in[4];
    const float* W1   = (const float*)d_in[5];
    const float* al1  = (const float*)d_in[6];
    const float* ar1  = (const float*)d_in[7];
    const float* W2   = (const float*)d_in[8];
    const float* al2  = (const float*)d_in[9];
    const float* ar2  = (const float*)d_in[10];
    const float* bn1g = (const float*)d_in[11];
    const float* bn1b = (const float*)d_in[12];
    const float* bn2g = (const float*)d_in[13];
    const float* bn2b = (const float*)d_in[14];
    const float* fw1  = (const float*)d_in[15];
    const float* fb1  = (const float*)d_in[16];
    const float* fw2  = (const float*)d_in[17];
    const float* fb2  = (const float*)d_in[18];
    float* out = (float*)d_out;

    cudaFuncSetAttribute(ff_kernel, cudaFuncAttributeMaxDynamicSharedMemorySize, FF_SMEM);

    csr_hist<<<(2*Ee + 255)/256, 256>>>(dst1, dst2);               // idx 0
    csr_scan<<<1, 1024>>>();                                        // idx 1
    scatter_zel<<<SCAT_BLKS + NTc/48, 256>>>(src1, dst1, src2, dst2,
        x, bn1g, bn1b, W1, al1, ar1, W2, al2, ar2);                 // idx 2
    gat_kernel<<<Nn, 192>>>(x, bn2g, bn2b);                         // idx 3 (profiled)
    ff_kernel<<<148, 512, FF_SMEM>>>(fw1, fb1, fw2, fb2, out);      // idx 4
}

// round 11
// speedup vs baseline: 2.6365x; 1.0078x over previous
#include <cuda_runtime.h>
#include <math.h>

#define Nn   10000
#define Tt   12
#define Ee   100000
#define NTc  (Nn*Tt)        // 120000
#define NTDc (NTc*64)       // 7680000
#define SCAT_BLKS 782       // ceil(2*Ee/256)

typedef unsigned long long ull;

// ---------------- scratch ----------------
__device__ float g_h[NTDc];          // BN2 output (input to FFN)
__device__ float g_z[2][NTDc];       // per-relation projected features
__device__ float g_x2[NTDc];         // residual x + m1 + m2
__device__ float g_el[2][NTc*4];
__device__ float g_er[2][NTc*4];
__device__ int   g_cnt[2*(Nn+1)];    // starts zero; scan re-zeros after reading
__device__ int   g_rowptr[2*(Nn+1)];
__device__ int   g_fill[2*Nn];
__device__ int   g_esrc[2][Ee];      // src node BYTE OFFSETS (src*3072)

// ---------------- f32x2 helpers ----------------
__device__ __forceinline__ ull pk(float a, float b){
    ull r;
    asm("mov.b64 %0, {%1, %2};" : "=l"(r) : "r"(__float_as_uint(a)), "r"(__float_as_uint(b)));
    return r;
}
__device__ __forceinline__ ull fma2(ull a, ull b, ull c){
    ull d;
    asm("fma.rn.f32x2 %0, %1, %2, %3;" : "=l"(d) : "l"(a), "l"(b), "l"(c));
    return d;
}
__device__ __forceinline__ ull mul2(ull a, ull b){
    ull d;
    asm("mul.rn.f32x2 %0, %1, %2;" : "=l"(d) : "l"(a), "l"(b));
    return d;
}
__device__ __forceinline__ ull add2(ull a, ull b){
    ull d;
    asm("add.rn.f32x2 %0, %1, %2;" : "=l"(d) : "l"(a), "l"(b));
    return d;
}
__device__ __forceinline__ float2 upk(ull v){
    unsigned lo, hi;
    asm("mov.b64 {%0, %1}, %2;" : "=r"(lo), "=r"(hi) : "l"(v));
    return make_float2(__uint_as_float(lo), __uint_as_float(hi));
}
// warp-wide reductions via shfl butterfly (no fp32 redux on sm_103)
__device__ __forceinline__ float rmax32(float v){
    #pragma unroll
    for (int o = 16; o; o >>= 1)
        v = fmaxf(v, __shfl_xor_sync(0xffffffffu, v, o));
    return v;
}
__device__ __forceinline__ float radd32(float v){
    #pragma unroll
    for (int o = 16; o; o >>= 1)
        v += __shfl_xor_sync(0xffffffffu, v, o);
    return v;
}
__device__ __forceinline__ float lrelu(float a){
    return (a > 0.f) ? a : 0.2f*a;
}

// ---------------- CSR: histogram ----------------
__global__ void csr_hist(const int* __restrict__ dst1, const int* __restrict__ dst2){
    int e = blockIdx.x * 256 + threadIdx.x;
    if (e < Ee)            atomicAdd(&g_cnt[dst1[e] + 1], 1);
    else if (e < 2*Ee)     atomicAdd(&g_cnt[(Nn+1) + dst2[e-Ee] + 1], 1);
}

// ---------------- CSR: scan (self-zeros g_cnt for next replay) ----------------
__global__ void csr_scan(){
    __shared__ int wsum[32];
    int tid = threadIdx.x, lane = tid & 31, w = tid >> 5;
    for (int rel = 0; rel < 2; rel++){
        int* cnt = g_cnt    + rel*(Nn+1);
        int* rp  = g_rowptr + rel*(Nn+1);
        int* fl  = g_fill   + rel*Nn;
        int base = tid * 10;
        int v[10]; int s = 0;
        #pragma unroll
        for (int i = 0; i < 10; i++){
            int idx = base + i;
            int c = 0;
            if (idx <= Nn){ c = cnt[idx]; cnt[idx] = 0; }
            s += c; v[i] = s;
        }
        int t = s;
        #pragma unroll
        for (int o = 1; o < 32; o <<= 1){
            int u = __shfl_up_sync(0xffffffffu, t, o);
            if (lane >= o) t += u;
        }
        if (lane == 31) wsum[w] = t;
        __syncthreads();
        if (w == 0){
            int ws = wsum[lane];
            #pragma unroll
            for (int o = 1; o < 32; o <<= 1){
                int u = __shfl_up_sync(0xffffffffu, ws, o);
                if (lane >= o) ws += u;
            }
            wsum[lane] = ws;
        }
        __syncthreads();
        int off = ((w > 0) ? wsum[w-1] : 0) + (t - s);
        #pragma unroll
        for (int i = 0; i < 10; i++){
            int idx = base + i;
            if (idx <= Nn){
                int val = off + v[i];
                rp[idx] = val;
                if (idx < Nn) fl[idx] = val;
            }
        }
        __syncthreads();
    }
}

// ---------------- profiler pad: shifts scatter_zel into capture slot 3 -------
__global__ void prof_pad(){}

// ---------------- fused: CSR scatter (blocks 0..781) + BN1/z/el/er (rest) -----
__global__ void scatter_zel(const int* __restrict__ src1, const int* __restrict__ dst1,
                            const int* __restrict__ src2, const int* __restrict__ dst2,
                            const float* __restrict__ x,
                            const float* __restrict__ bg, const float* __restrict__ bb,
                            const float* __restrict__ W1, const float* __restrict__ al1, const float* __restrict__ ar1,
                            const float* __restrict__ W2, const float* __restrict__ al2, const float* __restrict__ ar2){
    if (blockIdx.x < SCAT_BLKS){
        int e = blockIdx.x * 256 + threadIdx.x;
        if (e < Ee){
            int p = atomicAdd(&g_fill[dst1[e]], 1);
            g_esrc[0][p] = src1[e] * 3072;       // z-row byte offset
        } else if (e < 2*Ee){
            int p = atomicAdd(&g_fill[Nn + dst2[e-Ee]], 1);
            g_esrc[1][p] = src2[e-Ee] * 3072;
        }
        return;
    }

    __shared__ __align__(16) float sh[64*52];
    __shared__ __align__(16) float sW[64*64];
    __shared__ __align__(16) float zred[64*52];
    __shared__ float red[8];
    __shared__ float nsc[4], nsh[4];

    int tid  = threadIdx.x;
    int lane = tid & 31;
    int w    = tid >> 5;
    int wcol = w & 3;
    int khalf= w >> 2;
    int rg   = lane >> 3;
    int cg   = lane & 7;
    int r0   = rg * 12;
    int c0   = wcol*16 + 2*cg;
    int bz   = blockIdx.x - SCAT_BLKS;
    int nt0  = bz * 48;
    int nd0  = bz * 4;

    if (tid < 8) red[tid] = 0.f;
    __syncthreads();

    float ls[4] = {0,0,0,0}, lq[4] = {0,0,0,0};
    #pragma unroll
    for (int it = 0; it < 12; it++){
        int i = tid + it*256;
        float v = x[(size_t)nt0*64 + i];
        int row = i >> 6, d = i & 63;
        sh[d*52 + row] = v;
        int nl = row / 12;
        ls[nl] += v; lq[nl] += v*v;
    }
    #pragma unroll
    for (int nl = 0; nl < 4; nl++){
        ls[nl] = radd32(ls[nl]);
        lq[nl] = radd32(lq[nl]);
    }
    if (lane == 0){
        #pragma unroll
        for (int nl = 0; nl < 4; nl++){
            if (ls[nl] != 0.f || lq[nl] != 0.f){
                atomicAdd(&red[2*nl],   ls[nl]);
                atomicAdd(&red[2*nl+1], lq[nl]);
            }
        }
    }
    __syncthreads();
    if (tid < 4){
        float mean = red[2*tid] * (1.f/768.f);
        float var  = red[2*tid+1] * (1.f/768.f) - mean*mean;
        float sc   = rsqrtf(var + 1e-5f) * bg[nd0 + tid];
        nsc[tid] = sc;
        nsh[tid] = bb[nd0 + tid] - mean*sc;
    }
    __syncthreads();
    #pragma unroll
    for (int it = 0; it < 12; it++){
        int i = tid + it*256;
        int row = i >> 6, d = i & 63;
        int nl = row / 12;
        sh[d*52 + row] = sh[d*52 + row]*nsc[nl] + nsh[nl];
    }
    __syncthreads();

    for (int rel = 0; rel < 2; rel++){
        const float* W  = rel ? W2  : W1;
        const float* al = rel ? al2 : al1;
        const float* ar = rel ? ar2 : ar1;
        for (int i = tid; i < 4096; i += 256) sW[i] = W[i];
        __syncthreads();

        ull acc[2][6];
        #pragma unroll
        for (int c = 0; c < 2; c++)
            #pragma unroll
            for (int i = 0; i < 6; i++) acc[c][i] = 0ull;

        int kb = khalf * 32;
        #pragma unroll 4
        for (int kk = 0; kk < 32; kk++){
            int k = kb + kk;
            ull w2v = *(const ull*)&sW[k*64 + c0];
            float2 wf = upk(w2v);
            ull ws0 = pk(wf.x, wf.x);
            ull ws1 = pk(wf.y, wf.y);
            const float4* hb = (const float4*)&sh[k*52 + r0];
            float4 hA = hb[0], hB = hb[1], hC = hb[2];
            ull h2[6];
            h2[0] = pk(hA.x, hA.y); h2[1] = pk(hA.z, hA.w);
            h2[2] = pk(hB.x, hB.y); h2[3] = pk(hB.z, hB.w);
            h2[4] = pk(hC.x, hC.y); h2[5] = pk(hC.z, hC.w);
            #pragma unroll
            for (int i = 0; i < 6; i++){
                acc[0][i] = fma2(h2[i], ws0, acc[0][i]);
                acc[1][i] = fma2(h2[i], ws1, acc[1][i]);
            }
        }

        if (khalf == 1){
            #pragma unroll
            for (int c = 0; c < 2; c++)
                #pragma unroll
                for (int i = 0; i < 6; i++)
                    *(ull*)&zred[(c0+c)*52 + r0 + 2*i] = acc[c][i];
        }
        __syncthreads();
        if (khalf == 0){
            #pragma unroll
            for (int c = 0; c < 2; c++)
                #pragma unroll
                for (int i = 0; i < 6; i++)
                    acc[c][i] = add2(acc[c][i], *(const ull*)&zred[(c0+c)*52 + r0 + 2*i]);
            #pragma unroll
            for (int c = 0; c < 2; c++)
                #pragma unroll
                for (int i = 0; i < 6; i++)
                    *(ull*)&zred[(c0+c)*52 + r0 + 2*i] = acc[c][i];

            ull al0 = pk(al[c0], al[c0]),   al1v = pk(al[c0+1], al[c0+1]);
            ull ar0 = pk(ar[c0], ar[c0]),   ar1v = pk(ar[c0+1], ar[c0+1]);
            ull pl[6], pr[6];
            #pragma unroll
            for (int i = 0; i < 6; i++){
                pl[i] = fma2(acc[1][i], al1v, mul2(acc[0][i], al0));
                pr[i] = fma2(acc[1][i], ar1v, mul2(acc[0][i], ar0));
            }
            #pragma unroll
            for (int o = 1; o < 8; o <<= 1){
                #pragma unroll
                for (int i = 0; i < 6; i++){
                    pl[i] = add2(pl[i], __shfl_xor_sync(0xffffffffu, pl[i], o));
                    pr[i] = add2(pr[i], __shfl_xor_sync(0xffffffffu, pr[i], o));
                }
            }
            if (cg == 0){
                #pragma unroll
                for (int i = 0; i < 6; i++){
                    float2 fl = upk(pl[i]);
                    float2 fr = upk(pr[i]);
                    int nt = nt0 + r0 + 2*i;
                    g_el[rel][nt*4 + wcol]     = fl.x;
                    g_el[rel][(nt+1)*4 + wcol] = fl.y;
                    g_er[rel][nt*4 + wcol]     = fr.x;
                    g_er[rel][(nt+1)*4 + wcol] = fr.y;
                }
            }
        }
        __syncthreads();
        #pragma unroll
        for (int it = 0; it < 12; it++){
            int i = tid + it*256;
            int row = i >> 6, d = i & 63;
            g_z[rel][(size_t)nt0*64 + i] = zred[d*52 + row];
        }
        __syncthreads();
    }
}

// ---------------- GAT fallback for deg>32 (cold; noinline to cap regs) -------
struct U2 { ull a, b; };
__device__ __noinline__ U2 gat_fallback(const int* __restrict__ esrc, int bg_e, int dg,
                                        int t0, int half, int hA,
                                        const char* elb, const char* zbase,
                                        float4 er0, float4 er1){
    float mx00=-1e30f,mx01=-1e30f,mx02=-1e30f,mx03=-1e30f;
    float mx10=-1e30f,mx11=-1e30f,mx12=-1e30f,mx13=-1e30f;
    int lane = threadIdx.x & 31;
    for (int e = lane; e < dg; e += 32){
        int off = esrc[bg_e + e];
        const char* ep = elb + (off >> 4) + t0*16;
        float4 f0 = *(const float4*)ep;
        float4 f1 = *(const float4*)(ep + 16);
        mx00=fmaxf(mx00, lrelu(f0.x+er0.x)); mx01=fmaxf(mx01, lrelu(f0.y+er0.y));
        mx02=fmaxf(mx02, lrelu(f0.z+er0.z)); mx03=fmaxf(mx03, lrelu(f0.w+er0.w));
        mx10=fmaxf(mx10, lrelu(f1.x+er1.x)); mx11=fmaxf(mx11, lrelu(f1.y+er1.y));
        mx12=fmaxf(mx12, lrelu(f1.z+er1.z)); mx13=fmaxf(mx13, lrelu(f1.w+er1.w));
    }
    mx00=rmax32(mx00); mx01=rmax32(mx01); mx02=rmax32(mx02); mx03=rmax32(mx03);
    mx10=rmax32(mx10); mx11=rmax32(mx11); mx12=rmax32(mx12); mx13=rmax32(mx13);
    float dn00=0.f,dn01=0.f,dn02=0.f,dn03=0.f,dn10=0.f,dn11=0.f,dn12=0.f,dn13=0.f;
    for (int e = lane; e < dg; e += 32){
        int off = esrc[bg_e + e];
        const char* ep = elb + (off >> 4) + t0*16;
        float4 f0 = *(const float4*)ep;
        float4 f1 = *(const float4*)(ep + 16);
        dn00 += __expf(lrelu(f0.x+er0.x)-mx00); dn01 += __expf(lrelu(f0.y+er0.y)-mx01);
        dn02 += __expf(lrelu(f0.z+er0.z)-mx02); dn03 += __expf(lrelu(f0.w+er0.w)-mx03);
        dn10 += __expf(lrelu(f1.x+er1.x)-mx10); dn11 += __expf(lrelu(f1.y+er1.y)-mx11);
        dn12 += __expf(lrelu(f1.z+er1.z)-mx12); dn13 += __expf(lrelu(f1.w+er1.w)-mx13);
    }
    dn00=radd32(dn00); dn01=radd32(dn01); dn02=radd32(dn02); dn03=radd32(dn03);
    dn10=radd32(dn10); dn11=radd32(dn11); dn12=radd32(dn12); dn13=radd32(dn13);

    float dnSel = half ? ((hA==0)?dn10:(hA==1)?dn11:(hA==2)?dn12:dn13)
                       : ((hA==0)?dn00:(hA==1)?dn01:(hA==2)?dn02:dn03);
    float mxSel = half ? ((hA==0)?mx10:(hA==1)?mx11:(hA==2)?mx12:mx13)
                       : ((hA==0)?mx00:(hA==1)?mx01:(hA==2)?mx02:mx03);
    float erSel = half ? ((hA==0)?er1.x:(hA==1)?er1.y:(hA==2)?er1.z:er1.w)
                       : ((hA==0)?er0.x:(hA==1)?er0.y:(hA==2)?er0.z:er0.w);
    float inv = 1.f / fmaxf(dnSel, 1e-16f);

    ull p0=0ull, p1=0ull;
    for (int e = 0; e < dg; ++e){
        int off = esrc[bg_e + e];
        const float* ep = (const float*)(elb + (off >> 4) + (t0+half)*16);
        float a = lrelu(ep[hA] + erSel);
        float wv = __expf(a - mxSel);
        ulonglong2 zA = *(const ulonglong2*)(zbase + off);
        ull w2 = pk(wv, wv);
        p0 = fma2(w2, zA.x, p0);
        p1 = fma2(w2, zA.y, p1);
    }
    ull inv2 = pk(inv, inv);
    U2 r; r.a = mul2(p0, inv2); r.b = mul2(p1, inv2);
    return r;
}

// ---------------- fused GAT (both rels) + residual + BN2 ----------------
// block = node d, 6 warps; warp w handles t = 2w (half 0) and 2w+1 (half 1).
__global__ void __launch_bounds__(192, 7) gat_kernel(const float* __restrict__ x,
                           const float* __restrict__ bg, const float* __restrict__ bb){
    __shared__ float s_w[6][32*8];   // [warp][edge*8 + half*4 + head]
    __shared__ float sms[6], sqs[6];

    const unsigned FULL = 0xffffffffu;
    int d    = blockIdx.x;
    int w    = threadIdx.x >> 5;
    int lane = threadIdx.x & 31;
    int half = lane >> 4;
    int l16  = lane & 15;
    int hA   = l16 >> 2;
    int t0   = 2*w;

    ull m01 = 0ull, m23 = 0ull;

    #pragma unroll
    for (int rel = 0; rel < 2; rel++){
        int bg_e = g_rowptr[rel*(Nn+1) + d];
        int dg   = g_rowptr[rel*(Nn+1) + d + 1] - bg_e;
        const char* elb   = (const char*)g_el[rel];
        const char* zbase = (const char*)g_z[rel] + (t0+half)*256 + l16*16;
        float4 er0 = *(const float4*)&g_er[rel][d*48 + t0*4];
        float4 er1 = *(const float4*)&g_er[rel][d*48 + t0*4 + 4];

        if (dg <= 32){
            // ---- phase 1: lane = edge ----
            int off = 0;
            float a00=-1e30f,a01=-1e30f,a02=-1e30f,a03=-1e30f;
            float a10=-1e30f,a11=-1e30f,a12=-1e30f,a13=-1e30f;
            if (lane < dg){
                off = g_esrc[rel][bg_e + lane];
                const char* ep = elb + (off >> 4) + t0*16;
                float4 f0 = *(const float4*)ep;
                float4 f1 = *(const float4*)(ep + 16);
                a00 = lrelu(f0.x + er0.x); a01 = lrelu(f0.y + er0.y);
                a02 = lrelu(f0.z + er0.z); a03 = lrelu(f0.w + er0.w);
                a10 = lrelu(f1.x + er1.x); a11 = lrelu(f1.y + er1.y);
                a12 = lrelu(f1.z + er1.z); a13 = lrelu(f1.w + er1.w);
            }
            float mx00=rmax32(a00), mx01=rmax32(a01), mx02=rmax32(a02), mx03=rmax32(a03);
            float mx10=rmax32(a10), mx11=rmax32(a11), mx12=rmax32(a12), mx13=rmax32(a13);
            float w00=0.f,w01=0.f,w02=0.f,w03=0.f,w10=0.f,w11=0.f,w12=0.f,w13=0.f;
            if (lane < dg){
                w00=__expf(a00-mx00); w01=__expf(a01-mx01);
                w02=__expf(a02-mx02); w03=__expf(a03-mx03);
                w10=__expf(a10-mx10); w11=__expf(a11-mx11);
                w12=__expf(a12-mx12); w13=__expf(a13-mx13);
                *(float4*)&s_w[w][lane*8]     = make_float4(w00,w01,w02,w03);
                *(float4*)&s_w[w][lane*8 + 4] = make_float4(w10,w11,w12,w13);
            }
            float dn00=radd32(w00), dn01=radd32(w01), dn02=radd32(w02), dn03=radd32(w03);
            float dn10=radd32(w10), dn11=radd32(w11), dn12=radd32(w12), dn13=radd32(w13);

            float dnSel = half ? ((hA==0)?dn10:(hA==1)?dn11:(hA==2)?dn12:dn13)
                               : ((hA==0)?dn00:(hA==1)?dn01:(hA==2)?dn02:dn03);
            float inv = 1.f / fmaxf(dnSel, 1e-16f);

            __syncwarp();

            // ---- phase 2: edges serial, dual accumulators ----
            ull p0=0ull, p1=0ull, q0=0ull, q1=0ull;
            const float* wrow = &s_w[w][half*4 + hA];
            int e = 0;
            for (; e + 1 < dg; e += 2){
                int ofA = __shfl_sync(FULL, off, e);
                int ofB = __shfl_sync(FULL, off, e+1);
                float wA = wrow[e*8];
                float wB = wrow[e*8 + 8];
                ulonglong2 zA = *(const ulonglong2*)(zbase + ofA);
                ulonglong2 zB = *(const ulonglong2*)(zbase + ofB);
                ull wA2 = pk(wA, wA), wB2 = pk(wB, wB);
                p0 = fma2(wA2, zA.x, p0);
                p1 = fma2(wA2, zA.y, p1);
                q0 = fma2(wB2, zB.x, q0);
                q1 = fma2(wB2, zB.y, q1);
            }
            if (e < dg){
                int ofA = __shfl_sync(FULL, off, e);
                float wA = wrow[e*8];
                ulonglong2 zA = *(const ulonglong2*)(zbase + ofA);
                ull wA2 = pk(wA, wA);
                p0 = fma2(wA2, zA.x, p0);
                p1 = fma2(wA2, zA.y, p1);
            }
            ull inv2 = pk(inv, inv);
            m01 = add2(m01, mul2(add2(p0, q0), inv2));
            m23 = add2(m23, mul2(add2(p1, q1), inv2));
        } else {
            U2 r = gat_fallback(g_esrc[rel], bg_e, dg, t0, half, hA, elb, zbase, er0, er1);
            m01 = add2(m01, r.a);
            m23 = add2(m23, r.b);
        }
    }

    // residual + BN2; lane owns 4 floats at (t0+half, cols 4*l16..+3)
    size_t idxb = (size_t)d*3072 + (t0+half)*256 + l16*16;
    ulonglong2 xv = *(const ulonglong2*)((const char*)x + idxb);
    ull v01 = add2(xv.x, m01);
    ull v23 = add2(xv.y, m23);

    float2 u01 = upk(v01), u23 = upk(v23);
    float s = radd32(u01.x + u01.y + u23.x + u23.y);
    float q = radd32(u01.x*u01.x + u01.y*u01.y + u23.x*u23.x + u23.y*u23.y);
    if (lane == 0){ sms[w] = s; sqs[w] = q; }
    __syncthreads();
    float ts = 0.f, tq = 0.f;
    #pragma unroll
    for (int i = 0; i < 6; i++){ ts += sms[i]; tq += sqs[i]; }
    float mean = ts * (1.f/768.f);
    float var  = tq * (1.f/768.f) - mean*mean;
    float sc   = rsqrtf(var + 1e-5f) * bg[d];
    float sb   = bb[d] - mean*sc;
    ull sc2 = pk(sc, sc), sb2 = pk(sb, sb);

    ulonglong2 xo, ho;
    xo.x = v01; xo.y = v23;
    ho.x = fma2(v01, sc2, sb2);
    ho.y = fma2(v23, sc2, sb2);
    *(ulonglong2*)((char*)g_x2 + idxb) = xo;
    *(ulonglong2*)((char*)g_h  + idxb) = ho;
}

// ---------------- FFN (register-tiled, 512 thr, 128-row tiles) ----------------
#define FF_TILES ((NTc + 127) / 128)   // 938 (last tile has 64 rows)
#define FF_SMEM ((8192 + 8192 + 128 + 64 + 64*132 + 128*132) * 4)
__global__ void ff_kernel(const float* __restrict__ w1, const float* __restrict__ b1,
                          const float* __restrict__ w2, const float* __restrict__ b2,
                          float* __restrict__ out){
    extern __shared__ float sm[];
    float* sW1 = sm;
    float* sW2 = sW1 + 8192;
    float* sB1 = sW2 + 8192;
    float* sB2 = sB1 + 128;
    float* sX  = sB2 + 64;
    float* sG  = sX  + 64*132;

    int tid  = threadIdx.x;
    int w    = tid >> 5;
    int lane = tid & 31;

    for (int i = tid; i < 8192; i += 512) sW1[i] = w1[i];
    for (int i = tid; i < 8192; i += 512) sW2[i] = w2[i];
    if (tid < 128) sB1[tid] = b1[tid];
    else if (tid < 192) sB2[tid-128] = b2[tid-128];
    __syncthreads();

    float b2v0 = sB2[2*lane], b2v1 = sB2[2*lane+1];

    for (int tile = blockIdx.x; tile < FF_TILES; tile += 148){
        size_t base = (size_t)tile * 128 * 64;

        #pragma unroll
        for (int it = 0; it < 16; it++){
            int i = tid + it*512;
            size_t gi = base + i;
            if (gi < (size_t)NTDc){
                int r = i >> 6, k = i & 63;
                sX[k*132 + r] = g_h[gi];
            }
        }
        __syncthreads();

        ull a1[4][4];
        #pragma unroll
        for (int c = 0; c < 4; c++)
            #pragma unroll
            for (int i = 0; i < 4; i++) a1[c][i] = 0ull;

        #pragma unroll 4
        for (int k = 0; k < 64; k++){
            double2 hd0 = *(const double2*)&sX[k*132 + 8*w];
            double2 hd1 = *(const double2*)&sX[k*132 + 8*w + 4];
            ull h01 = __double_as_longlong(hd0.x);
            ull h23 = __double_as_longlong(hd0.y);
            ull h45 = __double_as_longlong(hd1.x);
            ull h67 = __double_as_longlong(hd1.y);
            float4 wv = *(const float4*)&sW1[k*128 + 4*lane];
            ull ws0 = pk(wv.x, wv.x), ws1 = pk(wv.y, wv.y);
            ull ws2 = pk(wv.z, wv.z), ws3 = pk(wv.w, wv.w);
            a1[0][0] = fma2(h01, ws0, a1[0][0]);
            a1[0][1] = fma2(h23, ws0, a1[0][1]);
            a1[0][2] = fma2(h45, ws0, a1[0][2]);
            a1[0][3] = fma2(h67, ws0, a1[0][3]);
            a1[1][0] = fma2(h01, ws1, a1[1][0]);
            a1[1][1] = fma2(h23, ws1, a1[1][1]);
            a1[1][2] = fma2(h45, ws1, a1[1][2]);
            a1[1][3] = fma2(h67, ws1, a1[1][3]);
            a1[2][0] = fma2(h01, ws2, a1[2][0]);
            a1[2][1] = fma2(h23, ws2, a1[2][1]);
            a1[2][2] = fma2(h45, ws2, a1[2][2]);
            a1[2][3] = fma2(h67, ws2, a1[2][3]);
            a1[3][0] = fma2(h01, ws3, a1[3][0]);
            a1[3][1] = fma2(h23, ws3, a1[3][1]);
            a1[3][2] = fma2(h45, ws3, a1[3][2]);
            a1[3][3] = fma2(h67, ws3, a1[3][3]);
        }

        #pragma unroll
        for (int c = 0; c < 4; c++){
            int j = 4*lane + c;
            float bj = sB1[j];
            float g[8];
            #pragma unroll
            for (int i = 0; i < 4; i++){
                float2 f = upk(a1[c][i]);
                float u0 = f.x + bj, u1 = f.y + bj;
                g[2*i]   = 0.5f * u0 * (1.f + erff(u0 * 0.70710678118654752f));
                g[2*i+1] = 0.5f * u1 * (1.f + erff(u1 * 0.70710678118654752f));
            }
            double2 st0, st1;
            st0.x = __longlong_as_double(pk(g[0], g[1]));
            st0.y = __longlong_as_double(pk(g[2], g[3]));
            st1.x = __longlong_as_double(pk(g[4], g[5]));
            st1.y = __longlong_as_double(pk(g[6], g[7]));
            *(double2*)&sG[j*132 + 8*w]     = st0;
            *(double2*)&sG[j*132 + 8*w + 4] = st1;
        }
        __syncthreads();

        ull a2[2][4];
        #pragma unroll
        for (int c = 0; c < 2; c++)
            #pragma unroll
            for (int i = 0; i < 4; i++) a2[c][i] = 0ull;

        #pragma unroll 4
        for (int k = 0; k < 128; k++){
            double2 gd0 = *(const double2*)&sG[k*132 + 8*w];
            double2 gd1 = *(const double2*)&sG[k*132 + 8*w + 4];
            ull g01 = __double_as_longlong(gd0.x);
            ull g23 = __double_as_longlong(gd0.y);
            ull g45 = __double_as_longlong(gd1.x);
            ull g67 = __double_as_longlong(gd1.y);
            ull wv2 = *(const ull*)&sW2[k*64 + 2*lane];
            float2 wf = upk(wv2);
            ull ws0 = pk(wf.x, wf.x), ws1 = pk(wf.y, wf.y);
            a2[0][0] = fma2(g01, ws0, a2[0][0]);
            a2[0][1] = fma2(g23, ws0, a2[0][1]);
            a2[0][2] = fma2(g45, ws0, a2[0][2]);
            a2[0][3] = fma2(g67, ws0, a2[0][3]);
            a2[1][0] = fma2(g01, ws1, a2[1][0]);
            a2[1][1] = fma2(g23, ws1, a2[1][1]);
            a2[1][2] = fma2(g45, ws1, a2[1][2]);
            a2[1][3] = fma2(g67, ws1, a2[1][3]);
        }

        #pragma unroll
        for (int i = 0; i < 4; i++){
            float2 f0 = upk(a2[0][i]);
            float2 f1 = upk(a2[1][i]);
            size_t o = base + (size_t)(8*w + 2*i)*64 + 2*lane;
            if (o < (size_t)NTDc){
                out[o]    = g_x2[o]    + f0.x + b2v0;
                out[o+1]  = g_x2[o+1]  + f1.x + b2v1;
                out[o+64] = g_x2[o+64] + f0.y + b2v0;
                out[o+65] = g_x2[o+65] + f1.y + b2v1;
            }
        }
        __syncthreads();
    }
}

// ---------------- launcher ----------------
extern "C" void kernel_launch(void* const* d_in, const int* in_sizes, int n_in,
                              void* d_out, int out_size){
    const float* x    = (const float*)d_in[0];
    const int*   src1 = (const int*)d_in[1];
    const int*   dst1 = (const int*)d_in[2];
    const int*   src2 = (const int*)d_in[3];
    const int*   dst2 = (const int*)d_in[4];
    const float* W1   = (const float*)d_in[5];
    const float* al1  = (const float*)d_in[6];
    const float* ar1  = (const float*)d_in[7];
    const float* W2   = (const float*)d_in[8];
    const float* al2  = (const float*)d_in[9];
    const float* ar2  = (const float*)d_in[10];
    const float* bn1g = (const float*)d_in[11];
    const float* bn1b = (const float*)d_in[12];
    const float* bn2g = (const float*)d_in[13];
    const float* bn2b = (const float*)d_in[14];
    const float* fw1  = (const float*)d_in[15];
    const float* fb1  = (const float*)d_in[16];
    const float* fw2  = (const float*)d_in[17];
    const float* fb2  = (const float*)d_in[18];
    float* out = (float*)d_out;

    cudaFuncSetAttribute(ff_kernel, cudaFuncAttributeMaxDynamicSharedMemorySize, FF_SMEM);

    csr_hist<<<(2*Ee + 255)/256, 256>>>(dst1, dst2);               // idx 0
    csr_scan<<<1, 1024>>>();                                        // idx 1
    prof_pad<<<1, 32>>>();                                          // idx 2 (pad)
    scatter_zel<<<SCAT_BLKS + NTc/48, 256>>>(src1, dst1, src2, dst2,
        x, bn1g, bn1b, W1, al1, ar1, W2, al2, ar2);                 // idx 3 (profiled)
    gat_kernel<<<Nn, 192>>>(x, bn2g, bn2b);                         // idx 4
    ff_kernel<<<148, 512, FF_SMEM>>>(fw1, fb1, fw2, fb2, out);      // idx 5
}

// round 12
// speedup vs baseline: 2.6534x; 1.0064x over previous
#include <cuda_runtime.h>
#include <math.h>

#define Nn   10000
#define Tt   12
#define Ee   100000
#define NTc  (Nn*Tt)        // 120000
#define NTDc (NTc*64)       // 7680000
#define SCAT_BLKS 782       // ceil(2*Ee/256)

typedef unsigned long long ull;

// ---------------- scratch ----------------
__device__ float g_h[NTDc];          // BN2 output (input to FFN)
__device__ float g_z[2][NTDc];       // per-relation projected features
__device__ float g_x2[NTDc];         // residual x + m1 + m2
__device__ float g_el[2][NTc*4];
__device__ float g_er[2][NTc*4];
__device__ int   g_cnt[2*(Nn+1)];    // starts zero; scan re-zeros after reading
__device__ int   g_rowptr[2*(Nn+1)];
__device__ int   g_fill[2*Nn];
__device__ int   g_esrc[2][Ee];      // src node BYTE OFFSETS (src*3072)

// ---------------- f32x2 helpers ----------------
__device__ __forceinline__ ull pk(float a, float b){
    ull r;
    asm("mov.b64 %0, {%1, %2};" : "=l"(r) : "r"(__float_as_uint(a)), "r"(__float_as_uint(b)));
    return r;
}
__device__ __forceinline__ ull fma2(ull a, ull b, ull c){
    ull d;
    asm("fma.rn.f32x2 %0, %1, %2, %3;" : "=l"(d) : "l"(a), "l"(b), "l"(c));
    return d;
}
__device__ __forceinline__ ull mul2(ull a, ull b){
    ull d;
    asm("mul.rn.f32x2 %0, %1, %2;" : "=l"(d) : "l"(a), "l"(b));
    return d;
}
__device__ __forceinline__ ull add2(ull a, ull b){
    ull d;
    asm("add.rn.f32x2 %0, %1, %2;" : "=l"(d) : "l"(a), "l"(b));
    return d;
}
__device__ __forceinline__ float2 upk(ull v){
    unsigned lo, hi;
    asm("mov.b64 {%0, %1}, %2;" : "=r"(lo), "=r"(hi) : "l"(v));
    return make_float2(__uint_as_float(lo), __uint_as_float(hi));
}
// warp-wide reductions via shfl butterfly (no fp32 redux on sm_103)
__device__ __forceinline__ float rmax32(float v){
    #pragma unroll
    for (int o = 16; o; o >>= 1)
        v = fmaxf(v, __shfl_xor_sync(0xffffffffu, v, o));
    return v;
}
__device__ __forceinline__ float radd32(float v){
    #pragma unroll
    for (int o = 16; o; o >>= 1)
        v += __shfl_xor_sync(0xffffffffu, v, o);
    return v;
}
__device__ __forceinline__ float lrelu(float a){
    return (a > 0.f) ? a : 0.2f*a;
}
// XOR swizzle: logical (d, r) -> physical float index (stride 64)
#define ZI(d, r) ((d)*64 + ((r) ^ (4*((d)&15))))

// ---------------- CSR: histogram ----------------
__global__ void csr_hist(const int* __restrict__ dst1, const int* __restrict__ dst2){
    int e = blockIdx.x * 256 + threadIdx.x;
    if (e < Ee)            atomicAdd(&g_cnt[dst1[e] + 1], 1);
    else if (e < 2*Ee)     atomicAdd(&g_cnt[(Nn+1) + dst2[e-Ee] + 1], 1);
}

// ---------------- CSR: scan (self-zeros g_cnt for next replay) ----------------
__global__ void csr_scan(){
    __shared__ int wsum[32];
    int tid = threadIdx.x, lane = tid & 31, w = tid >> 5;
    for (int rel = 0; rel < 2; rel++){
        int* cnt = g_cnt    + rel*(Nn+1);
        int* rp  = g_rowptr + rel*(Nn+1);
        int* fl  = g_fill   + rel*Nn;
        int base = tid * 10;
        int v[10]; int s = 0;
        #pragma unroll
        for (int i = 0; i < 10; i++){
            int idx = base + i;
            int c = 0;
            if (idx <= Nn){ c = cnt[idx]; cnt[idx] = 0; }
            s += c; v[i] = s;
        }
        int t = s;
        #pragma unroll
        for (int o = 1; o < 32; o <<= 1){
            int u = __shfl_up_sync(0xffffffffu, t, o);
            if (lane >= o) t += u;
        }
        if (lane == 31) wsum[w] = t;
        __syncthreads();
        if (w == 0){
            int ws = wsum[lane];
            #pragma unroll
            for (int o = 1; o < 32; o <<= 1){
                int u = __shfl_up_sync(0xffffffffu, ws, o);
                if (lane >= o) ws += u;
            }
            wsum[lane] = ws;
        }
        __syncthreads();
        int off = ((w > 0) ? wsum[w-1] : 0) + (t - s);
        #pragma unroll
        for (int i = 0; i < 10; i++){
            int idx = base + i;
            if (idx <= Nn){
                int val = off + v[i];
                rp[idx] = val;
                if (idx < Nn) fl[idx] = val;
            }
        }
        __syncthreads();
    }
}

// ---------------- profiler pad: shifts scatter_zel into capture slot 3 -------
__global__ void prof_pad(){}

// ---------------- fused: CSR scatter (blocks 0..781) + BN1/z/el/er (rest) -----
// BN1 is folded algebraically: z = sc_node*(x@W) + shift_node*colsum(W).
__global__ void __launch_bounds__(256, 4)
scatter_zel(const int* __restrict__ src1, const int* __restrict__ dst1,
            const int* __restrict__ src2, const int* __restrict__ dst2,
            const float* __restrict__ x,
            const float* __restrict__ bg, const float* __restrict__ bb,
            const float* __restrict__ W1, const float* __restrict__ al1, const float* __restrict__ ar1,
            const float* __restrict__ W2, const float* __restrict__ al2, const float* __restrict__ ar2){
    if (blockIdx.x < SCAT_BLKS){
        int e = blockIdx.x * 256 + threadIdx.x;
        if (e < Ee){
            int p = atomicAdd(&g_fill[dst1[e]], 1);
            g_esrc[0][p] = src1[e] * 3072;       // z-row byte offset
        } else if (e < 2*Ee){
            int p = atomicAdd(&g_fill[Nn + dst2[e-Ee]], 1);
            g_esrc[1][p] = src2[e-Ee] * 3072;
        }
        return;
    }

    __shared__ __align__(16) float sh[64*64];    // raw x, [d][row] swizzled
    __shared__ __align__(16) float sW[64*64];    // [k][c]
    __shared__ __align__(16) float zred[64*64];  // [c][row] swizzled
    __shared__ float red[8];
    __shared__ float nsc[4], nsh[4];
    __shared__ float csum[2][64];

    int tid  = threadIdx.x;
    int lane = tid & 31;
    int w    = tid >> 5;
    int wcol = w & 3;
    int khalf= w >> 2;
    int rg   = lane >> 3;
    int cg   = lane & 7;
    int r0   = rg * 12;
    int c0   = wcol*16 + 2*cg;
    int bz   = blockIdx.x - SCAT_BLKS;
    int nt0  = bz * 48;
    int nd0  = bz * 4;
    int dcol = tid & 63;      // staging column (fixed per thread)
    int rbas = tid >> 6;      // staging row base

    if (tid < 8) red[tid] = 0.f;
    if (tid < 64){ csum[0][tid] = 0.f; csum[1][tid] = 0.f; }
    else if (tid < 128){ csum[0][tid-64] = 0.f; }   // (harmless dup-zero guard)
    __syncthreads();
    if (tid < 64) csum[1][tid] = 0.f;   // ensure both zeroed (idempotent)

    // single-pass staging: read raw x, accumulate BN stats, store swizzled
    float ls[4] = {0,0,0,0}, lq[4] = {0,0,0,0};
    #pragma unroll
    for (int it = 0; it < 12; it++){
        float t = x[(size_t)nt0*64 + tid + it*256];
        int row = rbas + it*4;
        sh[ZI(dcol, row)] = t;
        int nl = row / 12;
        ls[nl] += t; lq[nl] += t*t;
    }
    #pragma unroll
    for (int nl = 0; nl < 4; nl++){
        ls[nl] = radd32(ls[nl]);
        lq[nl] = radd32(lq[nl]);
    }
    if (lane == 0){
        #pragma unroll
        for (int nl = 0; nl < 4; nl++){
            if (ls[nl] != 0.f || lq[nl] != 0.f){
                atomicAdd(&red[2*nl],   ls[nl]);
                atomicAdd(&red[2*nl+1], lq[nl]);
            }
        }
    }
    __syncthreads();
    if (tid < 4){
        float mean = red[2*tid] * (1.f/768.f);
        float var  = red[2*tid+1] * (1.f/768.f) - mean*mean;
        float sc   = rsqrtf(var + 1e-5f) * bg[nd0 + tid];
        nsc[tid] = sc;
        nsh[tid] = bb[nd0 + tid] - mean*sc;
    }
    __syncthreads();

    for (int rel = 0; rel < 2; rel++){
        const float* W  = rel ? W2  : W1;
        const float* al = rel ? al2 : al1;
        const float* ar = rel ? ar2 : ar1;
        for (int i = tid; i < 4096; i += 256) sW[i] = W[i];
        __syncthreads();

        // column sums of W (for folded BN shift term)
        {
            float cs = 0.f;
            int q = tid >> 6;
            #pragma unroll
            for (int j = 0; j < 16; j++)
                cs += sW[(q*16 + j)*64 + dcol];
            atomicAdd(&csum[rel][dcol], cs);
        }

        ull acc[2][6];
        #pragma unroll
        for (int c = 0; c < 2; c++)
            #pragma unroll
            for (int i = 0; i < 6; i++) acc[c][i] = 0ull;

        int kb = khalf * 32;
        #pragma unroll 4
        for (int kk = 0; kk < 32; kk++){
            int k = kb + kk;
            ull w2v = *(const ull*)&sW[k*64 + c0];
            float2 wf = upk(w2v);
            ull ws0 = pk(wf.x, wf.x);
            ull ws1 = pk(wf.y, wf.y);
            int xk = 4*(k & 15);
            const float* shk = &sh[k*64];
            float4 hA = *(const float4*)&shk[(r0)     ^ xk];
            float4 hB = *(const float4*)&shk[(r0 + 4) ^ xk];
            float4 hC = *(const float4*)&shk[(r0 + 8) ^ xk];
            ull h2[6];
            h2[0] = pk(hA.x, hA.y); h2[1] = pk(hA.z, hA.w);
            h2[2] = pk(hB.x, hB.y); h2[3] = pk(hB.z, hB.w);
            h2[4] = pk(hC.x, hC.y); h2[5] = pk(hC.z, hC.w);
            #pragma unroll
            for (int i = 0; i < 6; i++){
                acc[0][i] = fma2(h2[i], ws0, acc[0][i]);
                acc[1][i] = fma2(h2[i], ws1, acc[1][i]);
            }
        }

        if (khalf == 1){
            #pragma unroll
            for (int c = 0; c < 2; c++)
                #pragma unroll
                for (int i = 0; i < 6; i++)
                    *(ull*)&zred[ZI(c0+c, r0 + 2*i)] = acc[c][i];
        }
        __syncthreads();
        if (khalf == 0){
            // combine k-halves, then apply folded BN affine (node = rg)
            float scn = nsc[rg], shn = nsh[rg];
            ull sc2 = pk(scn, scn), sh2v = pk(shn, shn);
            #pragma unroll
            for (int c = 0; c < 2; c++){
                float cv = csum[rel][c0+c];
                ull csv = mul2(pk(cv, cv), sh2v);
                #pragma unroll
                for (int i = 0; i < 6; i++){
                    ull sum = add2(acc[c][i], *(const ull*)&zred[ZI(c0+c, r0 + 2*i)]);
                    acc[c][i] = fma2(sum, sc2, csv);
                }
            }
            #pragma unroll
            for (int c = 0; c < 2; c++)
                #pragma unroll
                for (int i = 0; i < 6; i++)
                    *(ull*)&zred[ZI(c0+c, r0 + 2*i)] = acc[c][i];

            ull al0 = pk(al[c0], al[c0]),   al1v = pk(al[c0+1], al[c0+1]);
            ull ar0 = pk(ar[c0], ar[c0]),   ar1v = pk(ar[c0+1], ar[c0+1]);
            ull pl[6], pr[6];
            #pragma unroll
            for (int i = 0; i < 6; i++){
                pl[i] = fma2(acc[1][i], al1v, mul2(acc[0][i], al0));
                pr[i] = fma2(acc[1][i], ar1v, mul2(acc[0][i], ar0));
            }
            #pragma unroll
            for (int o = 1; o < 8; o <<= 1){
                #pragma unroll
                for (int i = 0; i < 6; i++){
                    pl[i] = add2(pl[i], __shfl_xor_sync(0xffffffffu, pl[i], o));
                    pr[i] = add2(pr[i], __shfl_xor_sync(0xffffffffu, pr[i], o));
                }
            }
            if (cg == 0){
                #pragma unroll
                for (int i = 0; i < 6; i++){
                    float2 fl = upk(pl[i]);
                    float2 fr = upk(pr[i]);
                    int nt = nt0 + r0 + 2*i;
                    g_el[rel][nt*4 + wcol]     = fl.x;
                    g_el[rel][(nt+1)*4 + wcol] = fl.y;
                    g_er[rel][nt*4 + wcol]     = fr.x;
                    g_er[rel][(nt+1)*4 + wcol] = fr.y;
                }
            }
        }
        __syncthreads();
        // coalesced z write (swizzled read)
        #pragma unroll
        for (int it = 0; it < 12; it++){
            int row = rbas + it*4;
            g_z[rel][(size_t)nt0*64 + tid + it*256] = zred[ZI(dcol, row)];
        }
        __syncthreads();
    }
}

// ---------------- GAT fallback for deg>32 (cold; noinline to cap regs) -------
struct U2 { ull a, b; };
__device__ __noinline__ U2 gat_fallback(const int* __restrict__ esrc, int bg_e, int dg,
                                        int t0, int half, int hA,
                                        const char* elb, const char* zbase,
                                        float4 er0, float4 er1){
    float mx00=-1e30f,mx01=-1e30f,mx02=-1e30f,mx03=-1e30f;
    float mx10=-1e30f,mx11=-1e30f,mx12=-1e30f,mx13=-1e30f;
    int lane = threadIdx.x & 31;
    for (int e = lane; e < dg; e += 32){
        int off = esrc[bg_e + e];
        const char* ep = elb + (off >> 4) + t0*16;
        float4 f0 = *(const float4*)ep;
        float4 f1 = *(const float4*)(ep + 16);
        mx00=fmaxf(mx00, lrelu(f0.x+er0.x)); mx01=fmaxf(mx01, lrelu(f0.y+er0.y));
        mx02=fmaxf(mx02, lrelu(f0.z+er0.z)); mx03=fmaxf(mx03, lrelu(f0.w+er0.w));
        mx10=fmaxf(mx10, lrelu(f1.x+er1.x)); mx11=fmaxf(mx11, lrelu(f1.y+er1.y));
        mx12=fmaxf(mx12, lrelu(f1.z+er1.z)); mx13=fmaxf(mx13, lrelu(f1.w+er1.w));
    }
    mx00=rmax32(mx00); mx01=rmax32(mx01); mx02=rmax32(mx02); mx03=rmax32(mx03);
    mx10=rmax32(mx10); mx11=rmax32(mx11); mx12=rmax32(mx12); mx13=rmax32(mx13);
    float dn00=0.f,dn01=0.f,dn02=0.f,dn03=0.f,dn10=0.f,dn11=0.f,dn12=0.f,dn13=0.f;
    for (int e = lane; e < dg; e += 32){
        int off = esrc[bg_e + e];
        const char* ep = elb + (off >> 4) + t0*16;
        float4 f0 = *(const float4*)ep;
        float4 f1 = *(const float4*)(ep + 16);
        dn00 += __expf(lrelu(f0.x+er0.x)-mx00); dn01 += __expf(lrelu(f0.y+er0.y)-mx01);
        dn02 += __expf(lrelu(f0.z+er0.z)-mx02); dn03 += __expf(lrelu(f0.w+er0.w)-mx03);
        dn10 += __expf(lrelu(f1.x+er1.x)-mx10); dn11 += __expf(lrelu(f1.y+er1.y)-mx11);
        dn12 += __expf(lrelu(f1.z+er1.z)-mx12); dn13 += __expf(lrelu(f1.w+er1.w)-mx13);
    }
    dn00=radd32(dn00); dn01=radd32(dn01); dn02=radd32(dn02); dn03=radd32(dn03);
    dn10=radd32(dn10); dn11=radd32(dn11); dn12=radd32(dn12); dn13=radd32(dn13);

    float dnSel = half ? ((hA==0)?dn10:(hA==1)?dn11:(hA==2)?dn12:dn13)
                       : ((hA==0)?dn00:(hA==1)?dn01:(hA==2)?dn02:dn03);
    float mxSel = half ? ((hA==0)?mx10:(hA==1)?mx11:(hA==2)?mx12:mx13)
                       : ((hA==0)?mx00:(hA==1)?mx01:(hA==2)?mx02:mx03);
    float erSel = half ? ((hA==0)?er1.x:(hA==1)?er1.y:(hA==2)?er1.z:er1.w)
                       : ((hA==0)?er0.x:(hA==1)?er0.y:(hA==2)?er0.z:er0.w);
    float inv = 1.f / fmaxf(dnSel, 1e-16f);

    ull p0=0ull, p1=0ull;
    for (int e = 0; e < dg; ++e){
        int off = esrc[bg_e + e];
        const float* ep = (const float*)(elb + (off >> 4) + (t0+half)*16);
        float a = lrelu(ep[hA] + erSel);
        float wv = __expf(a - mxSel);
        ulonglong2 zA = *(const ulonglong2*)(zbase + off);
        ull w2 = pk(wv, wv);
        p0 = fma2(w2, zA.x, p0);
        p1 = fma2(w2, zA.y, p1);
    }
    ull inv2 = pk(inv, inv);
    U2 r; r.a = mul2(p0, inv2); r.b = mul2(p1, inv2);
    return r;
}

// ---------------- fused GAT (both rels) + residual + BN2 ----------------
__global__ void __launch_bounds__(192, 7) gat_kernel(const float* __restrict__ x,
                           const float* __restrict__ bg, const float* __restrict__ bb){
    __shared__ float s_w[6][32*8];   // [warp][edge*8 + half*4 + head]
    __shared__ float sms[6], sqs[6];

    const unsigned FULL = 0xffffffffu;
    int d    = blockIdx.x;
    int w    = threadIdx.x >> 5;
    int lane = threadIdx.x & 31;
    int half = lane >> 4;
    int l16  = lane & 15;
    int hA   = l16 >> 2;
    int t0   = 2*w;

    ull m01 = 0ull, m23 = 0ull;

    #pragma unroll
    for (int rel = 0; rel < 2; rel++){
        int bg_e = g_rowptr[rel*(Nn+1) + d];
        int dg   = g_rowptr[rel*(Nn+1) + d + 1] - bg_e;
        const char* elb   = (const char*)g_el[rel];
        const char* zbase = (const char*)g_z[rel] + (t0+half)*256 + l16*16;
        float4 er0 = *(const float4*)&g_er[rel][d*48 + t0*4];
        float4 er1 = *(const float4*)&g_er[rel][d*48 + t0*4 + 4];

        if (dg <= 32){
            int off = 0;
            float a00=-1e30f,a01=-1e30f,a02=-1e30f,a03=-1e30f;
            float a10=-1e30f,a11=-1e30f,a12=-1e30f,a13=-1e30f;
            if (lane < dg){
                off = g_esrc[rel][bg_e + lane];
                const char* ep = elb + (off >> 4) + t0*16;
                float4 f0 = *(const float4*)ep;
                float4 f1 = *(const float4*)(ep + 16);
                a00 = lrelu(f0.x + er0.x); a01 = lrelu(f0.y + er0.y);
                a02 = lrelu(f0.z + er0.z); a03 = lrelu(f0.w + er0.w);
                a10 = lrelu(f1.x + er1.x); a11 = lrelu(f1.y + er1.y);
                a12 = lrelu(f1.z + er1.z); a13 = lrelu(f1.w + er1.w);
            }
            float mx00=rmax32(a00), mx01=rmax32(a01), mx02=rmax32(a02), mx03=rmax32(a03);
            float mx10=rmax32(a10), mx11=rmax32(a11), mx12=rmax32(a12), mx13=rmax32(a13);
            float w00=0.f,w01=0.f,w02=0.f,w03=0.f,w10=0.f,w11=0.f,w12=0.f,w13=0.f;
            if (lane < dg){
                w00=__expf(a00-mx00); w01=__expf(a01-mx01);
                w02=__expf(a02-mx02); w03=__expf(a03-mx03);
                w10=__expf(a10-mx10); w11=__expf(a11-mx11);
                w12=__expf(a12-mx12); w13=__expf(a13-mx13);
                *(float4*)&s_w[w][lane*8]     = make_float4(w00,w01,w02,w03);
                *(float4*)&s_w[w][lane*8 + 4] = make_float4(w10,w11,w12,w13);
            }
            float dn00=radd32(w00), dn01=radd32(w01), dn02=radd32(w02), dn03=radd32(w03);
            float dn10=radd32(w10), dn11=radd32(w11), dn12=radd32(w12), dn13=radd32(w13);

            float dnSel = half ? ((hA==0)?dn10:(hA==1)?dn11:(hA==2)?dn12:dn13)
                               : ((hA==0)?dn00:(hA==1)?dn01:(hA==2)?dn02:dn03);
            float inv = 1.f / fmaxf(dnSel, 1e-16f);

            __syncwarp();

            ull p0=0ull, p1=0ull, q0=0ull, q1=0ull;
            const float* wrow = &s_w[w][half*4 + hA];
            int e = 0;
            for (; e + 1 < dg; e += 2){
                int ofA = __shfl_sync(FULL, off, e);
                int ofB = __shfl_sync(FULL, off, e+1);
                float wA = wrow[e*8];
                float wB = wrow[e*8 + 8];
                ulonglong2 zA = *(const ulonglong2*)(zbase + ofA);
                ulonglong2 zB = *(const ulonglong2*)(zbase + ofB);
                ull wA2 = pk(wA, wA), wB2 = pk(wB, wB);
                p0 = fma2(wA2, zA.x, p0);
                p1 = fma2(wA2, zA.y, p1);
                q0 = fma2(wB2, zB.x, q0);
                q1 = fma2(wB2, zB.y, q1);
            }
            if (e < dg){
                int ofA = __shfl_sync(FULL, off, e);
                float wA = wrow[e*8];
                ulonglong2 zA = *(const ulonglong2*)(zbase + ofA);
                ull wA2 = pk(wA, wA);
                p0 = fma2(wA2, zA.x, p0);
                p1 = fma2(wA2, zA.y, p1);
            }
            ull inv2 = pk(inv, inv);
            m01 = add2(m01, mul2(add2(p0, q0), inv2));
            m23 = add2(m23, mul2(add2(p1, q1), inv2));
        } else {
            U2 r = gat_fallback(g_esrc[rel], bg_e, dg, t0, half, hA, elb, zbase, er0, er1);
            m01 = add2(m01, r.a);
            m23 = add2(m23, r.b);
        }
    }

    size_t idxb = (size_t)d*3072 + (t0+half)*256 + l16*16;
    ulonglong2 xv = *(const ulonglong2*)((const char*)x + idxb);
    ull v01 = add2(xv.x, m01);
    ull v23 = add2(xv.y, m23);

    float2 u01 = upk(v01), u23 = upk(v23);
    float s = radd32(u01.x + u01.y + u23.x + u23.y);
    float q = radd32(u01.x*u01.x + u01.y*u01.y + u23.x*u23.x + u23.y*u23.y);
    if (lane == 0){ sms[w] = s; sqs[w] = q; }
    __syncthreads();
    float ts = 0.f, tq = 0.f;
    #pragma unroll
    for (int i = 0; i < 6; i++){ ts += sms[i]; tq += sqs[i]; }
    float mean = ts * (1.f/768.f);
    float var  = tq * (1.f/768.f) - mean*mean;
    float sc   = rsqrtf(var + 1e-5f) * bg[d];
    float sb   = bb[d] - mean*sc;
    ull sc2 = pk(sc, sc), sb2 = pk(sb, sb);

    ulonglong2 xo, ho;
    xo.x = v01; xo.y = v23;
    ho.x = fma2(v01, sc2, sb2);
    ho.y = fma2(v23, sc2, sb2);
    *(ulonglong2*)((char*)g_x2 + idxb) = xo;
    *(ulonglong2*)((char*)g_h  + idxb) = ho;
}

// ---------------- FFN (register-tiled, 512 thr, 128-row tiles) ----------------
#define FF_TILES ((NTc + 127) / 128)   // 938 (last tile has 64 rows)
#define FF_SMEM ((8192 + 8192 + 128 + 64 + 64*132 + 128*132) * 4)
__global__ void ff_kernel(const float* __restrict__ w1, const float* __restrict__ b1,
                          const float* __restrict__ w2, const float* __restrict__ b2,
                          float* __restrict__ out){
    extern __shared__ float sm[];
    float* sW1 = sm;
    float* sW2 = sW1 + 8192;
    float* sB1 = sW2 + 8192;
    float* sB2 = sB1 + 128;
    float* sX  = sB2 + 64;
    float* sG  = sX  + 64*132;

    int tid  = threadIdx.x;
    int w    = tid >> 5;
    int lane = tid & 31;

    for (int i = tid; i < 8192; i += 512) sW1[i] = w1[i];
    for (int i = tid; i < 8192; i += 512) sW2[i] = w2[i];
    if (tid < 128) sB1[tid] = b1[tid];
    else if (tid < 192) sB2[tid-128] = b2[tid-128];
    __syncthreads();

    float b2v0 = sB2[2*lane], b2v1 = sB2[2*lane+1];

    for (int tile = blockIdx.x; tile < FF_TILES; tile += 148){
        size_t base = (size_t)tile * 128 * 64;

        #pragma unroll
        for (int it = 0; it < 16; it++){
            int i = tid + it*512;
            size_t gi = base + i;
            if (gi < (size_t)NTDc){
                int r = i >> 6, k = i & 63;
                sX[k*132 + r] = g_h[gi];
            }
        }
        __syncthreads();

        ull a1[4][4];
        #pragma unroll
        for (int c = 0; c < 4; c++)
            #pragma unroll
            for (int i = 0; i < 4; i++) a1[c][i] = 0ull;

        #pragma unroll 4
        for (int k = 0; k < 64; k++){
            double2 hd0 = *(const double2*)&sX[k*132 + 8*w];
            double2 hd1 = *(const double2*)&sX[k*132 + 8*w + 4];
            ull h01 = __double_as_longlong(hd0.x);
            ull h23 = __double_as_longlong(hd0.y);
            ull h45 = __double_as_longlong(hd1.x);
            ull h67 = __double_as_longlong(hd1.y);
            float4 wv = *(const float4*)&sW1[k*128 + 4*lane];
            ull ws0 = pk(wv.x, wv.x), ws1 = pk(wv.y, wv.y);
            ull ws2 = pk(wv.z, wv.z), ws3 = pk(wv.w, wv.w);
            a1[0][0] = fma2(h01, ws0, a1[0][0]);
            a1[0][1] = fma2(h23, ws0, a1[0][1]);
            a1[0][2] = fma2(h45, ws0, a1[0][2]);
            a1[0][3] = fma2(h67, ws0, a1[0][3]);
            a1[1][0] = fma2(h01, ws1, a1[1][0]);
            a1[1][1] = fma2(h23, ws1, a1[1][1]);
            a1[1][2] = fma2(h45, ws1, a1[1][2]);
            a1[1][3] = fma2(h67, ws1, a1[1][3]);
            a1[2][0] = fma2(h01, ws2, a1[2][0]);
            a1[2][1] = fma2(h23, ws2, a1[2][1]);
            a1[2][2] = fma2(h45, ws2, a1[2][2]);
            a1[2][3] = fma2(h67, ws2, a1[2][3]);
            a1[3][0] = fma2(h01, ws3, a1[3][0]);
            a1[3][1] = fma2(h23, ws3, a1[3][1]);
            a1[3][2] = fma2(h45, ws3, a1[3][2]);
            a1[3][3] = fma2(h67, ws3, a1[3][3]);
        }

        #pragma unroll
        for (int c = 0; c < 4; c++){
            int j = 4*lane + c;
            float bj = sB1[j];
            float g[8];
            #pragma unroll
            for (int i = 0; i < 4; i++){
                float2 f = upk(a1[c][i]);
                float u0 = f.x + bj, u1 = f.y + bj;
                g[2*i]   = 0.5f * u0 * (1.f + erff(u0 * 0.70710678118654752f));
                g[2*i+1] = 0.5f * u1 * (1.f + erff(u1 * 0.70710678118654752f));
            }
            double2 st0, st1;
            st0.x = __longlong_as_double(pk(g[0], g[1]));
            st0.y = __longlong_as_double(pk(g[2], g[3]));
            st1.x = __longlong_as_double(pk(g[4], g[5]));
            st1.y = __longlong_as_double(pk(g[6], g[7]));
            *(double2*)&sG[j*132 + 8*w]     = st0;
            *(double2*)&sG[j*132 + 8*w + 4] = st1;
        }
        __syncthreads();

        ull a2[2][4];
        #pragma unroll
        for (int c = 0; c < 2; c++)
            #pragma unroll
            for (int i = 0; i < 4; i++) a2[c][i] = 0ull;

        #pragma unroll 4
        for (int k = 0; k < 128; k++){
            double2 gd0 = *(const double2*)&sG[k*132 + 8*w];
            double2 gd1 = *(const double2*)&sG[k*132 + 8*w + 4];
            ull g01 = __double_as_longlong(gd0.x);
            ull g23 = __double_as_longlong(gd0.y);
            ull g45 = __double_as_longlong(gd1.x);
            ull g67 = __double_as_longlong(gd1.y);
            ull wv2 = *(const ull*)&sW2[k*64 + 2*lane];
            float2 wf = upk(wv2);
            ull ws0 = pk(wf.x, wf.x), ws1 = pk(wf.y, wf.y);
            a2[0][0] = fma2(g01, ws0, a2[0][0]);
            a2[0][1] = fma2(g23, ws0, a2[0][1]);
            a2[0][2] = fma2(g45, ws0, a2[0][2]);
            a2[0][3] = fma2(g67, ws0, a2[0][3]);
            a2[1][0] = fma2(g01, ws1, a2[1][0]);
            a2[1][1] = fma2(g23, ws1, a2[1][1]);
            a2[1][2] = fma2(g45, ws1, a2[1][2]);
            a2[1][3] = fma2(g67, ws1, a2[1][3]);
        }

        #pragma unroll
        for (int i = 0; i < 4; i++){
            float2 f0 = upk(a2[0][i]);
            float2 f1 = upk(a2[1][i]);
            size_t o = base + (size_t)(8*w + 2*i)*64 + 2*lane;
            if (o < (size_t)NTDc){
                out[o]    = g_x2[o]    + f0.x + b2v0;
                out[o+1]  = g_x2[o+1]  + f1.x + b2v1;
                out[o+64] = g_x2[o+64] + f0.y + b2v0;
                out[o+65] = g_x2[o+65] + f1.y + b2v1;
            }
        }
        __syncthreads();
    }
}

// ---------------- launcher ----------------
extern "C" void kernel_launch(void* const* d_in, const int* in_sizes, int n_in,
                              void* d_out, int out_size){
    const float* x    = (const float*)d_in[0];
    const int*   src1 = (const int*)d_in[1];
    const int*   dst1 = (const int*)d_in[2];
    const int*   src2 = (const int*)d_in[3];
    const int*   dst2 = (const int*)d_in[4];
    const float* W1   = (const float*)d_in[5];
    const float* al1  = (const float*)d_in[6];
    const float* ar1  = (const float*)d_in[7];
    const float* W2   = (const float*)d_in[8];
    const float* al2  = (const float*)d_in[9];
    const float* ar2  = (const float*)d_in[10];
    const float* bn1g = (const float*)d_in[11];
    const float* bn1b = (const float*)d_in[12];
    const float* bn2g = (const float*)d_in[13];
    const float* bn2b = (const float*)d_in[14];
    const float* fw1  = (const float*)d_in[15];
    const float* fb1  = (const float*)d_in[16];
    const float* fw2  = (const float*)d_in[17];
    const float* fb2  = (const float*)d_in[18];
    float* out = (float*)d_out;

    cudaFuncSetAttribute(ff_kernel, cudaFuncAttributeMaxDynamicSharedMemorySize, FF_SMEM);

    csr_hist<<<(2*Ee + 255)/256, 256>>>(dst1, dst2);               // idx 0
    csr_scan<<<1, 1024>>>();                                        // idx 1
    prof_pad<<<1, 32>>>();                                          // idx 2 (pad)
    scatter_zel<<<SCAT_BLKS + NTc/48, 256>>>(src1, dst1, src2, dst2,
        x, bn1g, bn1b, W1, al1, ar1, W2, al2, ar2);                 // idx 3 (profiled)
    gat_kernel<<<Nn, 192>>>(x, bn2g, bn2b);                         // idx 4
    ff_kernel<<<148, 512, FF_SMEM>>>(fw1, fb1, fw2, fb2, out);      // idx 5
}

// round 13
// speedup vs baseline: 2.7190x; 1.0247x over previous
#include <cuda_runtime.h>
#include <math.h>

#define Nn   10000
#define Tt   12
#define Ee   100000
#define NTc  (Nn*Tt)        // 120000
#define NTDc (NTc*64)       // 7680000
#define SCAT_BLKS 782       // ceil(2*Ee/256)

typedef unsigned long long ull;

// ---------------- scratch ----------------
__device__ float g_h[NTDc];          // BN2 output (input to FFN)
__device__ float g_z[2][NTDc];       // per-relation projected features
__device__ float g_x2[NTDc];         // residual x + m1 + m2
__device__ float g_el[2][NTc*4];
__device__ float g_er[2][NTc*4];
__device__ int   g_cnt[2*(Nn+1)];    // starts zero; scan re-zeros after reading
__device__ int   g_rowptr[2*(Nn+1)];
__device__ int   g_fill[2*Nn];
__device__ int   g_esrc[2][Ee];      // src node BYTE OFFSETS (src*3072)

// ---------------- f32x2 helpers ----------------
__device__ __forceinline__ ull pk(float a, float b){
    ull r;
    asm("mov.b64 %0, {%1, %2};" : "=l"(r) : "r"(__float_as_uint(a)), "r"(__float_as_uint(b)));
    return r;
}
__device__ __forceinline__ ull fma2(ull a, ull b, ull c){
    ull d;
    asm("fma.rn.f32x2 %0, %1, %2, %3;" : "=l"(d) : "l"(a), "l"(b), "l"(c));
    return d;
}
__device__ __forceinline__ ull mul2(ull a, ull b){
    ull d;
    asm("mul.rn.f32x2 %0, %1, %2;" : "=l"(d) : "l"(a), "l"(b));
    return d;
}
__device__ __forceinline__ ull add2(ull a, ull b){
    ull d;
    asm("add.rn.f32x2 %0, %1, %2;" : "=l"(d) : "l"(a), "l"(b));
    return d;
}
__device__ __forceinline__ float2 upk(ull v){
    unsigned lo, hi;
    asm("mov.b64 {%0, %1}, %2;" : "=r"(lo), "=r"(hi) : "l"(v));
    return make_float2(__uint_as_float(lo), __uint_as_float(hi));
}
// warp-wide reductions via shfl butterfly (no fp32 redux on sm_103)
__device__ __forceinline__ float rmax32(float v){
    #pragma unroll
    for (int o = 16; o; o >>= 1)
        v = fmaxf(v, __shfl_xor_sync(0xffffffffu, v, o));
    return v;
}
__device__ __forceinline__ float radd32(float v){
    #pragma unroll
    for (int o = 16; o; o >>= 1)
        v += __shfl_xor_sync(0xffffffffu, v, o);
    return v;
}
__device__ __forceinline__ float lrelu(float a){
    return (a > 0.f) ? a : 0.2f*a;
}

// ---------------- CSR: histogram ----------------
__global__ void csr_hist(const int* __restrict__ dst1, const int* __restrict__ dst2){
    int e = blockIdx.x * 256 + threadIdx.x;
    if (e < Ee)            atomicAdd(&g_cnt[dst1[e] + 1], 1);
    else if (e < 2*Ee)     atomicAdd(&g_cnt[(Nn+1) + dst2[e-Ee] + 1], 1);
}

// ---------------- CSR: scan (self-zeros g_cnt for next replay) ----------------
__global__ void csr_scan(){
    __shared__ int wsum[32];
    int tid = threadIdx.x, lane = tid & 31, w = tid >> 5;
    for (int rel = 0; rel < 2; rel++){
        int* cnt = g_cnt    + rel*(Nn+1);
        int* rp  = g_rowptr + rel*(Nn+1);
        int* fl  = g_fill   + rel*Nn;
        int base = tid * 10;
        int v[10]; int s = 0;
        #pragma unroll
        for (int i = 0; i < 10; i++){
            int idx = base + i;
            int c = 0;
            if (idx <= Nn){ c = cnt[idx]; cnt[idx] = 0; }
            s += c; v[i] = s;
        }
        int t = s;
        #pragma unroll
        for (int o = 1; o < 32; o <<= 1){
            int u = __shfl_up_sync(0xffffffffu, t, o);
            if (lane >= o) t += u;
        }
        if (lane == 31) wsum[w] = t;
        __syncthreads();
        if (w == 0){
            int ws = wsum[lane];
            #pragma unroll
            for (int o = 1; o < 32; o <<= 1){
                int u = __shfl_up_sync(0xffffffffu, ws, o);
                if (lane >= o) ws += u;
            }
            wsum[lane] = ws;
        }
        __syncthreads();
        int off = ((w > 0) ? wsum[w-1] : 0) + (t - s);
        #pragma unroll
        for (int i = 0; i < 10; i++){
            int idx = base + i;
            if (idx <= Nn){
                int val = off + v[i];
                rp[idx] = val;
                if (idx < Nn) fl[idx] = val;
            }
        }
        __syncthreads();
    }
}

// ---------------- fused: CSR scatter (blocks 0..781) + BN1/z/el/er (rest) -----
// BN1 folded: z = sc_node*(x@W) + shift_node*colsum(W).
// GEMM layout: warp owns rows 12*(w&3)..+11 (warp-uniform, broadcast loads),
// k-half (w>>2); lane owns col pair c0 = 2*lane.
__global__ void __launch_bounds__(256, 4)
scatter_zel(const int* __restrict__ src1, const int* __restrict__ dst1,
            const int* __restrict__ src2, const int* __restrict__ dst2,
            const float* __restrict__ x,
            const float* __restrict__ bg, const float* __restrict__ bb,
            const float* __restrict__ W1, const float* __restrict__ al1, const float* __restrict__ ar1,
            const float* __restrict__ W2, const float* __restrict__ al2, const float* __restrict__ ar2){
    if (blockIdx.x < SCAT_BLKS){
        int e = blockIdx.x * 256 + threadIdx.x;
        if (e < Ee){
            int p = atomicAdd(&g_fill[dst1[e]], 1);
            g_esrc[0][p] = src1[e] * 3072;       // z-row byte offset
        } else if (e < 2*Ee){
            int p = atomicAdd(&g_fill[Nn + dst2[e-Ee]], 1);
            g_esrc[1][p] = src2[e-Ee] * 3072;
        }
        return;
    }

    __shared__ __align__(16) float sh[64*52];    // raw x, [d][row] stride 52
    __shared__ __align__(16) float sW[64*64];    // [k][c]
    __shared__ __align__(16) float zred[64*52];  // [c][row] stride 52
    __shared__ float red[8];
    __shared__ float nsc[4], nsh[4];
    __shared__ float csum[2][64];

    int tid  = threadIdx.x;
    int lane = tid & 31;
    int w    = tid >> 5;
    int rgrp = w & 3;          // row group (node) of this warp
    int khalf= w >> 2;
    int r0   = rgrp * 12;
    int c0   = 2 * lane;
    int bz   = blockIdx.x - SCAT_BLKS;
    int nt0  = bz * 48;
    int nd0  = bz * 4;
    int dcol = tid & 63;
    int rbas = tid >> 6;

    if (tid < 8) red[tid] = 0.f;
    if (tid >= 128 && tid < 192) csum[0][tid-128] = 0.f;
    if (tid >= 192)              csum[1][tid-192] = 0.f;
    __syncthreads();

    // single-pass staging: raw x -> sh, BN stats from registers
    float ls[4] = {0,0,0,0}, lq[4] = {0,0,0,0};
    #pragma unroll
    for (int it = 0; it < 12; it++){
        float t = x[(size_t)nt0*64 + tid + it*256];
        int row = rbas + it*4;
        sh[dcol*52 + row] = t;
        int nl = row / 12;
        ls[nl] += t; lq[nl] += t*t;
    }
    #pragma unroll
    for (int nl = 0; nl < 4; nl++){
        ls[nl] = radd32(ls[nl]);
        lq[nl] = radd32(lq[nl]);
    }
    if (lane == 0){
        #pragma unroll
        for (int nl = 0; nl < 4; nl++){
            if (ls[nl] != 0.f || lq[nl] != 0.f){
                atomicAdd(&red[2*nl],   ls[nl]);
                atomicAdd(&red[2*nl+1], lq[nl]);
            }
        }
    }
    __syncthreads();
    if (tid < 4){
        float mean = red[2*tid] * (1.f/768.f);
        float var  = red[2*tid+1] * (1.f/768.f) - mean*mean;
        float sc   = rsqrtf(var + 1e-5f) * bg[nd0 + tid];
        nsc[tid] = sc;
        nsh[tid] = bb[nd0 + tid] - mean*sc;
    }
    __syncthreads();

    for (int rel = 0; rel < 2; rel++){
        const float* W  = rel ? W2  : W1;
        const float* al = rel ? al2 : al1;
        const float* ar = rel ? ar2 : ar1;
        for (int i = tid; i < 4096; i += 256) sW[i] = W[i];
        __syncthreads();

        // column sums of W (folded BN shift term)
        {
            float cs = 0.f;
            int q = tid >> 6;
            #pragma unroll
            for (int j = 0; j < 16; j++)
                cs += sW[(q*16 + j)*64 + dcol];
            atomicAdd(&csum[rel][dcol], cs);
        }

        ull acc[2][6];
        #pragma unroll
        for (int c = 0; c < 2; c++)
            #pragma unroll
            for (int i = 0; i < 6; i++) acc[c][i] = 0ull;

        int kb = khalf * 32;
        #pragma unroll 4
        for (int kk = 0; kk < 32; kk++){
            int k = kb + kk;
            ull w2v = *(const ull*)&sW[k*64 + c0];
            float2 wf = upk(w2v);
            ull ws0 = pk(wf.x, wf.x);
            ull ws1 = pk(wf.y, wf.y);
            // warp-uniform broadcast loads (single address per instruction)
            const float4* hb = (const float4*)&sh[k*52 + r0];
            float4 hA = hb[0], hB = hb[1], hC = hb[2];
            ull h2[6];
            h2[0] = pk(hA.x, hA.y); h2[1] = pk(hA.z, hA.w);
            h2[2] = pk(hB.x, hB.y); h2[3] = pk(hB.z, hB.w);
            h2[4] = pk(hC.x, hC.y); h2[5] = pk(hC.z, hC.w);
            #pragma unroll
            for (int i = 0; i < 6; i++){
                acc[0][i] = fma2(h2[i], ws0, acc[0][i]);
                acc[1][i] = fma2(h2[i], ws1, acc[1][i]);
            }
        }

        if (khalf == 1){
            #pragma unroll
            for (int c = 0; c < 2; c++)
                #pragma unroll
                for (int i = 0; i < 6; i++)
                    *(ull*)&zred[(c0+c)*52 + r0 + 2*i] = acc[c][i];
        }
        __syncthreads();
        if (khalf == 0){
            // combine k-halves, then folded BN affine (node = rgrp)
            float scn = nsc[rgrp], shn = nsh[rgrp];
            ull sc2 = pk(scn, scn), sh2v = pk(shn, shn);
            #pragma unroll
            for (int c = 0; c < 2; c++){
                float cv = csum[rel][c0+c];
                ull csv = mul2(pk(cv, cv), sh2v);
                #pragma unroll
                for (int i = 0; i < 6; i++){
                    ull sum = add2(acc[c][i], *(const ull*)&zred[(c0+c)*52 + r0 + 2*i]);
                    acc[c][i] = fma2(sum, sc2, csv);
                }
            }
            #pragma unroll
            for (int c = 0; c < 2; c++)
                #pragma unroll
                for (int i = 0; i < 6; i++)
                    *(ull*)&zred[(c0+c)*52 + r0 + 2*i] = acc[c][i];

            // el/er: reduce over the 8 lanes of each head group (lane>>3 = head)
            ull al0 = pk(al[c0], al[c0]),   al1v = pk(al[c0+1], al[c0+1]);
            ull ar0 = pk(ar[c0], ar[c0]),   ar1v = pk(ar[c0+1], ar[c0+1]);
            ull pl[6], pr[6];
            #pragma unroll
            for (int i = 0; i < 6; i++){
                pl[i] = fma2(acc[1][i], al1v, mul2(acc[0][i], al0));
                pr[i] = fma2(acc[1][i], ar1v, mul2(acc[0][i], ar0));
            }
            #pragma unroll
            for (int o = 1; o < 8; o <<= 1){
                #pragma unroll
                for (int i = 0; i < 6; i++){
                    pl[i] = add2(pl[i], __shfl_xor_sync(0xffffffffu, pl[i], o));
                    pr[i] = add2(pr[i], __shfl_xor_sync(0xffffffffu, pr[i], o));
                }
            }
            if ((lane & 7) == 0){
                int hd = lane >> 3;
                #pragma unroll
                for (int i = 0; i < 6; i++){
                    float2 fl = upk(pl[i]);
                    float2 fr = upk(pr[i]);
                    int nt = nt0 + r0 + 2*i;
                    g_el[rel][nt*4 + hd]     = fl.x;
                    g_el[rel][(nt+1)*4 + hd] = fl.y;
                    g_er[rel][nt*4 + hd]     = fr.x;
                    g_er[rel][(nt+1)*4 + hd] = fr.y;
                }
            }
        }
        __syncthreads();
        // coalesced z write
        #pragma unroll
        for (int it = 0; it < 12; it++){
            int row = rbas + it*4;
            g_z[rel][(size_t)nt0*64 + tid + it*256] = zred[dcol*52 + row];
        }
        __syncthreads();
    }
}

// ---------------- GAT fallback for deg>32 (cold; noinline to cap regs) -------
struct U2 { ull a, b; };
__device__ __noinline__ U2 gat_fallback(const int* __restrict__ esrc, int bg_e, int dg,
                                        int t0, int half, int hA,
                                        const char* elb, const char* zbase,
                                        float4 er0, float4 er1){
    float mx00=-1e30f,mx01=-1e30f,mx02=-1e30f,mx03=-1e30f;
    float mx10=-1e30f,mx11=-1e30f,mx12=-1e30f,mx13=-1e30f;
    int lane = threadIdx.x & 31;
    for (int e = lane; e < dg; e += 32){
        int off = esrc[bg_e + e];
        const char* ep = elb + (off >> 4) + t0*16;
        float4 f0 = *(const float4*)ep;
        float4 f1 = *(const float4*)(ep + 16);
        mx00=fmaxf(mx00, lrelu(f0.x+er0.x)); mx01=fmaxf(mx01, lrelu(f0.y+er0.y));
        mx02=fmaxf(mx02, lrelu(f0.z+er0.z)); mx03=fmaxf(mx03, lrelu(f0.w+er0.w));
        mx10=fmaxf(mx10, lrelu(f1.x+er1.x)); mx11=fmaxf(mx11, lrelu(f1.y+er1.y));
        mx12=fmaxf(mx12, lrelu(f1.z+er1.z)); mx13=fmaxf(mx13, lrelu(f1.w+er1.w));
    }
    mx00=rmax32(mx00); mx01=rmax32(mx01); mx02=rmax32(mx02); mx03=rmax32(mx03);
    mx10=rmax32(mx10); mx11=rmax32(mx11); mx12=rmax32(mx12); mx13=rmax32(mx13);
    float dn00=0.f,dn01=0.f,dn02=0.f,dn03=0.f,dn10=0.f,dn11=0.f,dn12=0.f,dn13=0.f;
    for (int e = lane; e < dg; e += 32){
        int off = esrc[bg_e + e];
        const char* ep = elb + (off >> 4) + t0*16;
        float4 f0 = *(const float4*)ep;
        float4 f1 = *(const float4*)(ep + 16);
        dn00 += __expf(lrelu(f0.x+er0.x)-mx00); dn01 += __expf(lrelu(f0.y+er0.y)-mx01);
        dn02 += __expf(lrelu(f0.z+er0.z)-mx02); dn03 += __expf(lrelu(f0.w+er0.w)-mx03);
        dn10 += __expf(lrelu(f1.x+er1.x)-mx10); dn11 += __expf(lrelu(f1.y+er1.y)-mx11);
        dn12 += __expf(lrelu(f1.z+er1.z)-mx12); dn13 += __expf(lrelu(f1.w+er1.w)-mx13);
    }
    dn00=radd32(dn00); dn01=radd32(dn01); dn02=radd32(dn02); dn03=radd32(dn03);
    dn10=radd32(dn10); dn11=radd32(dn11); dn12=radd32(dn12); dn13=radd32(dn13);

    float dnSel = half ? ((hA==0)?dn10:(hA==1)?dn11:(hA==2)?dn12:dn13)
                       : ((hA==0)?dn00:(hA==1)?dn01:(hA==2)?dn02:dn03);
    float mxSel = half ? ((hA==0)?mx10:(hA==1)?mx11:(hA==2)?mx12:mx13)
                       : ((hA==0)?mx00:(hA==1)?mx01:(hA==2)?mx02:mx03);
    float erSel = half ? ((hA==0)?er1.x:(hA==1)?er1.y:(hA==2)?er1.z:er1.w)
                       : ((hA==0)?er0.x:(hA==1)?er0.y:(hA==2)?er0.z:er0.w);
    float inv = 1.f / fmaxf(dnSel, 1e-16f);

    ull p0=0ull, p1=0ull;
    for (int e = 0; e < dg; ++e){
        int off = esrc[bg_e + e];
        const float* ep = (const float*)(elb + (off >> 4) + (t0+half)*16);
        float a = lrelu(ep[hA] + erSel);
        float wv = __expf(a - mxSel);
        ulonglong2 zA = *(const ulonglong2*)(zbase + off);
        ull w2 = pk(wv, wv);
        p0 = fma2(w2, zA.x, p0);
        p1 = fma2(w2, zA.y, p1);
    }
    ull inv2 = pk(inv, inv);
    U2 r; r.a = mul2(p0, inv2); r.b = mul2(p1, inv2);
    return r;
}

// ---------------- fused GAT (both rels) + residual + BN2 ----------------
__global__ void __launch_bounds__(192, 7) gat_kernel(const float* __restrict__ x,
                           const float* __restrict__ bg, const float* __restrict__ bb){
    __shared__ float s_w[6][32*8];   // [warp][edge*8 + half*4 + head]
    __shared__ float sms[6], sqs[6];

    const unsigned FULL = 0xffffffffu;
    int d    = blockIdx.x;
    int w    = threadIdx.x >> 5;
    int lane = threadIdx.x & 31;
    int half = lane >> 4;
    int l16  = lane & 15;
    int hA   = l16 >> 2;
    int t0   = 2*w;

    ull m01 = 0ull, m23 = 0ull;

    #pragma unroll
    for (int rel = 0; rel < 2; rel++){
        int bg_e = g_rowptr[rel*(Nn+1) + d];
        int dg   = g_rowptr[rel*(Nn+1) + d + 1] - bg_e;
        const char* elb   = (const char*)g_el[rel];
        const char* zbase = (const char*)g_z[rel] + (t0+half)*256 + l16*16;
        float4 er0 = *(const float4*)&g_er[rel][d*48 + t0*4];
        float4 er1 = *(const float4*)&g_er[rel][d*48 + t0*4 + 4];

        if (dg <= 32){
            int off = 0;
            float a00=-1e30f,a01=-1e30f,a02=-1e30f,a03=-1e30f;
            float a10=-1e30f,a11=-1e30f,a12=-1e30f,a13=-1e30f;
            if (lane < dg){
                off = g_esrc[rel][bg_e + lane];
                const char* ep = elb + (off >> 4) + t0*16;
                float4 f0 = *(const float4*)ep;
                float4 f1 = *(const float4*)(ep + 16);
                a00 = lrelu(f0.x + er0.x); a01 = lrelu(f0.y + er0.y);
                a02 = lrelu(f0.z + er0.z); a03 = lrelu(f0.w + er0.w);
                a10 = lrelu(f1.x + er1.x); a11 = lrelu(f1.y + er1.y);
                a12 = lrelu(f1.z + er1.z); a13 = lrelu(f1.w + er1.w);
            }
            float mx00=rmax32(a00), mx01=rmax32(a01), mx02=rmax32(a02), mx03=rmax32(a03);
            float mx10=rmax32(a10), mx11=rmax32(a11), mx12=rmax32(a12), mx13=rmax32(a13);
            float w00=0.f,w01=0.f,w02=0.f,w03=0.f,w10=0.f,w11=0.f,w12=0.f,w13=0.f;
            if (lane < dg){
                w00=__expf(a00-mx00); w01=__expf(a01-mx01);
                w02=__expf(a02-mx02); w03=__expf(a03-mx03);
                w10=__expf(a10-mx10); w11=__expf(a11-mx11);
                w12=__expf(a12-mx12); w13=__expf(a13-mx13);
                *(float4*)&s_w[w][lane*8]     = make_float4(w00,w01,w02,w03);
                *(float4*)&s_w[w][lane*8 + 4] = make_float4(w10,w11,w12,w13);
            }
            float dn00=radd32(w00), dn01=radd32(w01), dn02=radd32(w02), dn03=radd32(w03);
            float dn10=radd32(w10), dn11=radd32(w11), dn12=radd32(w12), dn13=radd32(w13);

            float dnSel = half ? ((hA==0)?dn10:(hA==1)?dn11:(hA==2)?dn12:dn13)
                               : ((hA==0)?dn00:(hA==1)?dn01:(hA==2)?dn02:dn03);
            float inv = 1.f / fmaxf(dnSel, 1e-16f);

            __syncwarp();

            ull p0=0ull, p1=0ull, q0=0ull, q1=0ull;
            const float* wrow = &s_w[w][half*4 + hA];
            int e = 0;
            for (; e + 1 < dg; e += 2){
                int ofA = __shfl_sync(FULL, off, e);
                int ofB = __shfl_sync(FULL, off, e+1);
                float wA = wrow[e*8];
                float wB = wrow[e*8 + 8];
                ulonglong2 zA = *(const ulonglong2*)(zbase + ofA);
                ulonglong2 zB = *(const ulonglong2*)(zbase + ofB);
                ull wA2 = pk(wA, wA), wB2 = pk(wB, wB);
                p0 = fma2(wA2, zA.x, p0);
                p1 = fma2(wA2, zA.y, p1);
                q0 = fma2(wB2, zB.x, q0);
                q1 = fma2(wB2, zB.y, q1);
            }
            if (e < dg){
                int ofA = __shfl_sync(FULL, off, e);
                float wA = wrow[e*8];
                ulonglong2 zA = *(const ulonglong2*)(zbase + ofA);
                ull wA2 = pk(wA, wA);
                p0 = fma2(wA2, zA.x, p0);
                p1 = fma2(wA2, zA.y, p1);
            }
            ull inv2 = pk(inv, inv);
            m01 = add2(m01, mul2(add2(p0, q0), inv2));
            m23 = add2(m23, mul2(add2(p1, q1), inv2));
        } else {
            U2 r = gat_fallback(g_esrc[rel], bg_e, dg, t0, half, hA, elb, zbase, er0, er1);
            m01 = add2(m01, r.a);
            m23 = add2(m23, r.b);
        }
    }

    size_t idxb = (size_t)d*3072 + (t0+half)*256 + l16*16;
    ulonglong2 xv = *(const ulonglong2*)((const char*)x + idxb);
    ull v01 = add2(xv.x, m01);
    ull v23 = add2(xv.y, m23);

    float2 u01 = upk(v01), u23 = upk(v23);
    float s = radd32(u01.x + u01.y + u23.x + u23.y);
    float q = radd32(u01.x*u01.x + u01.y*u01.y + u23.x*u23.x + u23.y*u23.y);
    if (lane == 0){ sms[w] = s; sqs[w] = q; }
    __syncthreads();
    float ts = 0.f, tq = 0.f;
    #pragma unroll
    for (int i = 0; i < 6; i++){ ts += sms[i]; tq += sqs[i]; }
    float mean = ts * (1.f/768.f);
    float var  = tq * (1.f/768.f) - mean*mean;
    float sc   = rsqrtf(var + 1e-5f) * bg[d];
    float sb   = bb[d] - mean*sc;
    ull sc2 = pk(sc, sc), sb2 = pk(sb, sb);

    ulonglong2 xo, ho;
    xo.x = v01; xo.y = v23;
    ho.x = fma2(v01, sc2, sb2);
    ho.y = fma2(v23, sc2, sb2);
    *(ulonglong2*)((char*)g_x2 + idxb) = xo;
    *(ulonglong2*)((char*)g_h  + idxb) = ho;
}

// ---------------- FFN (register-tiled, 512 thr, 128-row tiles) ----------------
#define FF_TILES ((NTc + 127) / 128)   // 938 (last tile has 64 rows)
#define FF_SMEM ((8192 + 8192 + 128 + 64 + 64*132 + 128*132) * 4)
__global__ void ff_kernel(const float* __restrict__ w1, const float* __restrict__ b1,
                          const float* __restrict__ w2, const float* __restrict__ b2,
                          float* __restrict__ out){
    extern __shared__ float sm[];
    float* sW1 = sm;
    float* sW2 = sW1 + 8192;
    float* sB1 = sW2 + 8192;
    float* sB2 = sB1 + 128;
    float* sX  = sB2 + 64;
    float* sG  = sX  + 64*132;

    int tid  = threadIdx.x;
    int w    = tid >> 5;
    int lane = tid & 31;

    for (int i = tid; i < 8192; i += 512) sW1[i] = w1[i];
    for (int i = tid; i < 8192; i += 512) sW2[i] = w2[i];
    if (tid < 128) sB1[tid] = b1[tid];
    else if (tid < 192) sB2[tid-128] = b2[tid-128];
    __syncthreads();

    float b2v0 = sB2[2*lane], b2v1 = sB2[2*lane+1];

    for (int tile = blockIdx.x; tile < FF_TILES; tile += 148){
        size_t base = (size_t)tile * 128 * 64;

        #pragma unroll
        for (int it = 0; it < 16; it++){
            int i = tid + it*512;
            size_t gi = base + i;
            if (gi < (size_t)NTDc){
                int r = i >> 6, k = i & 63;
                sX[k*132 + r] = g_h[gi];
            }
        }
        __syncthreads();

        ull a1[4][4];
        #pragma unroll
        for (int c = 0; c < 4; c++)
            #pragma unroll
            for (int i = 0; i < 4; i++) a1[c][i] = 0ull;

        #pragma unroll 4
        for (int k = 0; k < 64; k++){
            double2 hd0 = *(const double2*)&sX[k*132 + 8*w];
            double2 hd1 = *(const double2*)&sX[k*132 + 8*w + 4];
            ull h01 = __double_as_longlong(hd0.x);
            ull h23 = __double_as_longlong(hd0.y);
            ull h45 = __double_as_longlong(hd1.x);
            ull h67 = __double_as_longlong(hd1.y);
            float4 wv = *(const float4*)&sW1[k*128 + 4*lane];
            ull ws0 = pk(wv.x, wv.x), ws1 = pk(wv.y, wv.y);
            ull ws2 = pk(wv.z, wv.z), ws3 = pk(wv.w, wv.w);
            a1[0][0] = fma2(h01, ws0, a1[0][0]);
            a1[0][1] = fma2(h23, ws0, a1[0][1]);
            a1[0][2] = fma2(h45, ws0, a1[0][2]);
            a1[0][3] = fma2(h67, ws0, a1[0][3]);
            a1[1][0] = fma2(h01, ws1, a1[1][0]);
            a1[1][1] = fma2(h23, ws1, a1[1][1]);
            a1[1][2] = fma2(h45, ws1, a1[1][2]);
            a1[1][3] = fma2(h67, ws1, a1[1][3]);
            a1[2][0] = fma2(h01, ws2, a1[2][0]);
            a1[2][1] = fma2(h23, ws2, a1[2][1]);
            a1[2][2] = fma2(h45, ws2, a1[2][2]);
            a1[2][3] = fma2(h67, ws2, a1[2][3]);
            a1[3][0] = fma2(h01, ws3, a1[3][0]);
            a1[3][1] = fma2(h23, ws3, a1[3][1]);
            a1[3][2] = fma2(h45, ws3, a1[3][2]);
            a1[3][3] = fma2(h67, ws3, a1[3][3]);
        }

        #pragma unroll
        for (int c = 0; c < 4; c++){
            int j = 4*lane + c;
            float bj = sB1[j];
            float g[8];
            #pragma unroll
            for (int i = 0; i < 4; i++){
                float2 f = upk(a1[c][i]);
                float u0 = f.x + bj, u1 = f.y + bj;
                g[2*i]   = 0.5f * u0 * (1.f + erff(u0 * 0.70710678118654752f));
                g[2*i+1] = 0.5f * u1 * (1.f + erff(u1 * 0.70710678118654752f));
            }
            double2 st0, st1;
            st0.x = __longlong_as_double(pk(g[0], g[1]));
            st0.y = __longlong_as_double(pk(g[2], g[3]));
            st1.x = __longlong_as_double(pk(g[4], g[5]));
            st1.y = __longlong_as_double(pk(g[6], g[7]));
            *(double2*)&sG[j*132 + 8*w]     = st0;
            *(double2*)&sG[j*132 + 8*w + 4] = st1;
        }
        __syncthreads();

        ull a2[2][4];
        #pragma unroll
        for (int c = 0; c < 2; c++)
            #pragma unroll
            for (int i = 0; i < 4; i++) a2[c][i] = 0ull;

        #pragma unroll 4
        for (int k = 0; k < 128; k++){
            double2 gd0 = *(const double2*)&sG[k*132 + 8*w];
            double2 gd1 = *(const double2*)&sG[k*132 + 8*w + 4];
            ull g01 = __double_as_longlong(gd0.x);
            ull g23 = __double_as_longlong(gd0.y);
            ull g45 = __double_as_longlong(gd1.x);
            ull g67 = __double_as_longlong(gd1.y);
            ull wv2 = *(const ull*)&sW2[k*64 + 2*lane];
            float2 wf = upk(wv2);
            ull ws0 = pk(wf.x, wf.x), ws1 = pk(wf.y, wf.y);
            a2[0][0] = fma2(g01, ws0, a2[0][0]);
            a2[0][1] = fma2(g23, ws0, a2[0][1]);
            a2[0][2] = fma2(g45, ws0, a2[0][2]);
            a2[0][3] = fma2(g67, ws0, a2[0][3]);
            a2[1][0] = fma2(g01, ws1, a2[1][0]);
            a2[1][1] = fma2(g23, ws1, a2[1][1]);
            a2[1][2] = fma2(g45, ws1, a2[1][2]);
            a2[1][3] = fma2(g67, ws1, a2[1][3]);
        }

        #pragma unroll
        for (int i = 0; i < 4; i++){
            float2 f0 = upk(a2[0][i]);
            float2 f1 = upk(a2[1][i]);
            size_t o = base + (size_t)(8*w + 2*i)*64 + 2*lane;
            if (o < (size_t)NTDc){
                out[o]    = g_x2[o]    + f0.x + b2v0;
                out[o+1]  = g_x2[o+1]  + f1.x + b2v1;
                out[o+64] = g_x2[o+64] + f0.y + b2v0;
                out[o+65] = g_x2[o+65] + f1.y + b2v1;
            }
        }
        __syncthreads();
    }
}

// ---------------- launcher ----------------
extern "C" void kernel_launch(void* const* d_in, const int* in_sizes, int n_in,
                              void* d_out, int out_size){
    const float* x    = (const float*)d_in[0];
    const int*   src1 = (const int*)d_in[1];
    const int*   dst1 = (const int*)d_in[2];
    const int*   src2 = (const int*)d_in[3];
    const int*   dst2 = (const int*)d_in[4];
    const float* W1   = (const float*)d_in[5];
    const float* al1  = (const float*)d_in[6];
    const float* ar1  = (const float*)d_in[7];
    const float* W2   = (const float*)d_in[8];
    const float* al2  = (const float*)d_in[9];
    const float* ar2  = (const float*)d_in[10];
    const float* bn1g = (const float*)d_in[11];
    const float* bn1b = (const float*)d_in[12];
    const float* bn2g = (const float*)d_in[13];
    const float* bn2b = (const float*)d_in[14];
    const float* fw1  = (const float*)d_in[15];
    const float* fb1  = (const float*)d_in[16];
    const float* fw2  = (const float*)d_in[17];
    const float* fb2  = (const float*)d_in[18];
    float* out = (float*)d_out;

    cudaFuncSetAttribute(ff_kernel, cudaFuncAttributeMaxDynamicSharedMemorySize, FF_SMEM);

    csr_hist<<<(2*Ee + 255)/256, 256>>>(dst1, dst2);               // idx 0
    csr_scan<<<1, 1024>>>();                                        // idx 1
    scatter_zel<<<SCAT_BLKS + NTc/48, 256>>>(src1, dst1, src2, dst2,
        x, bn1g, bn1b, W1, al1, ar1, W2, al2, ar2);                 // idx 2
    gat_kernel<<<Nn, 192>>>(x, bn2g, bn2b);                         // idx 3 (profiled)
    ff_kernel<<<148, 512, FF_SMEM>>>(fw1, fb1, fw2, fb2, out);      // idx 4
}